// round 6
// baseline (speedup 1.0000x reference)
#include <cuda_runtime.h>
#include <cuda_bf16.h>
#include <math.h>
#include <stdint.h>

// ---------------- problem constants ----------------
#define BATCH   8
#define HIMG    56
#define WIMG    56
#define CDIM    384
#define NHEADS  12
#define HDIM    32
#define WIN     7
#define NTOK    49
#define SHIFT_S 3
#define TOTWIN  512
#define MTOK    25088
#define FFNDIM  1536
#define QKVN    1152          // 3*CDIM

typedef __nv_bfloat16 bf16;

// ---------------- scratch (device globals; allocation-free) ----------------
__device__ bf16  g_xw  [MTOK * CDIM];
__device__ bf16  g_qkv [MTOK * QKVN];
__device__ bf16  g_ctx [MTOK * CDIM];
__device__ float g_h   [MTOK * CDIM];
__device__ bf16  g_ln2 [MTOK * CDIM];
__device__ bf16  g_y1  [MTOK * FFNDIM];
__device__ bf16  g_wqkv[CDIM * QKVN];   // [K][N] packed q|k|v
__device__ float g_bqkv[QKVN];
__device__ bf16  g_wp  [CDIM * CDIM];
__device__ bf16  g_w1  [CDIM * FFNDIM];
__device__ bf16  g_w2  [FFNDIM * CDIM];
__device__ bf16  g_bias[4 * NHEADS * 64 * 64];

// windowed row r <-> original token t (same map both directions)
__device__ __forceinline__ int win_row_to_token(int r) {
    int b    = r / (HIMG * WIMG);
    int rem  = r - b * (HIMG * WIMG);
    int widx = rem / NTOK;
    int tok  = rem - widx * NTOK;
    int wi = widx >> 3, wj = widx & 7;
    int i = tok / WIN, j = tok - i * WIN;
    int sh = wi * WIN + i + SHIFT_S; if (sh >= HIMG) sh -= HIMG;
    int sw = wj * WIN + j + SHIFT_S; if (sw >= WIMG) sw -= WIMG;
    return b * (HIMG * WIMG) + sh * WIMG + sw;
}

// ---------------- fp32 -> bf16 convert ----------------
__global__ void __launch_bounds__(256) f2bf_kernel(
    const float* __restrict__ src, bf16* __restrict__ dst, int n4)
{
    int i = blockIdx.x * blockDim.x + threadIdx.x;
    if (i < n4) {
        float4 v = ((const float4*)src)[i];
        bf16 o[4] = {__float2bfloat16(v.x), __float2bfloat16(v.y),
                     __float2bfloat16(v.z), __float2bfloat16(v.w)};
        *(uint64_t*)(dst + i * 4) = *(uint64_t*)o;
    }
}

// ---------------- pack q|k|v weights + biases ----------------
#define QKV_W4 (CDIM * QKVN / 4)
__global__ void __launch_bounds__(256) pack_qkv_kernel(
    const float* __restrict__ qw, const float* __restrict__ kw,
    const float* __restrict__ vw, const float* __restrict__ qb,
    const float* __restrict__ kb, const float* __restrict__ vb,
    bf16* __restrict__ wout, float* __restrict__ bout)
{
    int i = blockIdx.x * blockDim.x + threadIdx.x;
    if (i < QKV_W4) {
        int row = i / (QKVN / 4);
        int col = (i % (QKVN / 4)) * 4;
        const float* src = (col < CDIM) ? qw : (col < 2 * CDIM ? kw : vw);
        int c = col - (col < CDIM ? 0 : (col < 2 * CDIM ? CDIM : 2 * CDIM));
        float4 v = *(const float4*)(src + (size_t)row * CDIM + c);
        bf16 o[4] = {__float2bfloat16(v.x), __float2bfloat16(v.y),
                     __float2bfloat16(v.z), __float2bfloat16(v.w)};
        *(uint64_t*)(wout + (size_t)i * 4) = *(uint64_t*)o;
    } else if (i < QKV_W4 + QKVN / 4) {
        int col = (i - QKV_W4) * 4;
        const float* src = (col < CDIM) ? qb : (col < 2 * CDIM ? kb : vb);
        int c = col - (col < CDIM ? 0 : (col < 2 * CDIM ? CDIM : 2 * CDIM));
        *(float4*)(bout + col) = *(const float4*)(src + c);
    }
}

// ---------------- precompute attention bias+mask tiles ----------------
__global__ void __launch_bounds__(256) bias_kernel(
    const float* __restrict__ rpb, const int* __restrict__ rpi,
    bf16* __restrict__ out)
{
    int type = blockIdx.x, h = blockIdx.y;
    for (int idx = threadIdx.x; idx < 64 * 64; idx += 256) {
        int n = idx >> 6, m = idx & 63;
        float v;
        if (m >= 49)      v = -1e30f;
        else if (n >= 49) v = 0.f;
        else {
            v = rpb[rpi[n * 49 + m] * NHEADS + h];
            int ni = n / 7, nj = n % 7, mi = m / 7, mj = m % 7;
            int cn = ((type & 2) ? (ni < 4 ? 1 : 2) : 0) * 3 + ((type & 1) ? (nj < 4 ? 1 : 2) : 0);
            int cm = ((type & 2) ? (mi < 4 ? 1 : 2) : 0) * 3 + ((type & 1) ? (mj < 4 ? 1 : 2) : 0);
            if (cn != cm) v -= 100.0f;
        }
        out[(((size_t)type * NHEADS + h) * 64 + n) * 64 + m] = __float2bfloat16(v);
    }
}

// ---------------- LayerNorm (fp32 in, bf16 out) ----------------
__global__ void __launch_bounds__(128) ln_kernel(
    const float* __restrict__ x, const float* __restrict__ g,
    const float* __restrict__ b, bf16* __restrict__ out, int permute)
{
    int r = blockIdx.x;
    int t = permute ? win_row_to_token(r) : r;
    const float* xi = x + (size_t)t * CDIM;
    bf16*        yo = out + (size_t)r * CDIM;
    int tid = threadIdx.x;

    float v[3];
    float s = 0.f, ss = 0.f;
#pragma unroll
    for (int i = 0; i < 3; i++) {
        v[i] = xi[tid + i * 128];
        s += v[i]; ss += v[i] * v[i];
    }
#pragma unroll
    for (int o = 16; o; o >>= 1) {
        s  += __shfl_xor_sync(0xffffffffu, s,  o);
        ss += __shfl_xor_sync(0xffffffffu, ss, o);
    }
    __shared__ float red[8];
    __shared__ float stat[2];
    int wid = tid >> 5, lane = tid & 31;
    if (lane == 0) { red[wid] = s; red[4 + wid] = ss; }
    __syncthreads();
    if (tid == 0) {
        float S  = red[0] + red[1] + red[2] + red[3];
        float SS = red[4] + red[5] + red[6] + red[7];
        float mu = S * (1.0f / CDIM);
        float var = SS * (1.0f / CDIM) - mu * mu;
        stat[0] = mu;
        stat[1] = rsqrtf(var + 1e-5f);
    }
    __syncthreads();
    float mu = stat[0], rstd = stat[1];
#pragma unroll
    for (int i = 0; i < 3; i++) {
        int c = tid + i * 128;
        yo[c] = __float2bfloat16((v[i] - mu) * rstd * g[c] + b[c]);
    }
}

// ---------------- mma helpers ----------------
#define CP16(dst, src) \
    asm volatile("cp.async.ca.shared.global [%0], [%1], 16;\n" :: \
        "r"((uint32_t)__cvta_generic_to_shared(dst)), "l"(src))
#define CP_COMMIT()  asm volatile("cp.async.commit_group;\n" ::)
#define CP_WAIT(n)   asm volatile("cp.async.wait_group %0;\n" :: "n"(n))

__device__ __forceinline__ void ldm_x4(uint32_t* r, const void* p) {
    uint32_t a = (uint32_t)__cvta_generic_to_shared(p);
    asm volatile("ldmatrix.sync.aligned.m8n8.x4.shared.b16 {%0,%1,%2,%3},[%4];"
        : "=r"(r[0]), "=r"(r[1]), "=r"(r[2]), "=r"(r[3]) : "r"(a));
}
__device__ __forceinline__ void ldm_x4t(uint32_t* r, const void* p) {
    uint32_t a = (uint32_t)__cvta_generic_to_shared(p);
    asm volatile("ldmatrix.sync.aligned.m8n8.x4.trans.shared.b16 {%0,%1,%2,%3},[%4];"
        : "=r"(r[0]), "=r"(r[1]), "=r"(r[2]), "=r"(r[3]) : "r"(a));
}
#define MMA16816(d, a, b0, b1) \
    asm volatile("mma.sync.aligned.m16n8k16.row.col.f32.bf16.bf16.f32 " \
        "{%0,%1,%2,%3},{%4,%5,%6,%7},{%8,%9},{%0,%1,%2,%3};" \
        : "+f"(d[0]), "+f"(d[1]), "+f"(d[2]), "+f"(d[3]) \
        : "r"(a[0]), "r"(a[1]), "r"(a[2]), "r"(a[3]), "r"(b0), "r"(b1))

__device__ __forceinline__ uint32_t packbf(float lo, float hi) {
    __nv_bfloat162 h = __floats2bfloat162_rn(lo, hi);
    return *(uint32_t*)&h;
}

// ---------------- HMMA bf16 GEMM: 128x128x64, 4 warps of 64x64 -------------
// 3-stage cp.async ring, XOR-swizzled smem, one syncthreads per K-iter.
// EPI 0: store  1: exact GELU  2: scatter+residual  3: residual
#define GBM 128
#define GBN 128
#define GBK 64
#define TCSMEM (3 * (GBM * GBK + GBK * GBN) * 2)   // 98304 bytes

template <int EPI, typename OutT>
__global__ void __launch_bounds__(128, 2) mma_gemm(
    const bf16* __restrict__ A, const bf16* __restrict__ B,
    const float* __restrict__ bias, const float* __restrict__ add,
    OutT* __restrict__ C, int M, int N, int K)
{
    extern __shared__ __align__(16) bf16 sm[];
    bf16* As = sm;                      // 3 stages x 8192 elems
    bf16* Bs = sm + 3 * GBM * GBK;      // 3 stages x 8192 elems

    int t = threadIdx.x;
    int m0 = blockIdx.y * GBM, n0 = blockIdx.x * GBN;

    // A: one row per thread (128 rows), 8 x 16B chunks of 64 bf16 cols
    const bf16* Ag = A + (size_t)(m0 + t) * K;
    int aswz[8];
#pragma unroll
    for (int c = 0; c < 8; c++) aswz[c] = t * 64 + ((c ^ (t & 7)) << 3);
    // B: row t>>1 (64 rows), chunk half (t&1)*8 of 16 chunks (128 bf16 cols)
    int brow = t >> 1, bc0 = (t & 1) * 8;
    const bf16* Bg = B + (size_t)brow * N + n0;
    int bswz[8];
#pragma unroll
    for (int j = 0; j < 8; j++)
        bswz[j] = brow * 128 + (((bc0 + j) ^ (brow & 7)) << 3);

    int lane = t & 31, w = t >> 5;
    int mw = (w >> 1) * 64, nw = (w & 1) * 64;   // warp tile 64x64
    int lrow = (lane & 7) + (lane & 8);
    int lcol = (lane & 16) >> 1;

    float acc[4][8][4] = {};

    int nk = K / GBK;
    // prologue: stages 0,1
#pragma unroll
    for (int s = 0; s < 2; s++) {
        int k0 = s * GBK;
#pragma unroll
        for (int c = 0; c < 8; c++)
            CP16(&As[s * 8192 + aswz[c]], Ag + k0 + c * 8);
#pragma unroll
        for (int j = 0; j < 8; j++)
            CP16(&Bs[s * 8192 + bswz[j]], Bg + (size_t)k0 * N + (bc0 + j) * 8);
        CP_COMMIT();
    }

    for (int i = 0; i < nk; i++) {
        if (i + 1 < nk) { CP_WAIT(1); } else { CP_WAIT(0); }
        __syncthreads();
        if (i + 2 < nk) {
            int st = (i + 2) % 3;
            int k0 = (i + 2) * GBK;
#pragma unroll
            for (int c = 0; c < 8; c++)
                CP16(&As[st * 8192 + aswz[c]], Ag + k0 + c * 8);
#pragma unroll
            for (int j = 0; j < 8; j++)
                CP16(&Bs[st * 8192 + bswz[j]], Bg + (size_t)k0 * N + (bc0 + j) * 8);
            CP_COMMIT();
        }
        int cs = i % 3;
        const bf16* Asc = As + cs * 8192;
        const bf16* Bsc = Bs + cs * 8192;
#pragma unroll
        for (int kk = 0; kk < GBK; kk += 16) {
            uint32_t a[4][4], b[4][4];
#pragma unroll
            for (int mi = 0; mi < 4; mi++) {
                int R = mw + mi * 16 + lrow;
                int ch = (kk + lcol) >> 3;
                ldm_x4(a[mi], Asc + R * 64 + ((ch ^ (R & 7)) << 3));
            }
#pragma unroll
            for (int nj = 0; nj < 4; nj++) {
                int Kr = kk + lrow;
                int ch = (nw + nj * 16 + lcol) >> 3;
                ldm_x4t(b[nj], Bsc + Kr * 128 + ((ch ^ (Kr & 7)) << 3));
            }
#pragma unroll
            for (int mi = 0; mi < 4; mi++) {
#pragma unroll
                for (int nt = 0; nt < 8; nt++)
                    MMA16816(acc[mi][nt], a[mi],
                             b[nt >> 1][(nt & 1) * 2], b[nt >> 1][(nt & 1) * 2 + 1]);
            }
        }
    }

    // epilogue
#pragma unroll
    for (int mi = 0; mi < 4; mi++) {
        int rbase = m0 + mw + mi * 16 + (lane >> 2);
#pragma unroll
        for (int h2 = 0; h2 < 2; h2++) {
            int row = rbase + 8 * h2;
            int orow = (EPI == 2) ? win_row_to_token(row) : row;
#pragma unroll
            for (int nt = 0; nt < 8; nt++) {
                int col = n0 + nw + nt * 8 + (lane & 3) * 2;
                float v0 = acc[mi][nt][2 * h2 + 0] + bias[col];
                float v1 = acc[mi][nt][2 * h2 + 1] + bias[col + 1];
                if (EPI == 1) {
                    v0 = 0.5f * v0 * (1.0f + erff(v0 * 0.7071067811865475f));
                    v1 = 0.5f * v1 * (1.0f + erff(v1 * 0.7071067811865475f));
                } else if (EPI == 2 || EPI == 3) {
                    const float* ap = add + (size_t)orow * N + col;
                    v0 += ap[0];
                    v1 += ap[1];
                }
                OutT* cp = C + (size_t)orow * N + col;
                if (sizeof(OutT) == 2) {
                    __nv_bfloat162 pk;
                    pk.x = __float2bfloat16(v0);
                    pk.y = __float2bfloat16(v1);
                    *(__nv_bfloat162*)cp = pk;
                } else {
                    float2 pk = make_float2(v0, v1);
                    *(float2*)cp = pk;
                }
            }
        }
    }
}

// ---------------- tensor-core window attention ----------------
__global__ void __launch_bounds__(256) attn_mma_kernel(
    const bf16* __restrict__ QKV, const bf16* __restrict__ bias_all,
    bf16* __restrict__ O)
{
    __shared__ __align__(16) bf16 sQ[2][64][40];
    __shared__ __align__(16) bf16 sK[2][64][40];
    __shared__ __align__(16) bf16 sV[2][64][40];
    __shared__ __align__(16) bf16 sB[2][64][72];

    int win = blockIdx.x, t = threadIdx.x;
    int widx = win & 63;
    int type = (((widx >> 3) == 7) ? 2 : 0) + (((widx & 7) == 7) ? 1 : 0);

    for (int i = t; i < 2 * 15 * 40; i += 256) {
        int hs = i / 600, rem = i % 600;
        int row = 49 + rem / 40, col = rem % 40;
        sK[hs][row][col] = __float2bfloat16(0.f);
        sV[hs][row][col] = __float2bfloat16(0.f);
    }

    int lane = t & 31, w = t >> 5;
    int hs = w >> 2, ww = w & 3;
    int r0 = ww * 16;
    int lrow = (lane & 7) + (lane & 8);
    int lcol = (lane & 16) >> 1;
    int qr = lane >> 2, qc = lane & 3;
    const float scale = 0.17677669529663687f;

    int lr = t >> 2, lc = t & 3;

    for (int p = 0; p < 6; p++) {
        __syncthreads();
        if (lr < 49) {
            const bf16* src = QKV + (size_t)(win * NTOK + lr) * QKVN + lc * 8;
#pragma unroll
            for (int hh = 0; hh < 2; hh++) {
                int h = p * 2 + hh;
                CP16(&sQ[hh][lr][lc * 8], src + h * HDIM);
                CP16(&sK[hh][lr][lc * 8], src + h * HDIM + CDIM);
                CP16(&sV[hh][lr][lc * 8], src + h * HDIM + 2 * CDIM);
            }
        }
#pragma unroll
        for (int hh = 0; hh < 2; hh++) {
            int h = p * 2 + hh;
            const bf16* bsrc = bias_all + (((size_t)type * NHEADS + h) * 64 + lr) * 64;
            CP16(&sB[hh][lr][lc * 8], bsrc + lc * 8);
            CP16(&sB[hh][lr][(lc + 4) * 8], bsrc + (lc + 4) * 8);
        }
        CP_COMMIT(); CP_WAIT(0);
        __syncthreads();

        float acc[8][4] = {};
#pragma unroll
        for (int kc = 0; kc < 32; kc += 16) {
            uint32_t a[4];
            ldm_x4(a, &sQ[hs][r0 + lrow][kc + lcol]);
            uint32_t bb[4][4];
#pragma unroll
            for (int nj = 0; nj < 4; nj++)
                ldm_x4(bb[nj], &sK[hs][nj * 16 + lrow][kc + lcol]);
#pragma unroll
            for (int nj = 0; nj < 4; nj++) {
                MMA16816(acc[nj * 2 + 0], a, bb[nj][0], bb[nj][2]);
                MMA16816(acc[nj * 2 + 1], a, bb[nj][1], bb[nj][3]);
            }
        }
#pragma unroll
        for (int cj = 0; cj < 4; cj++) {
            uint32_t bf[4];
            ldm_x4(bf, &sB[hs][r0 + lrow][cj * 16 + lcol]);
            float2 f0 = __bfloat1622float2(*(__nv_bfloat162*)&bf[0]);
            float2 f1 = __bfloat1622float2(*(__nv_bfloat162*)&bf[1]);
            float2 f2 = __bfloat1622float2(*(__nv_bfloat162*)&bf[2]);
            float2 f3 = __bfloat1622float2(*(__nv_bfloat162*)&bf[3]);
            acc[2 * cj][0] = acc[2 * cj][0] * scale + f0.x;
            acc[2 * cj][1] = acc[2 * cj][1] * scale + f0.y;
            acc[2 * cj][2] = acc[2 * cj][2] * scale + f1.x;
            acc[2 * cj][3] = acc[2 * cj][3] * scale + f1.y;
            acc[2 * cj + 1][0] = acc[2 * cj + 1][0] * scale + f2.x;
            acc[2 * cj + 1][1] = acc[2 * cj + 1][1] * scale + f2.y;
            acc[2 * cj + 1][2] = acc[2 * cj + 1][2] * scale + f3.x;
            acc[2 * cj + 1][3] = acc[2 * cj + 1][3] * scale + f3.y;
        }
        float mx1 = -1e30f, mx2 = -1e30f;
#pragma unroll
        for (int nt = 0; nt < 8; nt++) {
            mx1 = fmaxf(mx1, fmaxf(acc[nt][0], acc[nt][1]));
            mx2 = fmaxf(mx2, fmaxf(acc[nt][2], acc[nt][3]));
        }
        mx1 = fmaxf(mx1, __shfl_xor_sync(0xffffffffu, mx1, 1));
        mx1 = fmaxf(mx1, __shfl_xor_sync(0xffffffffu, mx1, 2));
        mx2 = fmaxf(mx2, __shfl_xor_sync(0xffffffffu, mx2, 1));
        mx2 = fmaxf(mx2, __shfl_xor_sync(0xffffffffu, mx2, 2));
        float sum1 = 0.f, sum2 = 0.f;
#pragma unroll
        for (int nt = 0; nt < 8; nt++) {
            acc[nt][0] = __expf(acc[nt][0] - mx1);
            acc[nt][1] = __expf(acc[nt][1] - mx1);
            acc[nt][2] = __expf(acc[nt][2] - mx2);
            acc[nt][3] = __expf(acc[nt][3] - mx2);
            sum1 += acc[nt][0] + acc[nt][1];
            sum2 += acc[nt][2] + acc[nt][3];
        }
        sum1 += __shfl_xor_sync(0xffffffffu, sum1, 1);
        sum1 += __shfl_xor_sync(0xffffffffu, sum1, 2);
        sum2 += __shfl_xor_sync(0xffffffffu, sum2, 1);
        sum2 += __shfl_xor_sync(0xffffffffu, sum2, 2);
        float inv1 = 1.0f / sum1, inv2 = 1.0f / sum2;

        float o[4][4] = {};
#pragma unroll
        for (int kc2 = 0; kc2 < 4; kc2++) {
            uint32_t pa[4];
            pa[0] = packbf(acc[2 * kc2][0],     acc[2 * kc2][1]);
            pa[1] = packbf(acc[2 * kc2][2],     acc[2 * kc2][3]);
            pa[2] = packbf(acc[2 * kc2 + 1][0], acc[2 * kc2 + 1][1]);
            pa[3] = packbf(acc[2 * kc2 + 1][2], acc[2 * kc2 + 1][3]);
#pragma unroll
            for (int nj = 0; nj < 2; nj++) {
                uint32_t vb[4];
                ldm_x4t(vb, &sV[hs][kc2 * 16 + lrow][nj * 16 + lcol]);
                MMA16816(o[nj * 2 + 0], pa, vb[0], vb[1]);
                MMA16816(o[nj * 2 + 1], pa, vb[2], vb[3]);
            }
        }
        int H = p * 2 + hs;
        int row1 = r0 + qr, row2 = r0 + qr + 8;
        if (row1 < NTOK) {
            bf16* dst = O + (size_t)(win * NTOK + row1) * CDIM + H * HDIM + qc * 2;
#pragma unroll
            for (int nt = 0; nt < 4; nt++) {
                __nv_bfloat162 pk;
                pk.x = __float2bfloat16(o[nt][0] * inv1);
                pk.y = __float2bfloat16(o[nt][1] * inv1);
                *(__nv_bfloat162*)(dst + nt * 8) = pk;
            }
        }
        if (row2 < NTOK) {
            bf16* dst = O + (size_t)(win * NTOK + row2) * CDIM + H * HDIM + qc * 2;
#pragma unroll
            for (int nt = 0; nt < 4; nt++) {
                __nv_bfloat162 pk;
                pk.x = __float2bfloat16(o[nt][2] * inv2);
                pk.y = __float2bfloat16(o[nt][3] * inv2);
                *(__nv_bfloat162*)(dst + nt * 8) = pk;
            }
        }
    }
}

// ---------------- launch ----------------
extern "C" void kernel_launch(void* const* d_in, const int* in_sizes, int n_in,
                              void* d_out, int out_size)
{
    const float* hidden  = (const float*)d_in[0];
    const float* ln1_g   = (const float*)d_in[1];
    const float* ln1_b   = (const float*)d_in[2];
    const float* q_w     = (const float*)d_in[3];
    const float* q_b     = (const float*)d_in[4];
    const float* k_w     = (const float*)d_in[5];
    const float* k_b     = (const float*)d_in[6];
    const float* v_w     = (const float*)d_in[7];
    const float* v_b     = (const float*)d_in[8];
    const float* rpb     = (const float*)d_in[9];
    const int*   rpi     = (const int*)  d_in[10];
    const float* proj_w  = (const float*)d_in[11];
    const float* proj_b  = (const float*)d_in[12];
    const float* ln2_g   = (const float*)d_in[13];
    const float* ln2_b   = (const float*)d_in[14];
    const float* fc1_w   = (const float*)d_in[15];
    const float* fc1_b   = (const float*)d_in[16];
    const float* fc2_w   = (const float*)d_in[17];
    const float* fc2_b   = (const float*)d_in[18];
    float* out = (float*)d_out;

    bf16 *p_xw, *p_qkv, *p_ctx, *p_ln2, *p_y1;
    bf16 *p_wqkv, *p_wp, *p_w1, *p_w2, *p_bias;
    float *p_h, *p_bqkv;
    cudaGetSymbolAddress((void**)&p_xw,   g_xw);
    cudaGetSymbolAddress((void**)&p_qkv,  g_qkv);
    cudaGetSymbolAddress((void**)&p_ctx,  g_ctx);
    cudaGetSymbolAddress((void**)&p_h,    g_h);
    cudaGetSymbolAddress((void**)&p_ln2,  g_ln2);
    cudaGetSymbolAddress((void**)&p_y1,   g_y1);
    cudaGetSymbolAddress((void**)&p_wqkv, g_wqkv);
    cudaGetSymbolAddress((void**)&p_bqkv, g_bqkv);
    cudaGetSymbolAddress((void**)&p_wp,   g_wp);
    cudaGetSymbolAddress((void**)&p_w1,   g_w1);
    cudaGetSymbolAddress((void**)&p_w2,   g_w2);
    cudaGetSymbolAddress((void**)&p_bias, g_bias);

    cudaFuncSetAttribute(mma_gemm<0, bf16>,  cudaFuncAttributeMaxDynamicSharedMemorySize, TCSMEM);
    cudaFuncSetAttribute(mma_gemm<1, bf16>,  cudaFuncAttributeMaxDynamicSharedMemorySize, TCSMEM);
    cudaFuncSetAttribute(mma_gemm<2, float>, cudaFuncAttributeMaxDynamicSharedMemorySize, TCSMEM);
    cudaFuncSetAttribute(mma_gemm<3, float>, cudaFuncAttributeMaxDynamicSharedMemorySize, TCSMEM);

    // weight packing / conversion + bias tiles
    const int WSMALL = CDIM * CDIM / 4, WBIG = CDIM * FFNDIM / 4;
    pack_qkv_kernel<<<(QKV_W4 + QKVN / 4 + 255) / 256, 256>>>(
        q_w, k_w, v_w, q_b, k_b, v_b, p_wqkv, p_bqkv);
    f2bf_kernel<<<(WSMALL + 255) / 256, 256>>>(proj_w, p_wp, WSMALL);
    f2bf_kernel<<<(WBIG   + 255) / 256, 256>>>(fc1_w,  p_w1, WBIG);
    f2bf_kernel<<<(WBIG   + 255) / 256, 256>>>(fc2_w,  p_w2, WBIG);
    bias_kernel<<<dim3(4, NHEADS), 256>>>(rpb, rpi, p_bias);

    // 1) LN1 + shift-roll + window partition (gather)
    ln_kernel<<<MTOK, 128>>>(hidden, ln1_g, ln1_b, p_xw, 1);

    // 2) fused QKV projection
    mma_gemm<0, bf16><<<dim3(QKVN / GBN, MTOK / GBM), 128, TCSMEM>>>(
        p_xw, p_wqkv, p_bqkv, nullptr, p_qkv, MTOK, QKVN, CDIM);

    // 3) windowed attention (tensor cores)
    attn_mma_kernel<<<TOTWIN, 256>>>(p_qkv, p_bias, p_ctx);

    // 4) output projection + window-reverse + roll-back + residual (scatter)
    mma_gemm<2, float><<<dim3(CDIM / GBN, MTOK / GBM), 128, TCSMEM>>>(
        p_ctx, p_wp, proj_b, hidden, p_h, MTOK, CDIM, CDIM);

    // 5) LN2
    ln_kernel<<<MTOK, 128>>>(p_h, ln2_g, ln2_b, p_ln2, 0);

    // 6) fc1 + exact GELU
    mma_gemm<1, bf16><<<dim3(FFNDIM / GBN, MTOK / GBM), 128, TCSMEM>>>(
        p_ln2, p_w1, fc1_b, nullptr, p_y1, MTOK, FFNDIM, CDIM);

    // 7) fc2 + residual -> final output
    mma_gemm<3, float><<<dim3(CDIM / GBN, MTOK / GBM), 128, TCSMEM>>>(
        p_y1, p_w2, fc2_b, p_h, out, MTOK, CDIM, FFNDIM);
}

// round 7
// speedup vs baseline: 1.1575x; 1.1575x over previous
#include <cuda_runtime.h>
#include <cuda_bf16.h>
#include <math.h>
#include <stdint.h>

// ---------------- problem constants ----------------
#define BATCH   8
#define HIMG    56
#define WIMG    56
#define CDIM    384
#define NHEADS  12
#define HDIM    32
#define WIN     7
#define NTOK    49
#define SHIFT_S 3
#define TOTWIN  512
#define MTOK    25088
#define FFNDIM  1536
#define QKVN    1152          // 3*CDIM

typedef __nv_bfloat16 bf16;

// ---------------- scratch (device globals; allocation-free) ----------------
__device__ bf16  g_xw  [MTOK * CDIM];
__device__ bf16  g_qkv [MTOK * QKVN];
__device__ bf16  g_ctx [MTOK * CDIM];
__device__ float g_h   [MTOK * CDIM];
__device__ bf16  g_ln2 [MTOK * CDIM];
__device__ bf16  g_y1  [MTOK * FFNDIM];
__device__ bf16  g_wqkv[CDIM * QKVN];   // [K][N] packed q|k|v
__device__ float g_bqkv[QKVN];
__device__ bf16  g_wp  [CDIM * CDIM];
__device__ bf16  g_w1  [CDIM * FFNDIM];
__device__ bf16  g_w2  [FFNDIM * CDIM];
__device__ bf16  g_bias[4 * NHEADS * 64 * 64];

// windowed row r <-> original token t (same map both directions)
__device__ __forceinline__ int win_row_to_token(int r) {
    int b    = r / (HIMG * WIMG);
    int rem  = r - b * (HIMG * WIMG);
    int widx = rem / NTOK;
    int tok  = rem - widx * NTOK;
    int wi = widx >> 3, wj = widx & 7;
    int i = tok / WIN, j = tok - i * WIN;
    int sh = wi * WIN + i + SHIFT_S; if (sh >= HIMG) sh -= HIMG;
    int sw = wj * WIN + j + SHIFT_S; if (sw >= WIMG) sw -= WIMG;
    return b * (HIMG * WIMG) + sh * WIMG + sw;
}

// ---------------- fp32 -> bf16 convert ----------------
__global__ void __launch_bounds__(256) f2bf_kernel(
    const float* __restrict__ src, bf16* __restrict__ dst, int n4)
{
    int i = blockIdx.x * blockDim.x + threadIdx.x;
    if (i < n4) {
        float4 v = ((const float4*)src)[i];
        bf16 o[4] = {__float2bfloat16(v.x), __float2bfloat16(v.y),
                     __float2bfloat16(v.z), __float2bfloat16(v.w)};
        *(uint64_t*)(dst + i * 4) = *(uint64_t*)o;
    }
}

// ---------------- pack q|k|v weights + biases ----------------
#define QKV_W4 (CDIM * QKVN / 4)
__global__ void __launch_bounds__(256) pack_qkv_kernel(
    const float* __restrict__ qw, const float* __restrict__ kw,
    const float* __restrict__ vw, const float* __restrict__ qb,
    const float* __restrict__ kb, const float* __restrict__ vb,
    bf16* __restrict__ wout, float* __restrict__ bout)
{
    int i = blockIdx.x * blockDim.x + threadIdx.x;
    if (i < QKV_W4) {
        int row = i / (QKVN / 4);
        int col = (i % (QKVN / 4)) * 4;
        const float* src = (col < CDIM) ? qw : (col < 2 * CDIM ? kw : vw);
        int c = col - (col < CDIM ? 0 : (col < 2 * CDIM ? CDIM : 2 * CDIM));
        float4 v = *(const float4*)(src + (size_t)row * CDIM + c);
        bf16 o[4] = {__float2bfloat16(v.x), __float2bfloat16(v.y),
                     __float2bfloat16(v.z), __float2bfloat16(v.w)};
        *(uint64_t*)(wout + (size_t)i * 4) = *(uint64_t*)o;
    } else if (i < QKV_W4 + QKVN / 4) {
        int col = (i - QKV_W4) * 4;
        const float* src = (col < CDIM) ? qb : (col < 2 * CDIM ? kb : vb);
        int c = col - (col < CDIM ? 0 : (col < 2 * CDIM ? CDIM : 2 * CDIM));
        *(float4*)(bout + col) = *(const float4*)(src + c);
    }
}

// ---------------- precompute attention bias+mask tiles ----------------
__global__ void __launch_bounds__(256) bias_kernel(
    const float* __restrict__ rpb, const int* __restrict__ rpi,
    bf16* __restrict__ out)
{
    int type = blockIdx.x, h = blockIdx.y;
    for (int idx = threadIdx.x; idx < 64 * 64; idx += 256) {
        int n = idx >> 6, m = idx & 63;
        float v;
        if (m >= 49)      v = -1e30f;
        else if (n >= 49) v = 0.f;
        else {
            v = rpb[rpi[n * 49 + m] * NHEADS + h];
            int ni = n / 7, nj = n % 7, mi = m / 7, mj = m % 7;
            int cn = ((type & 2) ? (ni < 4 ? 1 : 2) : 0) * 3 + ((type & 1) ? (nj < 4 ? 1 : 2) : 0);
            int cm = ((type & 2) ? (mi < 4 ? 1 : 2) : 0) * 3 + ((type & 1) ? (mj < 4 ? 1 : 2) : 0);
            if (cn != cm) v -= 100.0f;
        }
        out[(((size_t)type * NHEADS + h) * 64 + n) * 64 + m] = __float2bfloat16(v);
    }
}

// ---------------- LayerNorm (fp32 in, bf16 out) ----------------
__global__ void __launch_bounds__(128) ln_kernel(
    const float* __restrict__ x, const float* __restrict__ g,
    const float* __restrict__ b, bf16* __restrict__ out, int permute)
{
    int r = blockIdx.x;
    int t = permute ? win_row_to_token(r) : r;
    const float* xi = x + (size_t)t * CDIM;
    bf16*        yo = out + (size_t)r * CDIM;
    int tid = threadIdx.x;

    float v[3];
    float s = 0.f, ss = 0.f;
#pragma unroll
    for (int i = 0; i < 3; i++) {
        v[i] = xi[tid + i * 128];
        s += v[i]; ss += v[i] * v[i];
    }
#pragma unroll
    for (int o = 16; o; o >>= 1) {
        s  += __shfl_xor_sync(0xffffffffu, s,  o);
        ss += __shfl_xor_sync(0xffffffffu, ss, o);
    }
    __shared__ float red[8];
    __shared__ float stat[2];
    int wid = tid >> 5, lane = tid & 31;
    if (lane == 0) { red[wid] = s; red[4 + wid] = ss; }
    __syncthreads();
    if (tid == 0) {
        float S  = red[0] + red[1] + red[2] + red[3];
        float SS = red[4] + red[5] + red[6] + red[7];
        float mu = S * (1.0f / CDIM);
        float var = SS * (1.0f / CDIM) - mu * mu;
        stat[0] = mu;
        stat[1] = rsqrtf(var + 1e-5f);
    }
    __syncthreads();
    float mu = stat[0], rstd = stat[1];
#pragma unroll
    for (int i = 0; i < 3; i++) {
        int c = tid + i * 128;
        yo[c] = __float2bfloat16((v[i] - mu) * rstd * g[c] + b[c]);
    }
}

// ---------------- mma helpers ----------------
#define CP16(dst, src) \
    asm volatile("cp.async.ca.shared.global [%0], [%1], 16;\n" :: \
        "r"((uint32_t)__cvta_generic_to_shared(dst)), "l"(src))
#define CP_COMMIT()  asm volatile("cp.async.commit_group;\n" ::)
#define CP_WAIT(n)   asm volatile("cp.async.wait_group %0;\n" :: "n"(n))

__device__ __forceinline__ void ldm_x4(uint32_t* r, const void* p) {
    uint32_t a = (uint32_t)__cvta_generic_to_shared(p);
    asm volatile("ldmatrix.sync.aligned.m8n8.x4.shared.b16 {%0,%1,%2,%3},[%4];"
        : "=r"(r[0]), "=r"(r[1]), "=r"(r[2]), "=r"(r[3]) : "r"(a));
}
__device__ __forceinline__ void ldm_x4t(uint32_t* r, const void* p) {
    uint32_t a = (uint32_t)__cvta_generic_to_shared(p);
    asm volatile("ldmatrix.sync.aligned.m8n8.x4.trans.shared.b16 {%0,%1,%2,%3},[%4];"
        : "=r"(r[0]), "=r"(r[1]), "=r"(r[2]), "=r"(r[3]) : "r"(a));
}
#define MMA16816(d, a, b0, b1) \
    asm volatile("mma.sync.aligned.m16n8k16.row.col.f32.bf16.bf16.f32 " \
        "{%0,%1,%2,%3},{%4,%5,%6,%7},{%8,%9},{%0,%1,%2,%3};" \
        : "+f"(d[0]), "+f"(d[1]), "+f"(d[2]), "+f"(d[3]) \
        : "r"(a[0]), "r"(a[1]), "r"(a[2]), "r"(a[3]), "r"(b0), "r"(b1))

__device__ __forceinline__ uint32_t packbf(float lo, float hi) {
    __nv_bfloat162 h = __floats2bfloat162_rn(lo, hi);
    return *(uint32_t*)&h;
}

// ---------------- HMMA bf16 GEMM: 128x128x64, 8 warps of 32x64 -------------
// 2-stage cp.async double buffer (GBK=64), XOR-swizzled smem,
// one __syncthreads per 64-K iteration. R3-proven warp layout.
// EPI 0: store  1: exact GELU  2: scatter+residual  3: residual
#define GBM 128
#define GBN 128
#define GBK 64
#define STG_A (GBM * GBK)            // 8192 elems per stage
#define STG_B (GBK * GBN)            // 8192 elems per stage
#define TCSMEM (2 * (STG_A + STG_B) * 2)   // 65536 bytes

template <int EPI, typename OutT>
__global__ void __launch_bounds__(256) mma_gemm(
    const bf16* __restrict__ A, const bf16* __restrict__ B,
    const float* __restrict__ bias, const float* __restrict__ add,
    OutT* __restrict__ C, int M, int N, int K)
{
    extern __shared__ __align__(16) bf16 sm[];
    bf16* As = sm;                   // 2 stages x 8192
    bf16* Bs = sm + 2 * STG_A;       // 2 stages x 8192

    int t = threadIdx.x;
    int m0 = blockIdx.y * GBM, n0 = blockIdx.x * GBN;

    // A loader: 2 threads per row, 4 x 16B chunks each (8 chunks of 64 cols)
    int arow = t >> 1, ac0 = (t & 1) * 4;
    const bf16* Ag = A + (size_t)(m0 + arow) * K + ac0 * 8;
    int aswz[4];
#pragma unroll
    for (int j = 0; j < 4; j++)
        aswz[j] = arow * 64 + (((ac0 + j) ^ (arow & 7)) << 3);

    // B loader: 4 threads per k-row, 4 x 16B chunks each (16 chunks of 128)
    int brow = t >> 2, bc0 = (t & 3) * 4;
    const bf16* Bg = B + (size_t)brow * N + n0 + bc0 * 8;
    int bswz[4];
#pragma unroll
    for (int j = 0; j < 4; j++)
        bswz[j] = brow * 128 + (((bc0 + j) ^ (brow & 7)) << 3);

    int lane = t & 31, w = t >> 5;
    int m0w = (w >> 1) * 32, nw = (w & 1) * 64;   // warp tile 32x64 (R3 layout)
    int lrow = (lane & 7) + (lane & 8);
    int lcol = (lane & 16) >> 1;

    float acc[2][8][4] = {};

    int nk = K / GBK;
    // prologue: stage 0
#pragma unroll
    for (int j = 0; j < 4; j++) {
        CP16(&As[aswz[j]], Ag + j * 8);
        CP16(&Bs[bswz[j]], Bg + j * 8);
    }
    CP_COMMIT();

    for (int i = 0; i < nk; i++) {
        CP_WAIT(0);                   // stage i landed
        __syncthreads();              // all warps done with the other buffer
        if (i + 1 < nk) {
            int s2 = (i + 1) & 1;
            int k0 = (i + 1) * GBK;
#pragma unroll
            for (int j = 0; j < 4; j++) {
                CP16(&As[s2 * STG_A + aswz[j]], Ag + k0 + j * 8);
                CP16(&Bs[s2 * STG_B + bswz[j]], Bg + (size_t)k0 * N + j * 8);
            }
            CP_COMMIT();
        }
        int cs = i & 1;
        const bf16* Asc = As + cs * STG_A;
        const bf16* Bsc = Bs + cs * STG_B;
#pragma unroll
        for (int kk = 0; kk < GBK; kk += 16) {
            uint32_t a[2][4], b[4][4];
#pragma unroll
            for (int mi = 0; mi < 2; mi++) {
                int R = m0w + mi * 16 + lrow;
                int cr = (kk + lcol) >> 3;
                ldm_x4(a[mi], Asc + R * 64 + ((cr ^ (R & 7)) << 3));
            }
#pragma unroll
            for (int nj = 0; nj < 4; nj++) {
                int Kr = kk + lrow;
                int cn = (nw + nj * 16 + lcol) >> 3;
                ldm_x4t(b[nj], Bsc + Kr * 128 + ((cn ^ (Kr & 7)) << 3));
            }
#pragma unroll
            for (int mi = 0; mi < 2; mi++) {
#pragma unroll
                for (int nt = 0; nt < 8; nt++)
                    MMA16816(acc[mi][nt], a[mi],
                             b[nt >> 1][(nt & 1) * 2], b[nt >> 1][(nt & 1) * 2 + 1]);
            }
        }
    }

    // epilogue (identical to R3)
#pragma unroll
    for (int mi = 0; mi < 2; mi++) {
        int rbase = m0 + m0w + mi * 16 + (lane >> 2);
#pragma unroll
        for (int h2 = 0; h2 < 2; h2++) {
            int row = rbase + 8 * h2;
            int orow = (EPI == 2) ? win_row_to_token(row) : row;
#pragma unroll
            for (int nt = 0; nt < 8; nt++) {
                int col = n0 + nw + nt * 8 + (lane & 3) * 2;
                float v0 = acc[mi][nt][2 * h2 + 0] + bias[col];
                float v1 = acc[mi][nt][2 * h2 + 1] + bias[col + 1];
                if (EPI == 1) {
                    v0 = 0.5f * v0 * (1.0f + erff(v0 * 0.7071067811865475f));
                    v1 = 0.5f * v1 * (1.0f + erff(v1 * 0.7071067811865475f));
                } else if (EPI == 2 || EPI == 3) {
                    const float* ap = add + (size_t)orow * N + col;
                    v0 += ap[0];
                    v1 += ap[1];
                }
                OutT* cp = C + (size_t)orow * N + col;
                if (sizeof(OutT) == 2) {
                    __nv_bfloat162 pk;
                    pk.x = __float2bfloat16(v0);
                    pk.y = __float2bfloat16(v1);
                    *(__nv_bfloat162*)cp = pk;
                } else {
                    float2 pk = make_float2(v0, v1);
                    *(float2*)cp = pk;
                }
            }
        }
    }
}

// ---------------- tensor-core window attention (R3, proven) ----------------
__global__ void __launch_bounds__(256) attn_mma_kernel(
    const bf16* __restrict__ QKV, const bf16* __restrict__ bias_all,
    bf16* __restrict__ O)
{
    __shared__ __align__(16) bf16 sQ[2][64][40];
    __shared__ __align__(16) bf16 sK[2][64][40];
    __shared__ __align__(16) bf16 sV[2][64][40];
    __shared__ __align__(16) bf16 sB[2][64][72];

    int win = blockIdx.x, t = threadIdx.x;
    int widx = win & 63;
    int type = (((widx >> 3) == 7) ? 2 : 0) + (((widx & 7) == 7) ? 1 : 0);

    for (int i = t; i < 2 * 15 * 40; i += 256) {
        int hs = i / 600, rem = i % 600;
        int row = 49 + rem / 40, col = rem % 40;
        sK[hs][row][col] = __float2bfloat16(0.f);
        sV[hs][row][col] = __float2bfloat16(0.f);
    }

    int lane = t & 31, w = t >> 5;
    int hs = w >> 2, ww = w & 3;
    int r0 = ww * 16;
    int lrow = (lane & 7) + (lane & 8);
    int lcol = (lane & 16) >> 1;
    int qr = lane >> 2, qc = lane & 3;
    const float scale = 0.17677669529663687f;

    int lr = t >> 2, lc = t & 3;

    for (int p = 0; p < 6; p++) {
        __syncthreads();
        if (lr < 49) {
            const bf16* src = QKV + (size_t)(win * NTOK + lr) * QKVN + lc * 8;
#pragma unroll
            for (int hh = 0; hh < 2; hh++) {
                int h = p * 2 + hh;
                CP16(&sQ[hh][lr][lc * 8], src + h * HDIM);
                CP16(&sK[hh][lr][lc * 8], src + h * HDIM + CDIM);
                CP16(&sV[hh][lr][lc * 8], src + h * HDIM + 2 * CDIM);
            }
        }
#pragma unroll
        for (int hh = 0; hh < 2; hh++) {
            int h = p * 2 + hh;
            const bf16* bsrc = bias_all + (((size_t)type * NHEADS + h) * 64 + lr) * 64;
            CP16(&sB[hh][lr][lc * 8], bsrc + lc * 8);
            CP16(&sB[hh][lr][(lc + 4) * 8], bsrc + (lc + 4) * 8);
        }
        CP_COMMIT(); CP_WAIT(0);
        __syncthreads();

        float acc[8][4] = {};
#pragma unroll
        for (int kc = 0; kc < 32; kc += 16) {
            uint32_t a[4];
            ldm_x4(a, &sQ[hs][r0 + lrow][kc + lcol]);
            uint32_t bb[4][4];
#pragma unroll
            for (int nj = 0; nj < 4; nj++)
                ldm_x4(bb[nj], &sK[hs][nj * 16 + lrow][kc + lcol]);
#pragma unroll
            for (int nj = 0; nj < 4; nj++) {
                MMA16816(acc[nj * 2 + 0], a, bb[nj][0], bb[nj][2]);
                MMA16816(acc[nj * 2 + 1], a, bb[nj][1], bb[nj][3]);
            }
        }
#pragma unroll
        for (int cj = 0; cj < 4; cj++) {
            uint32_t bf[4];
            ldm_x4(bf, &sB[hs][r0 + lrow][cj * 16 + lcol]);
            float2 f0 = __bfloat1622float2(*(__nv_bfloat162*)&bf[0]);
            float2 f1 = __bfloat1622float2(*(__nv_bfloat162*)&bf[1]);
            float2 f2 = __bfloat1622float2(*(__nv_bfloat162*)&bf[2]);
            float2 f3 = __bfloat1622float2(*(__nv_bfloat162*)&bf[3]);
            acc[2 * cj][0] = acc[2 * cj][0] * scale + f0.x;
            acc[2 * cj][1] = acc[2 * cj][1] * scale + f0.y;
            acc[2 * cj][2] = acc[2 * cj][2] * scale + f1.x;
            acc[2 * cj][3] = acc[2 * cj][3] * scale + f1.y;
            acc[2 * cj + 1][0] = acc[2 * cj + 1][0] * scale + f2.x;
            acc[2 * cj + 1][1] = acc[2 * cj + 1][1] * scale + f2.y;
            acc[2 * cj + 1][2] = acc[2 * cj + 1][2] * scale + f3.x;
            acc[2 * cj + 1][3] = acc[2 * cj + 1][3] * scale + f3.y;
        }
        float mx1 = -1e30f, mx2 = -1e30f;
#pragma unroll
        for (int nt = 0; nt < 8; nt++) {
            mx1 = fmaxf(mx1, fmaxf(acc[nt][0], acc[nt][1]));
            mx2 = fmaxf(mx2, fmaxf(acc[nt][2], acc[nt][3]));
        }
        mx1 = fmaxf(mx1, __shfl_xor_sync(0xffffffffu, mx1, 1));
        mx1 = fmaxf(mx1, __shfl_xor_sync(0xffffffffu, mx1, 2));
        mx2 = fmaxf(mx2, __shfl_xor_sync(0xffffffffu, mx2, 1));
        mx2 = fmaxf(mx2, __shfl_xor_sync(0xffffffffu, mx2, 2));
        float sum1 = 0.f, sum2 = 0.f;
#pragma unroll
        for (int nt = 0; nt < 8; nt++) {
            acc[nt][0] = __expf(acc[nt][0] - mx1);
            acc[nt][1] = __expf(acc[nt][1] - mx1);
            acc[nt][2] = __expf(acc[nt][2] - mx2);
            acc[nt][3] = __expf(acc[nt][3] - mx2);
            sum1 += acc[nt][0] + acc[nt][1];
            sum2 += acc[nt][2] + acc[nt][3];
        }
        sum1 += __shfl_xor_sync(0xffffffffu, sum1, 1);
        sum1 += __shfl_xor_sync(0xffffffffu, sum1, 2);
        sum2 += __shfl_xor_sync(0xffffffffu, sum2, 1);
        sum2 += __shfl_xor_sync(0xffffffffu, sum2, 2);
        float inv1 = 1.0f / sum1, inv2 = 1.0f / sum2;

        float o[4][4] = {};
#pragma unroll
        for (int kc2 = 0; kc2 < 4; kc2++) {
            uint32_t pa[4];
            pa[0] = packbf(acc[2 * kc2][0],     acc[2 * kc2][1]);
            pa[1] = packbf(acc[2 * kc2][2],     acc[2 * kc2][3]);
            pa[2] = packbf(acc[2 * kc2 + 1][0], acc[2 * kc2 + 1][1]);
            pa[3] = packbf(acc[2 * kc2 + 1][2], acc[2 * kc2 + 1][3]);
#pragma unroll
            for (int nj = 0; nj < 2; nj++) {
                uint32_t vb[4];
                ldm_x4t(vb, &sV[hs][kc2 * 16 + lrow][nj * 16 + lcol]);
                MMA16816(o[nj * 2 + 0], pa, vb[0], vb[1]);
                MMA16816(o[nj * 2 + 1], pa, vb[2], vb[3]);
            }
        }
        int H = p * 2 + hs;
        int row1 = r0 + qr, row2 = r0 + qr + 8;
        if (row1 < NTOK) {
            bf16* dst = O + (size_t)(win * NTOK + row1) * CDIM + H * HDIM + qc * 2;
#pragma unroll
            for (int nt = 0; nt < 4; nt++) {
                __nv_bfloat162 pk;
                pk.x = __float2bfloat16(o[nt][0] * inv1);
                pk.y = __float2bfloat16(o[nt][1] * inv1);
                *(__nv_bfloat162*)(dst + nt * 8) = pk;
            }
        }
        if (row2 < NTOK) {
            bf16* dst = O + (size_t)(win * NTOK + row2) * CDIM + H * HDIM + qc * 2;
#pragma unroll
            for (int nt = 0; nt < 4; nt++) {
                __nv_bfloat162 pk;
                pk.x = __float2bfloat16(o[nt][2] * inv2);
                pk.y = __float2bfloat16(o[nt][3] * inv2);
                *(__nv_bfloat162*)(dst + nt * 8) = pk;
            }
        }
    }
}

// ---------------- launch ----------------
extern "C" void kernel_launch(void* const* d_in, const int* in_sizes, int n_in,
                              void* d_out, int out_size)
{
    const float* hidden  = (const float*)d_in[0];
    const float* ln1_g   = (const float*)d_in[1];
    const float* ln1_b   = (const float*)d_in[2];
    const float* q_w     = (const float*)d_in[3];
    const float* q_b     = (const float*)d_in[4];
    const float* k_w     = (const float*)d_in[5];
    const float* k_b     = (const float*)d_in[6];
    const float* v_w     = (const float*)d_in[7];
    const float* v_b     = (const float*)d_in[8];
    const float* rpb     = (const float*)d_in[9];
    const int*   rpi     = (const int*)  d_in[10];
    const float* proj_w  = (const float*)d_in[11];
    const float* proj_b  = (const float*)d_in[12];
    const float* ln2_g   = (const float*)d_in[13];
    const float* ln2_b   = (const float*)d_in[14];
    const float* fc1_w   = (const float*)d_in[15];
    const float* fc1_b   = (const float*)d_in[16];
    const float* fc2_w   = (const float*)d_in[17];
    const float* fc2_b   = (const float*)d_in[18];
    float* out = (float*)d_out;

    bf16 *p_xw, *p_qkv, *p_ctx, *p_ln2, *p_y1;
    bf16 *p_wqkv, *p_wp, *p_w1, *p_w2, *p_bias;
    float *p_h, *p_bqkv;
    cudaGetSymbolAddress((void**)&p_xw,   g_xw);
    cudaGetSymbolAddress((void**)&p_qkv,  g_qkv);
    cudaGetSymbolAddress((void**)&p_ctx,  g_ctx);
    cudaGetSymbolAddress((void**)&p_h,    g_h);
    cudaGetSymbolAddress((void**)&p_ln2,  g_ln2);
    cudaGetSymbolAddress((void**)&p_y1,   g_y1);
    cudaGetSymbolAddress((void**)&p_wqkv, g_wqkv);
    cudaGetSymbolAddress((void**)&p_bqkv, g_bqkv);
    cudaGetSymbolAddress((void**)&p_wp,   g_wp);
    cudaGetSymbolAddress((void**)&p_w1,   g_w1);
    cudaGetSymbolAddress((void**)&p_w2,   g_w2);
    cudaGetSymbolAddress((void**)&p_bias, g_bias);

    cudaFuncSetAttribute(mma_gemm<0, bf16>,  cudaFuncAttributeMaxDynamicSharedMemorySize, TCSMEM);
    cudaFuncSetAttribute(mma_gemm<1, bf16>,  cudaFuncAttributeMaxDynamicSharedMemorySize, TCSMEM);
    cudaFuncSetAttribute(mma_gemm<2, float>, cudaFuncAttributeMaxDynamicSharedMemorySize, TCSMEM);
    cudaFuncSetAttribute(mma_gemm<3, float>, cudaFuncAttributeMaxDynamicSharedMemorySize, TCSMEM);

    // weight packing / conversion + bias tiles
    const int WSMALL = CDIM * CDIM / 4, WBIG = CDIM * FFNDIM / 4;
    pack_qkv_kernel<<<(QKV_W4 + QKVN / 4 + 255) / 256, 256>>>(
        q_w, k_w, v_w, q_b, k_b, v_b, p_wqkv, p_bqkv);
    f2bf_kernel<<<(WSMALL + 255) / 256, 256>>>(proj_w, p_wp, WSMALL);
    f2bf_kernel<<<(WBIG   + 255) / 256, 256>>>(fc1_w,  p_w1, WBIG);
    f2bf_kernel<<<(WBIG   + 255) / 256, 256>>>(fc2_w,  p_w2, WBIG);
    bias_kernel<<<dim3(4, NHEADS), 256>>>(rpb, rpi, p_bias);

    // 1) LN1 + shift-roll + window partition (gather)
    ln_kernel<<<MTOK, 128>>>(hidden, ln1_g, ln1_b, p_xw, 1);

    // 2) fused QKV projection
    mma_gemm<0, bf16><<<dim3(QKVN / GBN, MTOK / GBM), 256, TCSMEM>>>(
        p_xw, p_wqkv, p_bqkv, nullptr, p_qkv, MTOK, QKVN, CDIM);

    // 3) windowed attention (tensor cores)
    attn_mma_kernel<<<TOTWIN, 256>>>(p_qkv, p_bias, p_ctx);

    // 4) output projection + window-reverse + roll-back + residual (scatter)
    mma_gemm<2, float><<<dim3(CDIM / GBN, MTOK / GBM), 256, TCSMEM>>>(
        p_ctx, p_wp, proj_b, hidden, p_h, MTOK, CDIM, CDIM);

    // 5) LN2
    ln_kernel<<<MTOK, 128>>>(p_h, ln2_g, ln2_b, p_ln2, 0);

    // 6) fc1 + exact GELU
    mma_gemm<1, bf16><<<dim3(FFNDIM / GBN, MTOK / GBM), 256, TCSMEM>>>(
        p_ln2, p_w1, fc1_b, nullptr, p_y1, MTOK, FFNDIM, CDIM);

    // 7) fc2 + residual -> final output
    mma_gemm<3, float><<<dim3(CDIM / GBN, MTOK / GBM), 256, TCSMEM>>>(
        p_y1, p_w2, fc2_b, p_h, out, MTOK, CDIM, FFNDIM);
}

// round 8
// speedup vs baseline: 1.4850x; 1.2830x over previous
#include <cuda_runtime.h>
#include <cuda_bf16.h>
#include <math.h>
#include <stdint.h>

// ---------------- problem constants ----------------
#define BATCH   8
#define HIMG    56
#define WIMG    56
#define CDIM    384
#define NHEADS  12
#define HDIM    32
#define WIN     7
#define NTOK    49
#define SHIFT_S 3
#define TOTWIN  512
#define MTOK    25088
#define FFNDIM  1536
#define QKVN    1152          // 3*CDIM

typedef __nv_bfloat16 bf16;

// ---------------- scratch (device globals; allocation-free) ----------------
__device__ bf16  g_xw  [MTOK * CDIM];
__device__ bf16  g_qkv [MTOK * QKVN];
__device__ bf16  g_ctx [MTOK * CDIM];
__device__ float g_h   [MTOK * CDIM];
__device__ bf16  g_ln2 [MTOK * CDIM];
__device__ bf16  g_y1  [MTOK * FFNDIM];
__device__ bf16  g_wqkv[CDIM * QKVN];   // [K][N] packed q|k|v
__device__ float g_bqkv[QKVN];
__device__ bf16  g_wp  [CDIM * CDIM];
__device__ bf16  g_w1  [CDIM * FFNDIM];
__device__ bf16  g_w2  [FFNDIM * CDIM];
__device__ bf16  g_bias[4 * NHEADS * 64 * 64];

// windowed row r <-> original token t (same map both directions)
__device__ __forceinline__ int win_row_to_token(int r) {
    int b    = r / (HIMG * WIMG);
    int rem  = r - b * (HIMG * WIMG);
    int widx = rem / NTOK;
    int tok  = rem - widx * NTOK;
    int wi = widx >> 3, wj = widx & 7;
    int i = tok / WIN, j = tok - i * WIN;
    int sh = wi * WIN + i + SHIFT_S; if (sh >= HIMG) sh -= HIMG;
    int sw = wj * WIN + j + SHIFT_S; if (sw >= WIMG) sw -= WIMG;
    return b * (HIMG * WIMG) + sh * WIMG + sw;
}

// ---------------- fp32 -> bf16 convert ----------------
__global__ void __launch_bounds__(256) f2bf_kernel(
    const float* __restrict__ src, bf16* __restrict__ dst, int n4)
{
    int i = blockIdx.x * blockDim.x + threadIdx.x;
    if (i < n4) {
        float4 v = ((const float4*)src)[i];
        bf16 o[4] = {__float2bfloat16(v.x), __float2bfloat16(v.y),
                     __float2bfloat16(v.z), __float2bfloat16(v.w)};
        *(uint64_t*)(dst + i * 4) = *(uint64_t*)o;
    }
}

// ---------------- pack q|k|v weights + biases ----------------
#define QKV_W4 (CDIM * QKVN / 4)
__global__ void __launch_bounds__(256) pack_qkv_kernel(
    const float* __restrict__ qw, const float* __restrict__ kw,
    const float* __restrict__ vw, const float* __restrict__ qb,
    const float* __restrict__ kb, const float* __restrict__ vb,
    bf16* __restrict__ wout, float* __restrict__ bout)
{
    int i = blockIdx.x * blockDim.x + threadIdx.x;
    if (i < QKV_W4) {
        int row = i / (QKVN / 4);
        int col = (i % (QKVN / 4)) * 4;
        const float* src = (col < CDIM) ? qw : (col < 2 * CDIM ? kw : vw);
        int c = col - (col < CDIM ? 0 : (col < 2 * CDIM ? CDIM : 2 * CDIM));
        float4 v = *(const float4*)(src + (size_t)row * CDIM + c);
        bf16 o[4] = {__float2bfloat16(v.x), __float2bfloat16(v.y),
                     __float2bfloat16(v.z), __float2bfloat16(v.w)};
        *(uint64_t*)(wout + (size_t)i * 4) = *(uint64_t*)o;
    } else if (i < QKV_W4 + QKVN / 4) {
        int col = (i - QKV_W4) * 4;
        const float* src = (col < CDIM) ? qb : (col < 2 * CDIM ? kb : vb);
        int c = col - (col < CDIM ? 0 : (col < 2 * CDIM ? CDIM : 2 * CDIM));
        *(float4*)(bout + col) = *(const float4*)(src + c);
    }
}

// ---------------- precompute attention bias+mask tiles ----------------
__global__ void __launch_bounds__(256) bias_kernel(
    const float* __restrict__ rpb, const int* __restrict__ rpi,
    bf16* __restrict__ out)
{
    int type = blockIdx.x, h = blockIdx.y;
    for (int idx = threadIdx.x; idx < 64 * 64; idx += 256) {
        int n = idx >> 6, m = idx & 63;
        float v;
        if (m >= 49)      v = -1e30f;
        else if (n >= 49) v = 0.f;
        else {
            v = rpb[rpi[n * 49 + m] * NHEADS + h];
            int ni = n / 7, nj = n % 7, mi = m / 7, mj = m % 7;
            int cn = ((type & 2) ? (ni < 4 ? 1 : 2) : 0) * 3 + ((type & 1) ? (nj < 4 ? 1 : 2) : 0);
            int cm = ((type & 2) ? (mi < 4 ? 1 : 2) : 0) * 3 + ((type & 1) ? (mj < 4 ? 1 : 2) : 0);
            if (cn != cm) v -= 100.0f;
        }
        out[(((size_t)type * NHEADS + h) * 64 + n) * 64 + m] = __float2bfloat16(v);
    }
}

// ---------------- LayerNorm (fp32 in, bf16 out) ----------------
__global__ void __launch_bounds__(128) ln_kernel(
    const float* __restrict__ x, const float* __restrict__ g,
    const float* __restrict__ b, bf16* __restrict__ out, int permute)
{
    int r = blockIdx.x;
    int t = permute ? win_row_to_token(r) : r;
    const float* xi = x + (size_t)t * CDIM;
    bf16*        yo = out + (size_t)r * CDIM;
    int tid = threadIdx.x;

    float v[3];
    float s = 0.f, ss = 0.f;
#pragma unroll
    for (int i = 0; i < 3; i++) {
        v[i] = xi[tid + i * 128];
        s += v[i]; ss += v[i] * v[i];
    }
#pragma unroll
    for (int o = 16; o; o >>= 1) {
        s  += __shfl_xor_sync(0xffffffffu, s,  o);
        ss += __shfl_xor_sync(0xffffffffu, ss, o);
    }
    __shared__ float red[8];
    __shared__ float stat[2];
    int wid = tid >> 5, lane = tid & 31;
    if (lane == 0) { red[wid] = s; red[4 + wid] = ss; }
    __syncthreads();
    if (tid == 0) {
        float S  = red[0] + red[1] + red[2] + red[3];
        float SS = red[4] + red[5] + red[6] + red[7];
        float mu = S * (1.0f / CDIM);
        float var = SS * (1.0f / CDIM) - mu * mu;
        stat[0] = mu;
        stat[1] = rsqrtf(var + 1e-5f);
    }
    __syncthreads();
    float mu = stat[0], rstd = stat[1];
#pragma unroll
    for (int i = 0; i < 3; i++) {
        int c = tid + i * 128;
        yo[c] = __float2bfloat16((v[i] - mu) * rstd * g[c] + b[c]);
    }
}

// ---------------- mma helpers ----------------
#define CP16(dst, src) \
    asm volatile("cp.async.ca.shared.global [%0], [%1], 16;\n" :: \
        "r"((uint32_t)__cvta_generic_to_shared(dst)), "l"(src))
#define CP16CG(dst, src) \
    asm volatile("cp.async.cg.shared.global [%0], [%1], 16;\n" :: \
        "r"((uint32_t)__cvta_generic_to_shared(dst)), "l"(src))
#define CP_COMMIT()  asm volatile("cp.async.commit_group;\n" ::)
#define CP_WAIT(n)   asm volatile("cp.async.wait_group %0;\n" :: "n"(n))

__device__ __forceinline__ void ldm_x4(uint32_t* r, const void* p) {
    uint32_t a = (uint32_t)__cvta_generic_to_shared(p);
    asm volatile("ldmatrix.sync.aligned.m8n8.x4.shared.b16 {%0,%1,%2,%3},[%4];"
        : "=r"(r[0]), "=r"(r[1]), "=r"(r[2]), "=r"(r[3]) : "r"(a));
}
__device__ __forceinline__ void ldm_x4t(uint32_t* r, const void* p) {
    uint32_t a = (uint32_t)__cvta_generic_to_shared(p);
    asm volatile("ldmatrix.sync.aligned.m8n8.x4.trans.shared.b16 {%0,%1,%2,%3},[%4];"
        : "=r"(r[0]), "=r"(r[1]), "=r"(r[2]), "=r"(r[3]) : "r"(a));
}
#define MMA16816(d, a, b0, b1) \
    asm volatile("mma.sync.aligned.m16n8k16.row.col.f32.bf16.bf16.f32 " \
        "{%0,%1,%2,%3},{%4,%5,%6,%7},{%8,%9},{%0,%1,%2,%3};" \
        : "+f"(d[0]), "+f"(d[1]), "+f"(d[2]), "+f"(d[3]) \
        : "r"(a[0]), "r"(a[1]), "r"(a[2]), "r"(a[3]), "r"(b0), "r"(b1))

__device__ __forceinline__ uint32_t packbf(float lo, float hi) {
    __nv_bfloat162 h = __floats2bfloat162_rn(lo, hi);
    return *(uint32_t*)&h;
}

// ---------------- HMMA bf16 GEMM, 128x128x32, 4-stage, XOR-swizzled --------
// R3-proven warp layout (8 warps of 32x64); deeper prefetch (distance 2).
// EPI 0: store  1: exact GELU  2: scatter+residual  3: residual
#define GBM 128
#define GBN 128
#define GBK 32
#define NSTG 4
#define STG_A (GBM * GBK)     // 4096 elems = 8KB
#define STG_B (GBK * GBN)     // 4096 elems = 8KB
#define TCSMEM (NSTG * (STG_A + STG_B) * 2)   // 65536 bytes

template <int EPI, typename OutT>
__global__ void __launch_bounds__(256) mma_gemm(
    const bf16* __restrict__ A, const bf16* __restrict__ B,
    const float* __restrict__ bias, const float* __restrict__ add,
    OutT* __restrict__ C, int M, int N, int K)
{
    extern __shared__ __align__(16) bf16 sm[];
    bf16* As = sm;                    // NSTG stages x 4096 elems
    bf16* Bs = sm + NSTG * STG_A;     // NSTG stages x 4096 elems

    int t = threadIdx.x;
    int m0 = blockIdx.y * GBM, n0 = blockIdx.x * GBN;

    int ar = t >> 2, acw = t & 3;                 // A: row, 16B chunk
    int br = t >> 3, bcw = (t & 7) * 2;           // B: k-row, chunk pair
    const bf16* Ag = A + (size_t)(m0 + ar) * K + acw * 8;
    const bf16* Bg = B + (size_t)br * N + n0 + bcw * 8;

    int aswz = (ar >> 1) & 3;                     // same for row ar and ar+64
    int a_off0 = ar * 32 + ((acw ^ aswz) << 3);
    int a_off1 = (ar + 64) * 32 + (((acw ^ ((ar >> 1) & 3))) << 3);
    int b_off0 = br * 128 + (((bcw)     ^ (br & 7)) << 3);
    int b_off1 = br * 128 + (((bcw + 1) ^ (br & 7)) << 3);

    int lane = t & 31, w = t >> 5;
    int m0w = (w >> 1) * 32, nw = (w & 1) * 64;
    int lrow = (lane & 7) + (lane & 8);
    int lcol = (lane & 16) >> 1;

    float acc[2][8][4] = {};

    int nk = K / GBK;
    // prologue: stages 0,1,2
#pragma unroll
    for (int s = 0; s < NSTG - 1; s++) {
        int k0 = s * GBK;
        CP16CG(&As[s * STG_A + a_off0], Ag + k0);
        CP16CG(&As[s * STG_A + a_off1], Ag + (size_t)64 * K + k0);
        CP16CG(&Bs[s * STG_B + b_off0], Bg + (size_t)k0 * N);
        CP16CG(&Bs[s * STG_B + b_off1], Bg + (size_t)k0 * N + 8);
        CP_COMMIT();
    }

    for (int i = 0; i < nk; i++) {
        if (i + 2 < nk)      { CP_WAIT(2); }
        else if (i + 1 < nk) { CP_WAIT(1); }
        else                 { CP_WAIT(0); }
        __syncthreads();
        if (i + NSTG - 1 < nk) {
            int st = (i + NSTG - 1) % NSTG;
            int k0 = (i + NSTG - 1) * GBK;
            CP16CG(&As[st * STG_A + a_off0], Ag + k0);
            CP16CG(&As[st * STG_A + a_off1], Ag + (size_t)64 * K + k0);
            CP16CG(&Bs[st * STG_B + b_off0], Bg + (size_t)k0 * N);
            CP16CG(&Bs[st * STG_B + b_off1], Bg + (size_t)k0 * N + 8);
            CP_COMMIT();
        }
        int cs = i % NSTG;
        const bf16* Asc = As + cs * STG_A;
        const bf16* Bsc = Bs + cs * STG_B;
#pragma unroll
        for (int kk = 0; kk < GBK; kk += 16) {
            uint32_t a[2][4], b[4][4];
#pragma unroll
            for (int mi = 0; mi < 2; mi++) {
                int R = m0w + mi * 16 + lrow;
                int cr = (kk + lcol) >> 3;
                ldm_x4(a[mi], Asc + R * 32 + ((cr ^ ((R >> 1) & 3)) << 3));
            }
#pragma unroll
            for (int nj = 0; nj < 4; nj++) {
                int Kr = kk + lrow;
                int cn = (nw + nj * 16 + lcol) >> 3;
                ldm_x4t(b[nj], Bsc + Kr * 128 + ((cn ^ (Kr & 7)) << 3));
            }
#pragma unroll
            for (int mi = 0; mi < 2; mi++) {
#pragma unroll
                for (int nt = 0; nt < 8; nt++)
                    MMA16816(acc[mi][nt], a[mi],
                             b[nt >> 1][(nt & 1) * 2], b[nt >> 1][(nt & 1) * 2 + 1]);
            }
        }
    }

    // epilogue
#pragma unroll
    for (int mi = 0; mi < 2; mi++) {
        int rbase = m0 + m0w + mi * 16 + (lane >> 2);
#pragma unroll
        for (int h2 = 0; h2 < 2; h2++) {
            int row = rbase + 8 * h2;
            int orow = (EPI == 2) ? win_row_to_token(row) : row;
#pragma unroll
            for (int nt = 0; nt < 8; nt++) {
                int col = n0 + nw + nt * 8 + (lane & 3) * 2;
                float v0 = acc[mi][nt][2 * h2 + 0] + bias[col];
                float v1 = acc[mi][nt][2 * h2 + 1] + bias[col + 1];
                if (EPI == 1) {
                    v0 = 0.5f * v0 * (1.0f + erff(v0 * 0.7071067811865475f));
                    v1 = 0.5f * v1 * (1.0f + erff(v1 * 0.7071067811865475f));
                } else if (EPI == 2 || EPI == 3) {
                    const float* ap = add + (size_t)orow * N + col;
                    v0 += ap[0];
                    v1 += ap[1];
                }
                OutT* cp = C + (size_t)orow * N + col;
                if (sizeof(OutT) == 2) {
                    __nv_bfloat162 pk;
                    pk.x = __float2bfloat16(v0);
                    pk.y = __float2bfloat16(v1);
                    *(__nv_bfloat162*)cp = pk;
                } else {
                    float2 pk = make_float2(v0, v1);
                    *(float2*)cp = pk;
                }
            }
        }
    }
}

// ---------------- tensor-core window attention (R3, proven) ----------------
__global__ void __launch_bounds__(256) attn_mma_kernel(
    const bf16* __restrict__ QKV, const bf16* __restrict__ bias_all,
    bf16* __restrict__ O)
{
    __shared__ __align__(16) bf16 sQ[2][64][40];
    __shared__ __align__(16) bf16 sK[2][64][40];
    __shared__ __align__(16) bf16 sV[2][64][40];
    __shared__ __align__(16) bf16 sB[2][64][72];

    int win = blockIdx.x, t = threadIdx.x;
    int widx = win & 63;
    int type = (((widx >> 3) == 7) ? 2 : 0) + (((widx & 7) == 7) ? 1 : 0);

    for (int i = t; i < 2 * 15 * 40; i += 256) {
        int hs = i / 600, rem = i % 600;
        int row = 49 + rem / 40, col = rem % 40;
        sK[hs][row][col] = __float2bfloat16(0.f);
        sV[hs][row][col] = __float2bfloat16(0.f);
    }

    int lane = t & 31, w = t >> 5;
    int hs = w >> 2, ww = w & 3;
    int r0 = ww * 16;
    int lrow = (lane & 7) + (lane & 8);
    int lcol = (lane & 16) >> 1;
    int qr = lane >> 2, qc = lane & 3;
    const float scale = 0.17677669529663687f;

    int lr = t >> 2, lc = t & 3;

    for (int p = 0; p < 6; p++) {
        __syncthreads();
        if (lr < 49) {
            const bf16* src = QKV + (size_t)(win * NTOK + lr) * QKVN + lc * 8;
#pragma unroll
            for (int hh = 0; hh < 2; hh++) {
                int h = p * 2 + hh;
                CP16(&sQ[hh][lr][lc * 8], src + h * HDIM);
                CP16(&sK[hh][lr][lc * 8], src + h * HDIM + CDIM);
                CP16(&sV[hh][lr][lc * 8], src + h * HDIM + 2 * CDIM);
            }
        }
#pragma unroll
        for (int hh = 0; hh < 2; hh++) {
            int h = p * 2 + hh;
            const bf16* bsrc = bias_all + (((size_t)type * NHEADS + h) * 64 + lr) * 64;
            CP16(&sB[hh][lr][lc * 8], bsrc + lc * 8);
            CP16(&sB[hh][lr][(lc + 4) * 8], bsrc + (lc + 4) * 8);
        }
        CP_COMMIT(); CP_WAIT(0);
        __syncthreads();

        float acc[8][4] = {};
#pragma unroll
        for (int kc = 0; kc < 32; kc += 16) {
            uint32_t a[4];
            ldm_x4(a, &sQ[hs][r0 + lrow][kc + lcol]);
            uint32_t bb[4][4];
#pragma unroll
            for (int nj = 0; nj < 4; nj++)
                ldm_x4(bb[nj], &sK[hs][nj * 16 + lrow][kc + lcol]);
#pragma unroll
            for (int nj = 0; nj < 4; nj++) {
                MMA16816(acc[nj * 2 + 0], a, bb[nj][0], bb[nj][2]);
                MMA16816(acc[nj * 2 + 1], a, bb[nj][1], bb[nj][3]);
            }
        }
#pragma unroll
        for (int cj = 0; cj < 4; cj++) {
            uint32_t bf[4];
            ldm_x4(bf, &sB[hs][r0 + lrow][cj * 16 + lcol]);
            float2 f0 = __bfloat1622float2(*(__nv_bfloat162*)&bf[0]);
            float2 f1 = __bfloat1622float2(*(__nv_bfloat162*)&bf[1]);
            float2 f2 = __bfloat1622float2(*(__nv_bfloat162*)&bf[2]);
            float2 f3 = __bfloat1622float2(*(__nv_bfloat162*)&bf[3]);
            acc[2 * cj][0] = acc[2 * cj][0] * scale + f0.x;
            acc[2 * cj][1] = acc[2 * cj][1] * scale + f0.y;
            acc[2 * cj][2] = acc[2 * cj][2] * scale + f1.x;
            acc[2 * cj][3] = acc[2 * cj][3] * scale + f1.y;
            acc[2 * cj + 1][0] = acc[2 * cj + 1][0] * scale + f2.x;
            acc[2 * cj + 1][1] = acc[2 * cj + 1][1] * scale + f2.y;
            acc[2 * cj + 1][2] = acc[2 * cj + 1][2] * scale + f3.x;
            acc[2 * cj + 1][3] = acc[2 * cj + 1][3] * scale + f3.y;
        }
        float mx1 = -1e30f, mx2 = -1e30f;
#pragma unroll
        for (int nt = 0; nt < 8; nt++) {
            mx1 = fmaxf(mx1, fmaxf(acc[nt][0], acc[nt][1]));
            mx2 = fmaxf(mx2, fmaxf(acc[nt][2], acc[nt][3]));
        }
        mx1 = fmaxf(mx1, __shfl_xor_sync(0xffffffffu, mx1, 1));
        mx1 = fmaxf(mx1, __shfl_xor_sync(0xffffffffu, mx1, 2));
        mx2 = fmaxf(mx2, __shfl_xor_sync(0xffffffffu, mx2, 1));
        mx2 = fmaxf(mx2, __shfl_xor_sync(0xffffffffu, mx2, 2));
        float sum1 = 0.f, sum2 = 0.f;
#pragma unroll
        for (int nt = 0; nt < 8; nt++) {
            acc[nt][0] = __expf(acc[nt][0] - mx1);
            acc[nt][1] = __expf(acc[nt][1] - mx1);
            acc[nt][2] = __expf(acc[nt][2] - mx2);
            acc[nt][3] = __expf(acc[nt][3] - mx2);
            sum1 += acc[nt][0] + acc[nt][1];
            sum2 += acc[nt][2] + acc[nt][3];
        }
        sum1 += __shfl_xor_sync(0xffffffffu, sum1, 1);
        sum1 += __shfl_xor_sync(0xffffffffu, sum1, 2);
        sum2 += __shfl_xor_sync(0xffffffffu, sum2, 1);
        sum2 += __shfl_xor_sync(0xffffffffu, sum2, 2);
        float inv1 = 1.0f / sum1, inv2 = 1.0f / sum2;

        float o[4][4] = {};
#pragma unroll
        for (int kc2 = 0; kc2 < 4; kc2++) {
            uint32_t pa[4];
            pa[0] = packbf(acc[2 * kc2][0],     acc[2 * kc2][1]);
            pa[1] = packbf(acc[2 * kc2][2],     acc[2 * kc2][3]);
            pa[2] = packbf(acc[2 * kc2 + 1][0], acc[2 * kc2 + 1][1]);
            pa[3] = packbf(acc[2 * kc2 + 1][2], acc[2 * kc2 + 1][3]);
#pragma unroll
            for (int nj = 0; nj < 2; nj++) {
                uint32_t vb[4];
                ldm_x4t(vb, &sV[hs][kc2 * 16 + lrow][nj * 16 + lcol]);
                MMA16816(o[nj * 2 + 0], pa, vb[0], vb[1]);
                MMA16816(o[nj * 2 + 1], pa, vb[2], vb[3]);
            }
        }
        int H = p * 2 + hs;
        int row1 = r0 + qr, row2 = r0 + qr + 8;
        if (row1 < NTOK) {
            bf16* dst = O + (size_t)(win * NTOK + row1) * CDIM + H * HDIM + qc * 2;
#pragma unroll
            for (int nt = 0; nt < 4; nt++) {
                __nv_bfloat162 pk;
                pk.x = __float2bfloat16(o[nt][0] * inv1);
                pk.y = __float2bfloat16(o[nt][1] * inv1);
                *(__nv_bfloat162*)(dst + nt * 8) = pk;
            }
        }
        if (row2 < NTOK) {
            bf16* dst = O + (size_t)(win * NTOK + row2) * CDIM + H * HDIM + qc * 2;
#pragma unroll
            for (int nt = 0; nt < 4; nt++) {
                __nv_bfloat162 pk;
                pk.x = __float2bfloat16(o[nt][2] * inv2);
                pk.y = __float2bfloat16(o[nt][3] * inv2);
                *(__nv_bfloat162*)(dst + nt * 8) = pk;
            }
        }
    }
}

// ---------------- launch ----------------
extern "C" void kernel_launch(void* const* d_in, const int* in_sizes, int n_in,
                              void* d_out, int out_size)
{
    const float* hidden  = (const float*)d_in[0];
    const float* ln1_g   = (const float*)d_in[1];
    const float* ln1_b   = (const float*)d_in[2];
    const float* q_w     = (const float*)d_in[3];
    const float* q_b     = (const float*)d_in[4];
    const float* k_w     = (const float*)d_in[5];
    const float* k_b     = (const float*)d_in[6];
    const float* v_w     = (const float*)d_in[7];
    const float* v_b     = (const float*)d_in[8];
    const float* rpb     = (const float*)d_in[9];
    const int*   rpi     = (const int*)  d_in[10];
    const float* proj_w  = (const float*)d_in[11];
    const float* proj_b  = (const float*)d_in[12];
    const float* ln2_g   = (const float*)d_in[13];
    const float* ln2_b   = (const float*)d_in[14];
    const float* fc1_w   = (const float*)d_in[15];
    const float* fc1_b   = (const float*)d_in[16];
    const float* fc2_w   = (const float*)d_in[17];
    const float* fc2_b   = (const float*)d_in[18];
    float* out = (float*)d_out;

    bf16 *p_xw, *p_qkv, *p_ctx, *p_ln2, *p_y1;
    bf16 *p_wqkv, *p_wp, *p_w1, *p_w2, *p_bias;
    float *p_h, *p_bqkv;
    cudaGetSymbolAddress((void**)&p_xw,   g_xw);
    cudaGetSymbolAddress((void**)&p_qkv,  g_qkv);
    cudaGetSymbolAddress((void**)&p_ctx,  g_ctx);
    cudaGetSymbolAddress((void**)&p_h,    g_h);
    cudaGetSymbolAddress((void**)&p_ln2,  g_ln2);
    cudaGetSymbolAddress((void**)&p_y1,   g_y1);
    cudaGetSymbolAddress((void**)&p_wqkv, g_wqkv);
    cudaGetSymbolAddress((void**)&p_bqkv, g_bqkv);
    cudaGetSymbolAddress((void**)&p_wp,   g_wp);
    cudaGetSymbolAddress((void**)&p_w1,   g_w1);
    cudaGetSymbolAddress((void**)&p_w2,   g_w2);
    cudaGetSymbolAddress((void**)&p_bias, g_bias);

    cudaFuncSetAttribute(mma_gemm<0, bf16>,  cudaFuncAttributeMaxDynamicSharedMemorySize, TCSMEM);
    cudaFuncSetAttribute(mma_gemm<1, bf16>,  cudaFuncAttributeMaxDynamicSharedMemorySize, TCSMEM);
    cudaFuncSetAttribute(mma_gemm<2, float>, cudaFuncAttributeMaxDynamicSharedMemorySize, TCSMEM);
    cudaFuncSetAttribute(mma_gemm<3, float>, cudaFuncAttributeMaxDynamicSharedMemorySize, TCSMEM);

    // weight packing / conversion + bias tiles
    const int WSMALL = CDIM * CDIM / 4, WBIG = CDIM * FFNDIM / 4;
    pack_qkv_kernel<<<(QKV_W4 + QKVN / 4 + 255) / 256, 256>>>(
        q_w, k_w, v_w, q_b, k_b, v_b, p_wqkv, p_bqkv);
    f2bf_kernel<<<(WSMALL + 255) / 256, 256>>>(proj_w, p_wp, WSMALL);
    f2bf_kernel<<<(WBIG   + 255) / 256, 256>>>(fc1_w,  p_w1, WBIG);
    f2bf_kernel<<<(WBIG   + 255) / 256, 256>>>(fc2_w,  p_w2, WBIG);
    bias_kernel<<<dim3(4, NHEADS), 256>>>(rpb, rpi, p_bias);

    // 1) LN1 + shift-roll + window partition (gather)
    ln_kernel<<<MTOK, 128>>>(hidden, ln1_g, ln1_b, p_xw, 1);

    // 2) fused QKV projection
    mma_gemm<0, bf16><<<dim3(QKVN / GBN, MTOK / GBM), 256, TCSMEM>>>(
        p_xw, p_wqkv, p_bqkv, nullptr, p_qkv, MTOK, QKVN, CDIM);

    // 3) windowed attention (tensor cores)
    attn_mma_kernel<<<TOTWIN, 256>>>(p_qkv, p_bias, p_ctx);

    // 4) output projection + window-reverse + roll-back + residual (scatter)
    mma_gemm<2, float><<<dim3(CDIM / GBN, MTOK / GBM), 256, TCSMEM>>>(
        p_ctx, p_wp, proj_b, hidden, p_h, MTOK, CDIM, CDIM);

    // 5) LN2
    ln_kernel<<<MTOK, 128>>>(p_h, ln2_g, ln2_b, p_ln2, 0);

    // 6) fc1 + exact GELU
    mma_gemm<1, bf16><<<dim3(FFNDIM / GBN, MTOK / GBM), 256, TCSMEM>>>(
        p_ln2, p_w1, fc1_b, nullptr, p_y1, MTOK, FFNDIM, CDIM);

    // 7) fc2 + residual -> final output
    mma_gemm<3, float><<<dim3(CDIM / GBN, MTOK / GBM), 256, TCSMEM>>>(
        p_y1, p_w2, fc2_b, p_h, out, MTOK, CDIM, FFNDIM);
}

// round 9
// speedup vs baseline: 1.4926x; 1.0051x over previous
#include <cuda_runtime.h>
#include <cuda_bf16.h>
#include <math.h>
#include <stdint.h>

// ---------------- problem constants ----------------
#define BATCH   8
#define HIMG    56
#define WIMG    56
#define CDIM    384
#define NHEADS  12
#define HDIM    32
#define WIN     7
#define NTOK    49
#define SHIFT_S 3
#define TOTWIN  512
#define MTOK    25088
#define FFNDIM  1536
#define QKVN    1152          // 3*CDIM

typedef __nv_bfloat16 bf16;

// ---------------- scratch (device globals; allocation-free) ----------------
__device__ bf16  g_xw  [MTOK * CDIM];
__device__ bf16  g_qkv [MTOK * QKVN];
__device__ bf16  g_ctx [MTOK * CDIM];
__device__ float g_h   [MTOK * CDIM];
__device__ bf16  g_ln2 [MTOK * CDIM];
__device__ bf16  g_y1  [MTOK * FFNDIM];
__device__ bf16  g_wqkv[CDIM * QKVN];   // [K][N] packed q|k|v
__device__ float g_bqkv[QKVN];
__device__ bf16  g_wp  [CDIM * CDIM];
__device__ bf16  g_w1  [CDIM * FFNDIM];
__device__ bf16  g_w2  [FFNDIM * CDIM];
__device__ bf16  g_bias[4 * NHEADS * 64 * 64];

// windowed row r <-> original token t (same map both directions)
__device__ __forceinline__ int win_row_to_token(int r) {
    int b    = r / (HIMG * WIMG);
    int rem  = r - b * (HIMG * WIMG);
    int widx = rem / NTOK;
    int tok  = rem - widx * NTOK;
    int wi = widx >> 3, wj = widx & 7;
    int i = tok / WIN, j = tok - i * WIN;
    int sh = wi * WIN + i + SHIFT_S; if (sh >= HIMG) sh -= HIMG;
    int sw = wj * WIN + j + SHIFT_S; if (sw >= WIMG) sw -= WIMG;
    return b * (HIMG * WIMG) + sh * WIMG + sw;
}

// ---------------- fused fp32 -> bf16 convert (proj | fc1 | fc2) ------------
#define W_PROJ4 (CDIM * CDIM / 4)
#define W_FFN4  (CDIM * FFNDIM / 4)
__global__ void __launch_bounds__(256) f2bf3_kernel(
    const float* __restrict__ s0, bf16* __restrict__ d0,
    const float* __restrict__ s1, bf16* __restrict__ d1,
    const float* __restrict__ s2, bf16* __restrict__ d2)
{
    int i = blockIdx.x * blockDim.x + threadIdx.x;
    const float* src; bf16* dst; int idx;
    if (i < W_PROJ4)                 { src = s0; dst = d0; idx = i; }
    else if (i < W_PROJ4 + W_FFN4)   { src = s1; dst = d1; idx = i - W_PROJ4; }
    else if (i < W_PROJ4 + 2*W_FFN4) { src = s2; dst = d2; idx = i - W_PROJ4 - W_FFN4; }
    else return;
    float4 v = ((const float4*)src)[idx];
    bf16 o[4] = {__float2bfloat16(v.x), __float2bfloat16(v.y),
                 __float2bfloat16(v.z), __float2bfloat16(v.w)};
    *(uint64_t*)(dst + (size_t)idx * 4) = *(uint64_t*)o;
}

// ---------------- pack q|k|v weights + biases ----------------
#define QKV_W4 (CDIM * QKVN / 4)
__global__ void __launch_bounds__(256) pack_qkv_kernel(
    const float* __restrict__ qw, const float* __restrict__ kw,
    const float* __restrict__ vw, const float* __restrict__ qb,
    const float* __restrict__ kb, const float* __restrict__ vb,
    bf16* __restrict__ wout, float* __restrict__ bout)
{
    int i = blockIdx.x * blockDim.x + threadIdx.x;
    if (i < QKV_W4) {
        int row = i / (QKVN / 4);
        int col = (i % (QKVN / 4)) * 4;
        const float* src = (col < CDIM) ? qw : (col < 2 * CDIM ? kw : vw);
        int c = col - (col < CDIM ? 0 : (col < 2 * CDIM ? CDIM : 2 * CDIM));
        float4 v = *(const float4*)(src + (size_t)row * CDIM + c);
        bf16 o[4] = {__float2bfloat16(v.x), __float2bfloat16(v.y),
                     __float2bfloat16(v.z), __float2bfloat16(v.w)};
        *(uint64_t*)(wout + (size_t)i * 4) = *(uint64_t*)o;
    } else if (i < QKV_W4 + QKVN / 4) {
        int col = (i - QKV_W4) * 4;
        const float* src = (col < CDIM) ? qb : (col < 2 * CDIM ? kb : vb);
        int c = col - (col < CDIM ? 0 : (col < 2 * CDIM ? CDIM : 2 * CDIM));
        *(float4*)(bout + col) = *(const float4*)(src + c);
    }
}

// ---------------- precompute attention bias+mask tiles ----------------
__global__ void __launch_bounds__(256) bias_kernel(
    const float* __restrict__ rpb, const int* __restrict__ rpi,
    bf16* __restrict__ out)
{
    int type = blockIdx.x, h = blockIdx.y;
    for (int idx = threadIdx.x; idx < 64 * 64; idx += 256) {
        int n = idx >> 6, m = idx & 63;
        float v;
        if (m >= 49)      v = -1e30f;
        else if (n >= 49) v = 0.f;
        else {
            v = rpb[rpi[n * 49 + m] * NHEADS + h];
            int ni = n / 7, nj = n % 7, mi = m / 7, mj = m % 7;
            int cn = ((type & 2) ? (ni < 4 ? 1 : 2) : 0) * 3 + ((type & 1) ? (nj < 4 ? 1 : 2) : 0);
            int cm = ((type & 2) ? (mi < 4 ? 1 : 2) : 0) * 3 + ((type & 1) ? (mj < 4 ? 1 : 2) : 0);
            if (cn != cm) v -= 100.0f;
        }
        out[(((size_t)type * NHEADS + h) * 64 + n) * 64 + m] = __float2bfloat16(v);
    }
}

// ---------------- LayerNorm (fp32 in, bf16 out) ----------------
__global__ void __launch_bounds__(128) ln_kernel(
    const float* __restrict__ x, const float* __restrict__ g,
    const float* __restrict__ b, bf16* __restrict__ out, int permute)
{
    int r = blockIdx.x;
    int t = permute ? win_row_to_token(r) : r;
    const float* xi = x + (size_t)t * CDIM;
    bf16*        yo = out + (size_t)r * CDIM;
    int tid = threadIdx.x;

    float v[3];
    float s = 0.f, ss = 0.f;
#pragma unroll
    for (int i = 0; i < 3; i++) {
        v[i] = xi[tid + i * 128];
        s += v[i]; ss += v[i] * v[i];
    }
#pragma unroll
    for (int o = 16; o; o >>= 1) {
        s  += __shfl_xor_sync(0xffffffffu, s,  o);
        ss += __shfl_xor_sync(0xffffffffu, ss, o);
    }
    __shared__ float red[8];
    __shared__ float stat[2];
    int wid = tid >> 5, lane = tid & 31;
    if (lane == 0) { red[wid] = s; red[4 + wid] = ss; }
    __syncthreads();
    if (tid == 0) {
        float S  = red[0] + red[1] + red[2] + red[3];
        float SS = red[4] + red[5] + red[6] + red[7];
        float mu = S * (1.0f / CDIM);
        float var = SS * (1.0f / CDIM) - mu * mu;
        stat[0] = mu;
        stat[1] = rsqrtf(var + 1e-5f);
    }
    __syncthreads();
    float mu = stat[0], rstd = stat[1];
#pragma unroll
    for (int i = 0; i < 3; i++) {
        int c = tid + i * 128;
        yo[c] = __float2bfloat16((v[i] - mu) * rstd * g[c] + b[c]);
    }
}

// ---------------- mma helpers ----------------
#define CP16(dst, src) \
    asm volatile("cp.async.ca.shared.global [%0], [%1], 16;\n" :: \
        "r"((uint32_t)__cvta_generic_to_shared(dst)), "l"(src))
#define CP16CG(dst, src) \
    asm volatile("cp.async.cg.shared.global [%0], [%1], 16;\n" :: \
        "r"((uint32_t)__cvta_generic_to_shared(dst)), "l"(src))
#define CP_COMMIT()  asm volatile("cp.async.commit_group;\n" ::)
#define CP_WAIT(n)   asm volatile("cp.async.wait_group %0;\n" :: "n"(n))

__device__ __forceinline__ void ldm_x4(uint32_t* r, const void* p) {
    uint32_t a = (uint32_t)__cvta_generic_to_shared(p);
    asm volatile("ldmatrix.sync.aligned.m8n8.x4.shared.b16 {%0,%1,%2,%3},[%4];"
        : "=r"(r[0]), "=r"(r[1]), "=r"(r[2]), "=r"(r[3]) : "r"(a));
}
__device__ __forceinline__ void ldm_x4t(uint32_t* r, const void* p) {
    uint32_t a = (uint32_t)__cvta_generic_to_shared(p);
    asm volatile("ldmatrix.sync.aligned.m8n8.x4.trans.shared.b16 {%0,%1,%2,%3},[%4];"
        : "=r"(r[0]), "=r"(r[1]), "=r"(r[2]), "=r"(r[3]) : "r"(a));
}
#define MMA16816(d, a, b0, b1) \
    asm volatile("mma.sync.aligned.m16n8k16.row.col.f32.bf16.bf16.f32 " \
        "{%0,%1,%2,%3},{%4,%5,%6,%7},{%8,%9},{%0,%1,%2,%3};" \
        : "+f"(d[0]), "+f"(d[1]), "+f"(d[2]), "+f"(d[3]) \
        : "r"(a[0]), "r"(a[1]), "r"(a[2]), "r"(a[3]), "r"(b0), "r"(b1))

__device__ __forceinline__ uint32_t packbf(float lo, float hi) {
    __nv_bfloat162 h = __floats2bfloat162_rn(lo, hi);
    return *(uint32_t*)&h;
}

// ---------------- HMMA bf16 GEMM, 128x128x32, 5-stage, XOR-swizzled --------
// R3-proven warp layout (8 warps of 32x64); prefetch distance 3.
// EPI 0: store  1: exact GELU  2: scatter+residual  3: residual
#define GBM 128
#define GBN 128
#define GBK 32
#define NSTG 5
#define STG_A (GBM * GBK)     // 4096 elems = 8KB
#define STG_B (GBK * GBN)     // 4096 elems = 8KB
#define TCSMEM (NSTG * (STG_A + STG_B) * 2)   // 81920 bytes

template <int EPI, typename OutT>
__global__ void __launch_bounds__(256) mma_gemm(
    const bf16* __restrict__ A, const bf16* __restrict__ B,
    const float* __restrict__ bias, const float* __restrict__ add,
    OutT* __restrict__ C, int M, int N, int K)
{
    extern __shared__ __align__(16) bf16 sm[];
    bf16* As = sm;                    // NSTG stages x 4096 elems
    bf16* Bs = sm + NSTG * STG_A;     // NSTG stages x 4096 elems

    int t = threadIdx.x;
    int m0 = blockIdx.y * GBM, n0 = blockIdx.x * GBN;

    int ar = t >> 2, acw = t & 3;                 // A: row, 16B chunk
    int br = t >> 3, bcw = (t & 7) * 2;           // B: k-row, chunk pair
    const bf16* Ag = A + (size_t)(m0 + ar) * K + acw * 8;
    const bf16* Bg = B + (size_t)br * N + n0 + bcw * 8;

    int aswz = (ar >> 1) & 3;                     // same for row ar and ar+64
    int a_off0 = ar * 32 + ((acw ^ aswz) << 3);
    int a_off1 = (ar + 64) * 32 + ((acw ^ aswz) << 3);
    int b_off0 = br * 128 + (((bcw)     ^ (br & 7)) << 3);
    int b_off1 = br * 128 + (((bcw + 1) ^ (br & 7)) << 3);

    int lane = t & 31, w = t >> 5;
    int m0w = (w >> 1) * 32, nw = (w & 1) * 64;
    int lrow = (lane & 7) + (lane & 8);
    int lcol = (lane & 16) >> 1;

    float acc[2][8][4] = {};

    int nk = K / GBK;
    // prologue: stages 0..NSTG-2
#pragma unroll
    for (int s = 0; s < NSTG - 1; s++) {
        int k0 = s * GBK;
        CP16CG(&As[s * STG_A + a_off0], Ag + k0);
        CP16CG(&As[s * STG_A + a_off1], Ag + (size_t)64 * K + k0);
        CP16CG(&Bs[s * STG_B + b_off0], Bg + (size_t)k0 * N);
        CP16CG(&Bs[s * STG_B + b_off1], Bg + (size_t)k0 * N + 8);
        CP_COMMIT();
    }

    for (int i = 0; i < nk; i++) {
        if (i + 3 < nk)      { CP_WAIT(3); }
        else if (i + 2 < nk) { CP_WAIT(2); }
        else if (i + 1 < nk) { CP_WAIT(1); }
        else                 { CP_WAIT(0); }
        __syncthreads();
        if (i + NSTG - 1 < nk) {
            int st = (i + NSTG - 1) % NSTG;
            int k0 = (i + NSTG - 1) * GBK;
            CP16CG(&As[st * STG_A + a_off0], Ag + k0);
            CP16CG(&As[st * STG_A + a_off1], Ag + (size_t)64 * K + k0);
            CP16CG(&Bs[st * STG_B + b_off0], Bg + (size_t)k0 * N);
            CP16CG(&Bs[st * STG_B + b_off1], Bg + (size_t)k0 * N + 8);
            CP_COMMIT();
        }
        int cs = i % NSTG;
        const bf16* Asc = As + cs * STG_A;
        const bf16* Bsc = Bs + cs * STG_B;
#pragma unroll
        for (int kk = 0; kk < GBK; kk += 16) {
            uint32_t a[2][4], b[4][4];
#pragma unroll
            for (int mi = 0; mi < 2; mi++) {
                int R = m0w + mi * 16 + lrow;
                int cr = (kk + lcol) >> 3;
                ldm_x4(a[mi], Asc + R * 32 + ((cr ^ ((R >> 1) & 3)) << 3));
            }
#pragma unroll
            for (int nj = 0; nj < 4; nj++) {
                int Kr = kk + lrow;
                int cn = (nw + nj * 16 + lcol) >> 3;
                ldm_x4t(b[nj], Bsc + Kr * 128 + ((cn ^ (Kr & 7)) << 3));
            }
#pragma unroll
            for (int mi = 0; mi < 2; mi++) {
#pragma unroll
                for (int nt = 0; nt < 8; nt++)
                    MMA16816(acc[mi][nt], a[mi],
                             b[nt >> 1][(nt & 1) * 2], b[nt >> 1][(nt & 1) * 2 + 1]);
            }
        }
    }

    // epilogue
#pragma unroll
    for (int mi = 0; mi < 2; mi++) {
        int rbase = m0 + m0w + mi * 16 + (lane >> 2);
#pragma unroll
        for (int h2 = 0; h2 < 2; h2++) {
            int row = rbase + 8 * h2;
            int orow = (EPI == 2) ? win_row_to_token(row) : row;
#pragma unroll
            for (int nt = 0; nt < 8; nt++) {
                int col = n0 + nw + nt * 8 + (lane & 3) * 2;
                float v0 = acc[mi][nt][2 * h2 + 0] + bias[col];
                float v1 = acc[mi][nt][2 * h2 + 1] + bias[col + 1];
                if (EPI == 1) {
                    v0 = 0.5f * v0 * (1.0f + erff(v0 * 0.7071067811865475f));
                    v1 = 0.5f * v1 * (1.0f + erff(v1 * 0.7071067811865475f));
                } else if (EPI == 2 || EPI == 3) {
                    const float* ap = add + (size_t)orow * N + col;
                    v0 += ap[0];
                    v1 += ap[1];
                }
                OutT* cp = C + (size_t)orow * N + col;
                if (sizeof(OutT) == 2) {
                    __nv_bfloat162 pk;
                    pk.x = __float2bfloat16(v0);
                    pk.y = __float2bfloat16(v1);
                    *(__nv_bfloat162*)cp = pk;
                } else {
                    float2 pk = make_float2(v0, v1);
                    *(float2*)cp = pk;
                }
            }
        }
    }
}

// ---------------- tensor-core window attention ----------------
__global__ void __launch_bounds__(256) attn_mma_kernel(
    const bf16* __restrict__ QKV, const bf16* __restrict__ bias_all,
    bf16* __restrict__ O)
{
    __shared__ __align__(16) bf16 sQ[2][64][40];
    __shared__ __align__(16) bf16 sK[2][64][40];
    __shared__ __align__(16) bf16 sV[2][64][40];
    __shared__ __align__(16) bf16 sB[2][64][72];

    int win = blockIdx.x, t = threadIdx.x;
    int widx = win & 63;
    int type = (((widx >> 3) == 7) ? 2 : 0) + (((widx & 7) == 7) ? 1 : 0);

    for (int i = t; i < 2 * 15 * 40; i += 256) {
        int hs = i / 600, rem = i % 600;
        int row = 49 + rem / 40, col = rem % 40;
        sK[hs][row][col] = __float2bfloat16(0.f);
        sV[hs][row][col] = __float2bfloat16(0.f);
    }

    int lane = t & 31, w = t >> 5;
    int hs = w >> 2, ww = w & 3;
    int r0 = ww * 16;
    int lrow = (lane & 7) + (lane & 8);
    int lcol = (lane & 16) >> 1;
    int qr = lane >> 2, qc = lane & 3;
    const float scale = 0.17677669529663687f;

    int lr = t >> 2, lc = t & 3;

    for (int p = 0; p < 6; p++) {
        __syncthreads();
        if (lr < 49) {
            const bf16* src = QKV + (size_t)(win * NTOK + lr) * QKVN + lc * 8;
#pragma unroll
            for (int hh = 0; hh < 2; hh++) {
                int h = p * 2 + hh;
                CP16CG(&sQ[hh][lr][lc * 8], src + h * HDIM);
                CP16CG(&sK[hh][lr][lc * 8], src + h * HDIM + CDIM);
                CP16CG(&sV[hh][lr][lc * 8], src + h * HDIM + 2 * CDIM);
            }
        }
#pragma unroll
        for (int hh = 0; hh < 2; hh++) {
            int h = p * 2 + hh;
            const bf16* bsrc = bias_all + (((size_t)type * NHEADS + h) * 64 + lr) * 64;
            CP16(&sB[hh][lr][lc * 8], bsrc + lc * 8);
            CP16(&sB[hh][lr][(lc + 4) * 8], bsrc + (lc + 4) * 8);
        }
        CP_COMMIT(); CP_WAIT(0);
        __syncthreads();

        float acc[8][4] = {};
#pragma unroll
        for (int kc = 0; kc < 32; kc += 16) {
            uint32_t a[4];
            ldm_x4(a, &sQ[hs][r0 + lrow][kc + lcol]);
            uint32_t bb[4][4];
#pragma unroll
            for (int nj = 0; nj < 4; nj++)
                ldm_x4(bb[nj], &sK[hs][nj * 16 + lrow][kc + lcol]);
#pragma unroll
            for (int nj = 0; nj < 4; nj++) {
                MMA16816(acc[nj * 2 + 0], a, bb[nj][0], bb[nj][2]);
                MMA16816(acc[nj * 2 + 1], a, bb[nj][1], bb[nj][3]);
            }
        }
#pragma unroll
        for (int cj = 0; cj < 4; cj++) {
            uint32_t bf[4];
            ldm_x4(bf, &sB[hs][r0 + lrow][cj * 16 + lcol]);
            float2 f0 = __bfloat1622float2(*(__nv_bfloat162*)&bf[0]);
            float2 f1 = __bfloat1622float2(*(__nv_bfloat162*)&bf[1]);
            float2 f2 = __bfloat1622float2(*(__nv_bfloat162*)&bf[2]);
            float2 f3 = __bfloat1622float2(*(__nv_bfloat162*)&bf[3]);
            acc[2 * cj][0] = acc[2 * cj][0] * scale + f0.x;
            acc[2 * cj][1] = acc[2 * cj][1] * scale + f0.y;
            acc[2 * cj][2] = acc[2 * cj][2] * scale + f1.x;
            acc[2 * cj][3] = acc[2 * cj][3] * scale + f1.y;
            acc[2 * cj + 1][0] = acc[2 * cj + 1][0] * scale + f2.x;
            acc[2 * cj + 1][1] = acc[2 * cj + 1][1] * scale + f2.y;
            acc[2 * cj + 1][2] = acc[2 * cj + 1][2] * scale + f3.x;
            acc[2 * cj + 1][3] = acc[2 * cj + 1][3] * scale + f3.y;
        }
        float mx1 = -1e30f, mx2 = -1e30f;
#pragma unroll
        for (int nt = 0; nt < 8; nt++) {
            mx1 = fmaxf(mx1, fmaxf(acc[nt][0], acc[nt][1]));
            mx2 = fmaxf(mx2, fmaxf(acc[nt][2], acc[nt][3]));
        }
        mx1 = fmaxf(mx1, __shfl_xor_sync(0xffffffffu, mx1, 1));
        mx1 = fmaxf(mx1, __shfl_xor_sync(0xffffffffu, mx1, 2));
        mx2 = fmaxf(mx2, __shfl_xor_sync(0xffffffffu, mx2, 1));
        mx2 = fmaxf(mx2, __shfl_xor_sync(0xffffffffu, mx2, 2));
        float sum1 = 0.f, sum2 = 0.f;
#pragma unroll
        for (int nt = 0; nt < 8; nt++) {
            acc[nt][0] = __expf(acc[nt][0] - mx1);
            acc[nt][1] = __expf(acc[nt][1] - mx1);
            acc[nt][2] = __expf(acc[nt][2] - mx2);
            acc[nt][3] = __expf(acc[nt][3] - mx2);
            sum1 += acc[nt][0] + acc[nt][1];
            sum2 += acc[nt][2] + acc[nt][3];
        }
        sum1 += __shfl_xor_sync(0xffffffffu, sum1, 1);
        sum1 += __shfl_xor_sync(0xffffffffu, sum1, 2);
        sum2 += __shfl_xor_sync(0xffffffffu, sum2, 1);
        sum2 += __shfl_xor_sync(0xffffffffu, sum2, 2);
        float inv1 = 1.0f / sum1, inv2 = 1.0f / sum2;

        float o[4][4] = {};
#pragma unroll
        for (int kc2 = 0; kc2 < 4; kc2++) {
            uint32_t pa[4];
            pa[0] = packbf(acc[2 * kc2][0],     acc[2 * kc2][1]);
            pa[1] = packbf(acc[2 * kc2][2],     acc[2 * kc2][3]);
            pa[2] = packbf(acc[2 * kc2 + 1][0], acc[2 * kc2 + 1][1]);
            pa[3] = packbf(acc[2 * kc2 + 1][2], acc[2 * kc2 + 1][3]);
#pragma unroll
            for (int nj = 0; nj < 2; nj++) {
                uint32_t vb[4];
                ldm_x4t(vb, &sV[hs][kc2 * 16 + lrow][nj * 16 + lcol]);
                MMA16816(o[nj * 2 + 0], pa, vb[0], vb[1]);
                MMA16816(o[nj * 2 + 1], pa, vb[2], vb[3]);
            }
        }
        int H = p * 2 + hs;
        int row1 = r0 + qr, row2 = r0 + qr + 8;
        if (row1 < NTOK) {
            bf16* dst = O + (size_t)(win * NTOK + row1) * CDIM + H * HDIM + qc * 2;
#pragma unroll
            for (int nt = 0; nt < 4; nt++) {
                __nv_bfloat162 pk;
                pk.x = __float2bfloat16(o[nt][0] * inv1);
                pk.y = __float2bfloat16(o[nt][1] * inv1);
                *(__nv_bfloat162*)(dst + nt * 8) = pk;
            }
        }
        if (row2 < NTOK) {
            bf16* dst = O + (size_t)(win * NTOK + row2) * CDIM + H * HDIM + qc * 2;
#pragma unroll
            for (int nt = 0; nt < 4; nt++) {
                __nv_bfloat162 pk;
                pk.x = __float2bfloat16(o[nt][2] * inv2);
                pk.y = __float2bfloat16(o[nt][3] * inv2);
                *(__nv_bfloat162*)(dst + nt * 8) = pk;
            }
        }
    }
}

// ---------------- launch ----------------
extern "C" void kernel_launch(void* const* d_in, const int* in_sizes, int n_in,
                              void* d_out, int out_size)
{
    const float* hidden  = (const float*)d_in[0];
    const float* ln1_g   = (const float*)d_in[1];
    const float* ln1_b   = (const float*)d_in[2];
    const float* q_w     = (const float*)d_in[3];
    const float* q_b     = (const float*)d_in[4];
    const float* k_w     = (const float*)d_in[5];
    const float* k_b     = (const float*)d_in[6];
    const float* v_w     = (const float*)d_in[7];
    const float* v_b     = (const float*)d_in[8];
    const float* rpb     = (const float*)d_in[9];
    const int*   rpi     = (const int*)  d_in[10];
    const float* proj_w  = (const float*)d_in[11];
    const float* proj_b  = (const float*)d_in[12];
    const float* ln2_g   = (const float*)d_in[13];
    const float* ln2_b   = (const float*)d_in[14];
    const float* fc1_w   = (const float*)d_in[15];
    const float* fc1_b   = (const float*)d_in[16];
    const float* fc2_w   = (const float*)d_in[17];
    const float* fc2_b   = (const float*)d_in[18];
    float* out = (float*)d_out;

    bf16 *p_xw, *p_qkv, *p_ctx, *p_ln2, *p_y1;
    bf16 *p_wqkv, *p_wp, *p_w1, *p_w2, *p_bias;
    float *p_h, *p_bqkv;
    cudaGetSymbolAddress((void**)&p_xw,   g_xw);
    cudaGetSymbolAddress((void**)&p_qkv,  g_qkv);
    cudaGetSymbolAddress((void**)&p_ctx,  g_ctx);
    cudaGetSymbolAddress((void**)&p_h,    g_h);
    cudaGetSymbolAddress((void**)&p_ln2,  g_ln2);
    cudaGetSymbolAddress((void**)&p_y1,   g_y1);
    cudaGetSymbolAddress((void**)&p_wqkv, g_wqkv);
    cudaGetSymbolAddress((void**)&p_bqkv, g_bqkv);
    cudaGetSymbolAddress((void**)&p_wp,   g_wp);
    cudaGetSymbolAddress((void**)&p_w1,   g_w1);
    cudaGetSymbolAddress((void**)&p_w2,   g_w2);
    cudaGetSymbolAddress((void**)&p_bias, g_bias);

    cudaFuncSetAttribute(mma_gemm<0, bf16>,  cudaFuncAttributeMaxDynamicSharedMemorySize, TCSMEM);
    cudaFuncSetAttribute(mma_gemm<1, bf16>,  cudaFuncAttributeMaxDynamicSharedMemorySize, TCSMEM);
    cudaFuncSetAttribute(mma_gemm<2, float>, cudaFuncAttributeMaxDynamicSharedMemorySize, TCSMEM);
    cudaFuncSetAttribute(mma_gemm<3, float>, cudaFuncAttributeMaxDynamicSharedMemorySize, TCSMEM);

    // weight packing / conversion + bias tiles
    pack_qkv_kernel<<<(QKV_W4 + QKVN / 4 + 255) / 256, 256>>>(
        q_w, k_w, v_w, q_b, k_b, v_b, p_wqkv, p_bqkv);
    f2bf3_kernel<<<(W_PROJ4 + 2 * W_FFN4 + 255) / 256, 256>>>(
        proj_w, p_wp, fc1_w, p_w1, fc2_w, p_w2);
    bias_kernel<<<dim3(4, NHEADS), 256>>>(rpb, rpi, p_bias);

    // 1) LN1 + shift-roll + window partition (gather)
    ln_kernel<<<MTOK, 128>>>(hidden, ln1_g, ln1_b, p_xw, 1);

    // 2) fused QKV projection
    mma_gemm<0, bf16><<<dim3(QKVN / GBN, MTOK / GBM), 256, TCSMEM>>>(
        p_xw, p_wqkv, p_bqkv, nullptr, p_qkv, MTOK, QKVN, CDIM);

    // 3) windowed attention (tensor cores)
    attn_mma_kernel<<<TOTWIN, 256>>>(p_qkv, p_bias, p_ctx);

    // 4) output projection + window-reverse + roll-back + residual (scatter)
    mma_gemm<2, float><<<dim3(CDIM / GBN, MTOK / GBM), 256, TCSMEM>>>(
        p_ctx, p_wp, proj_b, hidden, p_h, MTOK, CDIM, CDIM);

    // 5) LN2
    ln_kernel<<<MTOK, 128>>>(p_h, ln2_g, ln2_b, p_ln2, 0);

    // 6) fc1 + exact GELU
    mma_gemm<1, bf16><<<dim3(FFNDIM / GBN, MTOK / GBM), 256, TCSMEM>>>(
        p_ln2, p_w1, fc1_b, nullptr, p_y1, MTOK, FFNDIM, CDIM);

    // 7) fc2 + residual -> final output
    mma_gemm<3, float><<<dim3(CDIM / GBN, MTOK / GBM), 256, TCSMEM>>>(
        p_y1, p_w2, fc2_b, p_h, out, MTOK, CDIM, FFNDIM);
}

// round 10
// speedup vs baseline: 1.4933x; 1.0005x over previous
#include <cuda_runtime.h>
#include <cuda_bf16.h>
#include <math.h>
#include <stdint.h>

// ---------------- problem constants ----------------
#define BATCH   8
#define HIMG    56
#define WIMG    56
#define CDIM    384
#define NHEADS  12
#define HDIM    32
#define WIN     7
#define NTOK    49
#define SHIFT_S 3
#define TOTWIN  512
#define MTOK    25088
#define FFNDIM  1536
#define QKVN    1152          // 3*CDIM

typedef __nv_bfloat16 bf16;

// ---------------- scratch (device globals; allocation-free) ----------------
__device__ bf16  g_xw  [MTOK * CDIM];
__device__ bf16  g_qkv [MTOK * QKVN];
__device__ bf16  g_ctx [MTOK * CDIM];
__device__ float g_h   [MTOK * CDIM];
__device__ bf16  g_ln2 [MTOK * CDIM];
__device__ bf16  g_y1  [MTOK * FFNDIM];
__device__ bf16  g_wqkv[CDIM * QKVN];   // [K][N] packed q|k|v
__device__ float g_bqkv[QKVN];
__device__ bf16  g_wp  [CDIM * CDIM];
__device__ bf16  g_w1  [CDIM * FFNDIM];
__device__ bf16  g_w2  [FFNDIM * CDIM];
__device__ bf16  g_bias[4 * NHEADS * 64 * 64];

// windowed row r <-> original token t (same map both directions)
__device__ __forceinline__ int win_row_to_token(int r) {
    int b    = r / (HIMG * WIMG);
    int rem  = r - b * (HIMG * WIMG);
    int widx = rem / NTOK;
    int tok  = rem - widx * NTOK;
    int wi = widx >> 3, wj = widx & 7;
    int i = tok / WIN, j = tok - i * WIN;
    int sh = wi * WIN + i + SHIFT_S; if (sh >= HIMG) sh -= HIMG;
    int sw = wj * WIN + j + SHIFT_S; if (sw >= WIMG) sw -= WIMG;
    return b * (HIMG * WIMG) + sh * WIMG + sw;
}

// ---------------- fused fp32 -> bf16 convert (proj | fc1 | fc2) ------------
#define W_PROJ4 (CDIM * CDIM / 4)
#define W_FFN4  (CDIM * FFNDIM / 4)
__global__ void __launch_bounds__(256) f2bf3_kernel(
    const float* __restrict__ s0, bf16* __restrict__ d0,
    const float* __restrict__ s1, bf16* __restrict__ d1,
    const float* __restrict__ s2, bf16* __restrict__ d2)
{
    int i = blockIdx.x * blockDim.x + threadIdx.x;
    const float* src; bf16* dst; int idx;
    if (i < W_PROJ4)                 { src = s0; dst = d0; idx = i; }
    else if (i < W_PROJ4 + W_FFN4)   { src = s1; dst = d1; idx = i - W_PROJ4; }
    else if (i < W_PROJ4 + 2*W_FFN4) { src = s2; dst = d2; idx = i - W_PROJ4 - W_FFN4; }
    else return;
    float4 v = ((const float4*)src)[idx];
    bf16 o[4] = {__float2bfloat16(v.x), __float2bfloat16(v.y),
                 __float2bfloat16(v.z), __float2bfloat16(v.w)};
    *(uint64_t*)(dst + (size_t)idx * 4) = *(uint64_t*)o;
}

// ---------------- pack q|k|v weights + biases ----------------
#define QKV_W4 (CDIM * QKVN / 4)
__global__ void __launch_bounds__(256) pack_qkv_kernel(
    const float* __restrict__ qw, const float* __restrict__ kw,
    const float* __restrict__ vw, const float* __restrict__ qb,
    const float* __restrict__ kb, const float* __restrict__ vb,
    bf16* __restrict__ wout, float* __restrict__ bout)
{
    int i = blockIdx.x * blockDim.x + threadIdx.x;
    if (i < QKV_W4) {
        int row = i / (QKVN / 4);
        int col = (i % (QKVN / 4)) * 4;
        const float* src = (col < CDIM) ? qw : (col < 2 * CDIM ? kw : vw);
        int c = col - (col < CDIM ? 0 : (col < 2 * CDIM ? CDIM : 2 * CDIM));
        float4 v = *(const float4*)(src + (size_t)row * CDIM + c);
        bf16 o[4] = {__float2bfloat16(v.x), __float2bfloat16(v.y),
                     __float2bfloat16(v.z), __float2bfloat16(v.w)};
        *(uint64_t*)(wout + (size_t)i * 4) = *(uint64_t*)o;
    } else if (i < QKV_W4 + QKVN / 4) {
        int col = (i - QKV_W4) * 4;
        const float* src = (col < CDIM) ? qb : (col < 2 * CDIM ? kb : vb);
        int c = col - (col < CDIM ? 0 : (col < 2 * CDIM ? CDIM : 2 * CDIM));
        *(float4*)(bout + col) = *(const float4*)(src + c);
    }
}

// ---------------- precompute attention bias+mask tiles ----------------
__global__ void __launch_bounds__(256) bias_kernel(
    const float* __restrict__ rpb, const int* __restrict__ rpi,
    bf16* __restrict__ out)
{
    int type = blockIdx.x, h = blockIdx.y;
    for (int idx = threadIdx.x; idx < 64 * 64; idx += 256) {
        int n = idx >> 6, m = idx & 63;
        float v;
        if (m >= 49)      v = -1e30f;
        else if (n >= 49) v = 0.f;
        else {
            v = rpb[rpi[n * 49 + m] * NHEADS + h];
            int ni = n / 7, nj = n % 7, mi = m / 7, mj = m % 7;
            int cn = ((type & 2) ? (ni < 4 ? 1 : 2) : 0) * 3 + ((type & 1) ? (nj < 4 ? 1 : 2) : 0);
            int cm = ((type & 2) ? (mi < 4 ? 1 : 2) : 0) * 3 + ((type & 1) ? (mj < 4 ? 1 : 2) : 0);
            if (cn != cm) v -= 100.0f;
        }
        out[(((size_t)type * NHEADS + h) * 64 + n) * 64 + m] = __float2bfloat16(v);
    }
}

// ---------------- LayerNorm (fp32 in, bf16 out) ----------------
__global__ void __launch_bounds__(128) ln_kernel(
    const float* __restrict__ x, const float* __restrict__ g,
    const float* __restrict__ b, bf16* __restrict__ out, int permute)
{
    int r = blockIdx.x;
    int t = permute ? win_row_to_token(r) : r;
    const float* xi = x + (size_t)t * CDIM;
    bf16*        yo = out + (size_t)r * CDIM;
    int tid = threadIdx.x;

    float v[3];
    float s = 0.f, ss = 0.f;
#pragma unroll
    for (int i = 0; i < 3; i++) {
        v[i] = xi[tid + i * 128];
        s += v[i]; ss += v[i] * v[i];
    }
#pragma unroll
    for (int o = 16; o; o >>= 1) {
        s  += __shfl_xor_sync(0xffffffffu, s,  o);
        ss += __shfl_xor_sync(0xffffffffu, ss, o);
    }
    __shared__ float red[8];
    __shared__ float stat[2];
    int wid = tid >> 5, lane = tid & 31;
    if (lane == 0) { red[wid] = s; red[4 + wid] = ss; }
    __syncthreads();
    if (tid == 0) {
        float S  = red[0] + red[1] + red[2] + red[3];
        float SS = red[4] + red[5] + red[6] + red[7];
        float mu = S * (1.0f / CDIM);
        float var = SS * (1.0f / CDIM) - mu * mu;
        stat[0] = mu;
        stat[1] = rsqrtf(var + 1e-5f);
    }
    __syncthreads();
    float mu = stat[0], rstd = stat[1];
#pragma unroll
    for (int i = 0; i < 3; i++) {
        int c = tid + i * 128;
        yo[c] = __float2bfloat16((v[i] - mu) * rstd * g[c] + b[c]);
    }
}

// ---------------- mma helpers ----------------
#define CP16(dst, src) \
    asm volatile("cp.async.ca.shared.global [%0], [%1], 16;\n" :: \
        "r"((uint32_t)__cvta_generic_to_shared(dst)), "l"(src))
#define CP16CG(dst, src) \
    asm volatile("cp.async.cg.shared.global [%0], [%1], 16;\n" :: \
        "r"((uint32_t)__cvta_generic_to_shared(dst)), "l"(src))
#define CP_COMMIT()  asm volatile("cp.async.commit_group;\n" ::)
#define CP_WAIT(n)   asm volatile("cp.async.wait_group %0;\n" :: "n"(n))

__device__ __forceinline__ void ldm_x4(uint32_t* r, const void* p) {
    uint32_t a = (uint32_t)__cvta_generic_to_shared(p);
    asm volatile("ldmatrix.sync.aligned.m8n8.x4.shared.b16 {%0,%1,%2,%3},[%4];"
        : "=r"(r[0]), "=r"(r[1]), "=r"(r[2]), "=r"(r[3]) : "r"(a));
}
__device__ __forceinline__ void ldm_x4t(uint32_t* r, const void* p) {
    uint32_t a = (uint32_t)__cvta_generic_to_shared(p);
    asm volatile("ldmatrix.sync.aligned.m8n8.x4.trans.shared.b16 {%0,%1,%2,%3},[%4];"
        : "=r"(r[0]), "=r"(r[1]), "=r"(r[2]), "=r"(r[3]) : "r"(a));
}
#define MMA16816(d, a, b0, b1) \
    asm volatile("mma.sync.aligned.m16n8k16.row.col.f32.bf16.bf16.f32 " \
        "{%0,%1,%2,%3},{%4,%5,%6,%7},{%8,%9},{%0,%1,%2,%3};" \
        : "+f"(d[0]), "+f"(d[1]), "+f"(d[2]), "+f"(d[3]) \
        : "r"(a[0]), "r"(a[1]), "r"(a[2]), "r"(a[3]), "r"(b0), "r"(b1))

__device__ __forceinline__ uint32_t packbf(float lo, float hi) {
    __nv_bfloat162 h = __floats2bfloat162_rn(lo, hi);
    return *(uint32_t*)&h;
}

// ---------------- HMMA bf16 GEMM, 128x128x32, 5-stage, XOR-swizzled --------
// R3-proven warp layout (8 warps of 32x64); prefetch distance 3.
// EPI 0: store  1: exact GELU  2: scatter+residual  3: residual
#define GBM 128
#define GBN 128
#define GBK 32
#define NSTG 5
#define STG_A (GBM * GBK)     // 4096 elems = 8KB
#define STG_B (GBK * GBN)     // 4096 elems = 8KB
#define TCSMEM (NSTG * (STG_A + STG_B) * 2)   // 81920 bytes

template <int EPI, typename OutT>
__global__ void __launch_bounds__(256) mma_gemm(
    const bf16* __restrict__ A, const bf16* __restrict__ B,
    const float* __restrict__ bias, const float* __restrict__ add,
    OutT* __restrict__ C, int M, int N, int K)
{
    extern __shared__ __align__(16) bf16 sm[];
    bf16* As = sm;                    // NSTG stages x 4096 elems
    bf16* Bs = sm + NSTG * STG_A;     // NSTG stages x 4096 elems

    int t = threadIdx.x;
    int m0 = blockIdx.y * GBM, n0 = blockIdx.x * GBN;

    int ar = t >> 2, acw = t & 3;                 // A: row, 16B chunk
    int br = t >> 3, bcw = (t & 7) * 2;           // B: k-row, chunk pair
    const bf16* Ag = A + (size_t)(m0 + ar) * K + acw * 8;
    const bf16* Bg = B + (size_t)br * N + n0 + bcw * 8;

    int aswz = (ar >> 1) & 3;                     // same for row ar and ar+64
    int a_off0 = ar * 32 + ((acw ^ aswz) << 3);
    int a_off1 = (ar + 64) * 32 + ((acw ^ aswz) << 3);
    int b_off0 = br * 128 + (((bcw)     ^ (br & 7)) << 3);
    int b_off1 = br * 128 + (((bcw + 1) ^ (br & 7)) << 3);

    int lane = t & 31, w = t >> 5;
    int m0w = (w >> 1) * 32, nw = (w & 1) * 64;
    int lrow = (lane & 7) + (lane & 8);
    int lcol = (lane & 16) >> 1;

    float acc[2][8][4] = {};

    int nk = K / GBK;
    // prologue: stages 0..NSTG-2
#pragma unroll
    for (int s = 0; s < NSTG - 1; s++) {
        int k0 = s * GBK;
        CP16CG(&As[s * STG_A + a_off0], Ag + k0);
        CP16CG(&As[s * STG_A + a_off1], Ag + (size_t)64 * K + k0);
        CP16CG(&Bs[s * STG_B + b_off0], Bg + (size_t)k0 * N);
        CP16CG(&Bs[s * STG_B + b_off1], Bg + (size_t)k0 * N + 8);
        CP_COMMIT();
    }

    for (int i = 0; i < nk; i++) {
        if (i + 3 < nk)      { CP_WAIT(3); }
        else if (i + 2 < nk) { CP_WAIT(2); }
        else if (i + 1 < nk) { CP_WAIT(1); }
        else                 { CP_WAIT(0); }
        __syncthreads();
        if (i + NSTG - 1 < nk) {
            int st = (i + NSTG - 1) % NSTG;
            int k0 = (i + NSTG - 1) * GBK;
            CP16CG(&As[st * STG_A + a_off0], Ag + k0);
            CP16CG(&As[st * STG_A + a_off1], Ag + (size_t)64 * K + k0);
            CP16CG(&Bs[st * STG_B + b_off0], Bg + (size_t)k0 * N);
            CP16CG(&Bs[st * STG_B + b_off1], Bg + (size_t)k0 * N + 8);
            CP_COMMIT();
        }
        int cs = i % NSTG;
        const bf16* Asc = As + cs * STG_A;
        const bf16* Bsc = Bs + cs * STG_B;
#pragma unroll
        for (int kk = 0; kk < GBK; kk += 16) {
            uint32_t a[2][4], b[4][4];
#pragma unroll
            for (int mi = 0; mi < 2; mi++) {
                int R = m0w + mi * 16 + lrow;
                int cr = (kk + lcol) >> 3;
                ldm_x4(a[mi], Asc + R * 32 + ((cr ^ ((R >> 1) & 3)) << 3));
            }
#pragma unroll
            for (int nj = 0; nj < 4; nj++) {
                int Kr = kk + lrow;
                int cn = (nw + nj * 16 + lcol) >> 3;
                ldm_x4t(b[nj], Bsc + Kr * 128 + ((cn ^ (Kr & 7)) << 3));
            }
#pragma unroll
            for (int mi = 0; mi < 2; mi++) {
#pragma unroll
                for (int nt = 0; nt < 8; nt++)
                    MMA16816(acc[mi][nt], a[mi],
                             b[nt >> 1][(nt & 1) * 2], b[nt >> 1][(nt & 1) * 2 + 1]);
            }
        }
    }

    // epilogue
#pragma unroll
    for (int mi = 0; mi < 2; mi++) {
        int rbase = m0 + m0w + mi * 16 + (lane >> 2);
#pragma unroll
        for (int h2 = 0; h2 < 2; h2++) {
            int row = rbase + 8 * h2;
            int orow = (EPI == 2) ? win_row_to_token(row) : row;
#pragma unroll
            for (int nt = 0; nt < 8; nt++) {
                int col = n0 + nw + nt * 8 + (lane & 3) * 2;
                float v0 = acc[mi][nt][2 * h2 + 0] + bias[col];
                float v1 = acc[mi][nt][2 * h2 + 1] + bias[col + 1];
                if (EPI == 1) {
                    v0 = 0.5f * v0 * (1.0f + erff(v0 * 0.7071067811865475f));
                    v1 = 0.5f * v1 * (1.0f + erff(v1 * 0.7071067811865475f));
                } else if (EPI == 2 || EPI == 3) {
                    const float* ap = add + (size_t)orow * N + col;
                    v0 += ap[0];
                    v1 += ap[1];
                }
                OutT* cp = C + (size_t)orow * N + col;
                if (sizeof(OutT) == 2) {
                    __nv_bfloat162 pk;
                    pk.x = __float2bfloat16(v0);
                    pk.y = __float2bfloat16(v1);
                    *(__nv_bfloat162*)cp = pk;
                } else {
                    float2 pk = make_float2(v0, v1);
                    *(float2*)cp = pk;
                }
            }
        }
    }
}

// ---------------- tensor-core window attention ----------------
__global__ void __launch_bounds__(256) attn_mma_kernel(
    const bf16* __restrict__ QKV, const bf16* __restrict__ bias_all,
    bf16* __restrict__ O)
{
    __shared__ __align__(16) bf16 sQ[2][64][40];
    __shared__ __align__(16) bf16 sK[2][64][40];
    __shared__ __align__(16) bf16 sV[2][64][40];
    __shared__ __align__(16) bf16 sB[2][64][72];

    int win = blockIdx.x, t = threadIdx.x;
    int widx = win & 63;
    int type = (((widx >> 3) == 7) ? 2 : 0) + (((widx & 7) == 7) ? 1 : 0);

    for (int i = t; i < 2 * 15 * 40; i += 256) {
        int hs = i / 600, rem = i % 600;
        int row = 49 + rem / 40, col = rem % 40;
        sK[hs][row][col] = __float2bfloat16(0.f);
        sV[hs][row][col] = __float2bfloat16(0.f);
    }

    int lane = t & 31, w = t >> 5;
    int hs = w >> 2, ww = w & 3;
    int r0 = ww * 16;
    int lrow = (lane & 7) + (lane & 8);
    int lcol = (lane & 16) >> 1;
    int qr = lane >> 2, qc = lane & 3;
    const float scale = 0.17677669529663687f;

    int lr = t >> 2, lc = t & 3;

    for (int p = 0; p < 6; p++) {
        __syncthreads();
        if (lr < 49) {
            const bf16* src = QKV + (size_t)(win * NTOK + lr) * QKVN + lc * 8;
#pragma unroll
            for (int hh = 0; hh < 2; hh++) {
                int h = p * 2 + hh;
                CP16CG(&sQ[hh][lr][lc * 8], src + h * HDIM);
                CP16CG(&sK[hh][lr][lc * 8], src + h * HDIM + CDIM);
                CP16CG(&sV[hh][lr][lc * 8], src + h * HDIM + 2 * CDIM);
            }
        }
#pragma unroll
        for (int hh = 0; hh < 2; hh++) {
            int h = p * 2 + hh;
            const bf16* bsrc = bias_all + (((size_t)type * NHEADS + h) * 64 + lr) * 64;
            CP16(&sB[hh][lr][lc * 8], bsrc + lc * 8);
            CP16(&sB[hh][lr][(lc + 4) * 8], bsrc + (lc + 4) * 8);
        }
        CP_COMMIT(); CP_WAIT(0);
        __syncthreads();

        float acc[8][4] = {};
#pragma unroll
        for (int kc = 0; kc < 32; kc += 16) {
            uint32_t a[4];
            ldm_x4(a, &sQ[hs][r0 + lrow][kc + lcol]);
            uint32_t bb[4][4];
#pragma unroll
            for (int nj = 0; nj < 4; nj++)
                ldm_x4(bb[nj], &sK[hs][nj * 16 + lrow][kc + lcol]);
#pragma unroll
            for (int nj = 0; nj < 4; nj++) {
                MMA16816(acc[nj * 2 + 0], a, bb[nj][0], bb[nj][2]);
                MMA16816(acc[nj * 2 + 1], a, bb[nj][1], bb[nj][3]);
            }
        }
#pragma unroll
        for (int cj = 0; cj < 4; cj++) {
            uint32_t bf[4];
            ldm_x4(bf, &sB[hs][r0 + lrow][cj * 16 + lcol]);
            float2 f0 = __bfloat1622float2(*(__nv_bfloat162*)&bf[0]);
            float2 f1 = __bfloat1622float2(*(__nv_bfloat162*)&bf[1]);
            float2 f2 = __bfloat1622float2(*(__nv_bfloat162*)&bf[2]);
            float2 f3 = __bfloat1622float2(*(__nv_bfloat162*)&bf[3]);
            acc[2 * cj][0] = acc[2 * cj][0] * scale + f0.x;
            acc[2 * cj][1] = acc[2 * cj][1] * scale + f0.y;
            acc[2 * cj][2] = acc[2 * cj][2] * scale + f1.x;
            acc[2 * cj][3] = acc[2 * cj][3] * scale + f1.y;
            acc[2 * cj + 1][0] = acc[2 * cj + 1][0] * scale + f2.x;
            acc[2 * cj + 1][1] = acc[2 * cj + 1][1] * scale + f2.y;
            acc[2 * cj + 1][2] = acc[2 * cj + 1][2] * scale + f3.x;
            acc[2 * cj + 1][3] = acc[2 * cj + 1][3] * scale + f3.y;
        }
        float mx1 = -1e30f, mx2 = -1e30f;
#pragma unroll
        for (int nt = 0; nt < 8; nt++) {
            mx1 = fmaxf(mx1, fmaxf(acc[nt][0], acc[nt][1]));
            mx2 = fmaxf(mx2, fmaxf(acc[nt][2], acc[nt][3]));
        }
        mx1 = fmaxf(mx1, __shfl_xor_sync(0xffffffffu, mx1, 1));
        mx1 = fmaxf(mx1, __shfl_xor_sync(0xffffffffu, mx1, 2));
        mx2 = fmaxf(mx2, __shfl_xor_sync(0xffffffffu, mx2, 1));
        mx2 = fmaxf(mx2, __shfl_xor_sync(0xffffffffu, mx2, 2));
        float sum1 = 0.f, sum2 = 0.f;
#pragma unroll
        for (int nt = 0; nt < 8; nt++) {
            acc[nt][0] = __expf(acc[nt][0] - mx1);
            acc[nt][1] = __expf(acc[nt][1] - mx1);
            acc[nt][2] = __expf(acc[nt][2] - mx2);
            acc[nt][3] = __expf(acc[nt][3] - mx2);
            sum1 += acc[nt][0] + acc[nt][1];
            sum2 += acc[nt][2] + acc[nt][3];
        }
        sum1 += __shfl_xor_sync(0xffffffffu, sum1, 1);
        sum1 += __shfl_xor_sync(0xffffffffu, sum1, 2);
        sum2 += __shfl_xor_sync(0xffffffffu, sum2, 1);
        sum2 += __shfl_xor_sync(0xffffffffu, sum2, 2);
        float inv1 = 1.0f / sum1, inv2 = 1.0f / sum2;

        float o[4][4] = {};
#pragma unroll
        for (int kc2 = 0; kc2 < 4; kc2++) {
            uint32_t pa[4];
            pa[0] = packbf(acc[2 * kc2][0],     acc[2 * kc2][1]);
            pa[1] = packbf(acc[2 * kc2][2],     acc[2 * kc2][3]);
            pa[2] = packbf(acc[2 * kc2 + 1][0], acc[2 * kc2 + 1][1]);
            pa[3] = packbf(acc[2 * kc2 + 1][2], acc[2 * kc2 + 1][3]);
#pragma unroll
            for (int nj = 0; nj < 2; nj++) {
                uint32_t vb[4];
                ldm_x4t(vb, &sV[hs][kc2 * 16 + lrow][nj * 16 + lcol]);
                MMA16816(o[nj * 2 + 0], pa, vb[0], vb[1]);
                MMA16816(o[nj * 2 + 1], pa, vb[2], vb[3]);
            }
        }
        int H = p * 2 + hs;
        int row1 = r0 + qr, row2 = r0 + qr + 8;
        if (row1 < NTOK) {
            bf16* dst = O + (size_t)(win * NTOK + row1) * CDIM + H * HDIM + qc * 2;
#pragma unroll
            for (int nt = 0; nt < 4; nt++) {
                __nv_bfloat162 pk;
                pk.x = __float2bfloat16(o[nt][0] * inv1);
                pk.y = __float2bfloat16(o[nt][1] * inv1);
                *(__nv_bfloat162*)(dst + nt * 8) = pk;
            }
        }
        if (row2 < NTOK) {
            bf16* dst = O + (size_t)(win * NTOK + row2) * CDIM + H * HDIM + qc * 2;
#pragma unroll
            for (int nt = 0; nt < 4; nt++) {
                __nv_bfloat162 pk;
                pk.x = __float2bfloat16(o[nt][2] * inv2);
                pk.y = __float2bfloat16(o[nt][3] * inv2);
                *(__nv_bfloat162*)(dst + nt * 8) = pk;
            }
        }
    }
}

// ---------------- launch ----------------
extern "C" void kernel_launch(void* const* d_in, const int* in_sizes, int n_in,
                              void* d_out, int out_size)
{
    const float* hidden  = (const float*)d_in[0];
    const float* ln1_g   = (const float*)d_in[1];
    const float* ln1_b   = (const float*)d_in[2];
    const float* q_w     = (const float*)d_in[3];
    const float* q_b     = (const float*)d_in[4];
    const float* k_w     = (const float*)d_in[5];
    const float* k_b     = (const float*)d_in[6];
    const float* v_w     = (const float*)d_in[7];
    const float* v_b     = (const float*)d_in[8];
    const float* rpb     = (const float*)d_in[9];
    const int*   rpi     = (const int*)  d_in[10];
    const float* proj_w  = (const float*)d_in[11];
    const float* proj_b  = (const float*)d_in[12];
    const float* ln2_g   = (const float*)d_in[13];
    const float* ln2_b   = (const float*)d_in[14];
    const float* fc1_w   = (const float*)d_in[15];
    const float* fc1_b   = (const float*)d_in[16];
    const float* fc2_w   = (const float*)d_in[17];
    const float* fc2_b   = (const float*)d_in[18];
    float* out = (float*)d_out;

    bf16 *p_xw, *p_qkv, *p_ctx, *p_ln2, *p_y1;
    bf16 *p_wqkv, *p_wp, *p_w1, *p_w2, *p_bias;
    float *p_h, *p_bqkv;
    cudaGetSymbolAddress((void**)&p_xw,   g_xw);
    cudaGetSymbolAddress((void**)&p_qkv,  g_qkv);
    cudaGetSymbolAddress((void**)&p_ctx,  g_ctx);
    cudaGetSymbolAddress((void**)&p_h,    g_h);
    cudaGetSymbolAddress((void**)&p_ln2,  g_ln2);
    cudaGetSymbolAddress((void**)&p_y1,   g_y1);
    cudaGetSymbolAddress((void**)&p_wqkv, g_wqkv);
    cudaGetSymbolAddress((void**)&p_bqkv, g_bqkv);
    cudaGetSymbolAddress((void**)&p_wp,   g_wp);
    cudaGetSymbolAddress((void**)&p_w1,   g_w1);
    cudaGetSymbolAddress((void**)&p_w2,   g_w2);
    cudaGetSymbolAddress((void**)&p_bias, g_bias);

    cudaFuncSetAttribute(mma_gemm<0, bf16>,  cudaFuncAttributeMaxDynamicSharedMemorySize, TCSMEM);
    cudaFuncSetAttribute(mma_gemm<1, bf16>,  cudaFuncAttributeMaxDynamicSharedMemorySize, TCSMEM);
    cudaFuncSetAttribute(mma_gemm<2, float>, cudaFuncAttributeMaxDynamicSharedMemorySize, TCSMEM);
    cudaFuncSetAttribute(mma_gemm<3, float>, cudaFuncAttributeMaxDynamicSharedMemorySize, TCSMEM);

    // weight packing / conversion + bias tiles
    pack_qkv_kernel<<<(QKV_W4 + QKVN / 4 + 255) / 256, 256>>>(
        q_w, k_w, v_w, q_b, k_b, v_b, p_wqkv, p_bqkv);
    f2bf3_kernel<<<(W_PROJ4 + 2 * W_FFN4 + 255) / 256, 256>>>(
        proj_w, p_wp, fc1_w, p_w1, fc2_w, p_w2);
    bias_kernel<<<dim3(4, NHEADS), 256>>>(rpb, rpi, p_bias);

    // 1) LN1 + shift-roll + window partition (gather)
    ln_kernel<<<MTOK, 128>>>(hidden, ln1_g, ln1_b, p_xw, 1);

    // 2) fused QKV projection
    mma_gemm<0, bf16><<<dim3(QKVN / GBN, MTOK / GBM), 256, TCSMEM>>>(
        p_xw, p_wqkv, p_bqkv, nullptr, p_qkv, MTOK, QKVN, CDIM);

    // 3) windowed attention (tensor cores)
    attn_mma_kernel<<<TOTWIN, 256>>>(p_qkv, p_bias, p_ctx);

    // 4) output projection + window-reverse + roll-back + residual (scatter)
    mma_gemm<2, float><<<dim3(CDIM / GBN, MTOK / GBM), 256, TCSMEM>>>(
        p_ctx, p_wp, proj_b, hidden, p_h, MTOK, CDIM, CDIM);

    // 5) LN2
    ln_kernel<<<MTOK, 128>>>(p_h, ln2_g, ln2_b, p_ln2, 0);

    // 6) fc1 + exact GELU
    mma_gemm<1, bf16><<<dim3(FFNDIM / GBN, MTOK / GBM), 256, TCSMEM>>>(
        p_ln2, p_w1, fc1_b, nullptr, p_y1, MTOK, FFNDIM, CDIM);

    // 7) fc2 + residual -> final output
    mma_gemm<3, float><<<dim3(CDIM / GBN, MTOK / GBM), 256, TCSMEM>>>(
        p_y1, p_w2, fc2_b, p_h, out, MTOK, CDIM, FFNDIM);
}

// round 11
// speedup vs baseline: 1.5516x; 1.0390x over previous
#include <cuda_runtime.h>
#include <cuda_bf16.h>
#include <math.h>
#include <stdint.h>

// ---------------- problem constants ----------------
#define BATCH   8
#define HIMG    56
#define WIMG    56
#define CDIM    384
#define NHEADS  12
#define HDIM    32
#define WIN     7
#define NTOK    49
#define SHIFT_S 3
#define TOTWIN  512
#define MTOK    25088
#define FFNDIM  1536
#define QKVN    1152          // 3*CDIM

typedef __nv_bfloat16 bf16;

// ---------------- scratch (device globals; allocation-free) ----------------
__device__ bf16  g_xw  [MTOK * CDIM];
__device__ bf16  g_qkv [MTOK * QKVN];
__device__ bf16  g_ctx [MTOK * CDIM];
__device__ float g_h   [MTOK * CDIM];
__device__ bf16  g_ln2 [MTOK * CDIM];
__device__ bf16  g_y1  [MTOK * FFNDIM];
__device__ bf16  g_wqkv[CDIM * QKVN];   // [K][N] packed q|k|v
__device__ float g_bqkv[QKVN];
__device__ bf16  g_wp  [CDIM * CDIM];
__device__ bf16  g_w1  [CDIM * FFNDIM];
__device__ bf16  g_w2  [FFNDIM * CDIM];
__device__ bf16  g_bias[4 * NHEADS * 64 * 64];

// windowed row r <-> original token t (same map both directions)
__device__ __forceinline__ int win_row_to_token(int r) {
    int b    = r / (HIMG * WIMG);
    int rem  = r - b * (HIMG * WIMG);
    int widx = rem / NTOK;
    int tok  = rem - widx * NTOK;
    int wi = widx >> 3, wj = widx & 7;
    int i = tok / WIN, j = tok - i * WIN;
    int sh = wi * WIN + i + SHIFT_S; if (sh >= HIMG) sh -= HIMG;
    int sw = wj * WIN + j + SHIFT_S; if (sw >= WIMG) sw -= WIMG;
    return b * (HIMG * WIMG) + sh * WIMG + sw;
}

// ---------------- fused prep: pack qkv | convert weights | bias tiles ------
#define W_PROJ4 (CDIM * CDIM / 4)          // 36864
#define W_FFN4  (CDIM * FFNDIM / 4)        // 147456
#define QKV_W4  (CDIM * QKVN / 4)          // 110592
#define PREP_QKV_ITEMS  (QKV_W4 + QKVN / 4)
#define PREP_W_ITEMS    (W_PROJ4 + 2 * W_FFN4)
#define PREP_QKV_BLOCKS ((PREP_QKV_ITEMS + 255) / 256)
#define PREP_W_BLOCKS   ((PREP_W_ITEMS + 255) / 256)
#define PREP_BIAS_BLOCKS 48
#define PREP_BLOCKS (PREP_QKV_BLOCKS + PREP_W_BLOCKS + PREP_BIAS_BLOCKS)

__global__ void __launch_bounds__(256) prep_kernel(
    const float* __restrict__ qw, const float* __restrict__ kw,
    const float* __restrict__ vw, const float* __restrict__ qb,
    const float* __restrict__ kb, const float* __restrict__ vb,
    bf16* __restrict__ wqkv, float* __restrict__ bqkv,
    const float* __restrict__ pw, bf16* __restrict__ wp,
    const float* __restrict__ w1s, bf16* __restrict__ w1,
    const float* __restrict__ w2s, bf16* __restrict__ w2,
    const float* __restrict__ rpb, const int* __restrict__ rpi,
    bf16* __restrict__ bias_out)
{
    int blk = blockIdx.x;
    if (blk < PREP_QKV_BLOCKS) {
        int i = blk * 256 + threadIdx.x;
        if (i < QKV_W4) {
            int row = i / (QKVN / 4);
            int col = (i % (QKVN / 4)) * 4;
            const float* src = (col < CDIM) ? qw : (col < 2 * CDIM ? kw : vw);
            int c = col - (col < CDIM ? 0 : (col < 2 * CDIM ? CDIM : 2 * CDIM));
            float4 v = *(const float4*)(src + (size_t)row * CDIM + c);
            bf16 o[4] = {__float2bfloat16(v.x), __float2bfloat16(v.y),
                         __float2bfloat16(v.z), __float2bfloat16(v.w)};
            *(uint64_t*)(wqkv + (size_t)i * 4) = *(uint64_t*)o;
        } else if (i < PREP_QKV_ITEMS) {
            int col = (i - QKV_W4) * 4;
            const float* src = (col < CDIM) ? qb : (col < 2 * CDIM ? kb : vb);
            int c = col - (col < CDIM ? 0 : (col < 2 * CDIM ? CDIM : 2 * CDIM));
            *(float4*)(bqkv + col) = *(const float4*)(src + c);
        }
    } else if (blk < PREP_QKV_BLOCKS + PREP_W_BLOCKS) {
        int i = (blk - PREP_QKV_BLOCKS) * 256 + threadIdx.x;
        const float* src; bf16* dst; int idx;
        if (i < W_PROJ4)                 { src = pw;  dst = wp; idx = i; }
        else if (i < W_PROJ4 + W_FFN4)   { src = w1s; dst = w1; idx = i - W_PROJ4; }
        else if (i < PREP_W_ITEMS)       { src = w2s; dst = w2; idx = i - W_PROJ4 - W_FFN4; }
        else return;
        float4 v = ((const float4*)src)[idx];
        bf16 o[4] = {__float2bfloat16(v.x), __float2bfloat16(v.y),
                     __float2bfloat16(v.z), __float2bfloat16(v.w)};
        *(uint64_t*)(dst + (size_t)idx * 4) = *(uint64_t*)o;
    } else {
        int bb = blk - PREP_QKV_BLOCKS - PREP_W_BLOCKS;   // 0..47
        int type = bb / NHEADS, h = bb % NHEADS;
        for (int idx = threadIdx.x; idx < 64 * 64; idx += 256) {
            int n = idx >> 6, m = idx & 63;
            float v;
            if (m >= 49)      v = -1e30f;
            else if (n >= 49) v = 0.f;
            else {
                v = rpb[rpi[n * 49 + m] * NHEADS + h];
                int ni = n / 7, nj = n % 7, mi = m / 7, mj = m % 7;
                int cn = ((type & 2) ? (ni < 4 ? 1 : 2) : 0) * 3 + ((type & 1) ? (nj < 4 ? 1 : 2) : 0);
                int cm = ((type & 2) ? (mi < 4 ? 1 : 2) : 0) * 3 + ((type & 1) ? (mj < 4 ? 1 : 2) : 0);
                if (cn != cm) v -= 100.0f;
            }
            bias_out[(((size_t)type * NHEADS + h) * 64 + n) * 64 + m] = __float2bfloat16(v);
        }
    }
}

// ---------------- LayerNorm: warp-per-row, no barriers ----------------
// 256 threads = 8 warps = 8 rows per block; lane loads 3 float4 (coalesced).
__global__ void __launch_bounds__(256) ln_kernel(
    const float* __restrict__ x, const float* __restrict__ g,
    const float* __restrict__ b, bf16* __restrict__ out, int permute)
{
    int r = blockIdx.x * 8 + (threadIdx.x >> 5);
    int lane = threadIdx.x & 31;
    int t = permute ? win_row_to_token(r) : r;
    const float4* xi = (const float4*)(x + (size_t)t * CDIM);

    float4 v[3];
    float s = 0.f, ss = 0.f;
#pragma unroll
    for (int j = 0; j < 3; j++) {
        v[j] = xi[lane + 32 * j];
        s  += v[j].x + v[j].y + v[j].z + v[j].w;
        ss += v[j].x * v[j].x + v[j].y * v[j].y
            + v[j].z * v[j].z + v[j].w * v[j].w;
    }
#pragma unroll
    for (int o = 16; o; o >>= 1) {
        s  += __shfl_xor_sync(0xffffffffu, s,  o);
        ss += __shfl_xor_sync(0xffffffffu, ss, o);
    }
    float mu = s * (1.0f / CDIM);
    float var = ss * (1.0f / CDIM) - mu * mu;
    float rstd = rsqrtf(var + 1e-5f);

    bf16* yo = out + (size_t)r * CDIM;
#pragma unroll
    for (int j = 0; j < 3; j++) {
        int c = (lane + 32 * j) * 4;
        float4 gg = *(const float4*)(g + c);
        float4 bb = *(const float4*)(b + c);
        bf16 o[4];
        o[0] = __float2bfloat16((v[j].x - mu) * rstd * gg.x + bb.x);
        o[1] = __float2bfloat16((v[j].y - mu) * rstd * gg.y + bb.y);
        o[2] = __float2bfloat16((v[j].z - mu) * rstd * gg.z + bb.z);
        o[3] = __float2bfloat16((v[j].w - mu) * rstd * gg.w + bb.w);
        *(uint64_t*)(yo + c) = *(uint64_t*)o;
    }
}

// ---------------- mma helpers ----------------
#define CP16(dst, src) \
    asm volatile("cp.async.ca.shared.global [%0], [%1], 16;\n" :: \
        "r"((uint32_t)__cvta_generic_to_shared(dst)), "l"(src))
#define CP16CG(dst, src) \
    asm volatile("cp.async.cg.shared.global [%0], [%1], 16;\n" :: \
        "r"((uint32_t)__cvta_generic_to_shared(dst)), "l"(src))
#define CP_COMMIT()  asm volatile("cp.async.commit_group;\n" ::)
#define CP_WAIT(n)   asm volatile("cp.async.wait_group %0;\n" :: "n"(n))

__device__ __forceinline__ void ldm_x4(uint32_t* r, const void* p) {
    uint32_t a = (uint32_t)__cvta_generic_to_shared(p);
    asm volatile("ldmatrix.sync.aligned.m8n8.x4.shared.b16 {%0,%1,%2,%3},[%4];"
        : "=r"(r[0]), "=r"(r[1]), "=r"(r[2]), "=r"(r[3]) : "r"(a));
}
__device__ __forceinline__ void ldm_x4t(uint32_t* r, const void* p) {
    uint32_t a = (uint32_t)__cvta_generic_to_shared(p);
    asm volatile("ldmatrix.sync.aligned.m8n8.x4.trans.shared.b16 {%0,%1,%2,%3},[%4];"
        : "=r"(r[0]), "=r"(r[1]), "=r"(r[2]), "=r"(r[3]) : "r"(a));
}
#define MMA16816(d, a, b0, b1) \
    asm volatile("mma.sync.aligned.m16n8k16.row.col.f32.bf16.bf16.f32 " \
        "{%0,%1,%2,%3},{%4,%5,%6,%7},{%8,%9},{%0,%1,%2,%3};" \
        : "+f"(d[0]), "+f"(d[1]), "+f"(d[2]), "+f"(d[3]) \
        : "r"(a[0]), "r"(a[1]), "r"(a[2]), "r"(a[3]), "r"(b0), "r"(b1))

__device__ __forceinline__ uint32_t packbf(float lo, float hi) {
    __nv_bfloat162 h = __floats2bfloat162_rn(lo, hi);
    return *(uint32_t*)&h;
}

// ---------------- HMMA bf16 GEMM, 128x128x32, 5-stage, XOR-swizzled --------
// EPI 0: store  1: exact GELU  2: scatter+residual  3: residual
#define GBM 128
#define GBN 128
#define GBK 32
#define NSTG 5
#define STG_A (GBM * GBK)
#define STG_B (GBK * GBN)
#define TCSMEM (NSTG * (STG_A + STG_B) * 2)   // 81920 bytes

template <int EPI, typename OutT>
__global__ void __launch_bounds__(256) mma_gemm(
    const bf16* __restrict__ A, const bf16* __restrict__ B,
    const float* __restrict__ bias, const float* __restrict__ add,
    OutT* __restrict__ C, int M, int N, int K)
{
    extern __shared__ __align__(16) bf16 sm[];
    bf16* As = sm;
    bf16* Bs = sm + NSTG * STG_A;

    int t = threadIdx.x;
    int m0 = blockIdx.y * GBM, n0 = blockIdx.x * GBN;

    int ar = t >> 2, acw = t & 3;
    int br = t >> 3, bcw = (t & 7) * 2;
    const bf16* Ag = A + (size_t)(m0 + ar) * K + acw * 8;
    const bf16* Bg = B + (size_t)br * N + n0 + bcw * 8;

    int aswz = (ar >> 1) & 3;
    int a_off0 = ar * 32 + ((acw ^ aswz) << 3);
    int a_off1 = (ar + 64) * 32 + ((acw ^ aswz) << 3);
    int b_off0 = br * 128 + (((bcw)     ^ (br & 7)) << 3);
    int b_off1 = br * 128 + (((bcw + 1) ^ (br & 7)) << 3);

    int lane = t & 31, w = t >> 5;
    int m0w = (w >> 1) * 32, nw = (w & 1) * 64;
    int lrow = (lane & 7) + (lane & 8);
    int lcol = (lane & 16) >> 1;

    float acc[2][8][4] = {};

    int nk = K / GBK;
#pragma unroll
    for (int s = 0; s < NSTG - 1; s++) {
        int k0 = s * GBK;
        CP16CG(&As[s * STG_A + a_off0], Ag + k0);
        CP16CG(&As[s * STG_A + a_off1], Ag + (size_t)64 * K + k0);
        CP16CG(&Bs[s * STG_B + b_off0], Bg + (size_t)k0 * N);
        CP16CG(&Bs[s * STG_B + b_off1], Bg + (size_t)k0 * N + 8);
        CP_COMMIT();
    }

    for (int i = 0; i < nk; i++) {
        if (i + 3 < nk)      { CP_WAIT(3); }
        else if (i + 2 < nk) { CP_WAIT(2); }
        else if (i + 1 < nk) { CP_WAIT(1); }
        else                 { CP_WAIT(0); }
        __syncthreads();
        if (i + NSTG - 1 < nk) {
            int st = (i + NSTG - 1) % NSTG;
            int k0 = (i + NSTG - 1) * GBK;
            CP16CG(&As[st * STG_A + a_off0], Ag + k0);
            CP16CG(&As[st * STG_A + a_off1], Ag + (size_t)64 * K + k0);
            CP16CG(&Bs[st * STG_B + b_off0], Bg + (size_t)k0 * N);
            CP16CG(&Bs[st * STG_B + b_off1], Bg + (size_t)k0 * N + 8);
            CP_COMMIT();
        }
        int cs = i % NSTG;
        const bf16* Asc = As + cs * STG_A;
        const bf16* Bsc = Bs + cs * STG_B;
#pragma unroll
        for (int kk = 0; kk < GBK; kk += 16) {
            uint32_t a[2][4], b[4][4];
#pragma unroll
            for (int mi = 0; mi < 2; mi++) {
                int R = m0w + mi * 16 + lrow;
                int cr = (kk + lcol) >> 3;
                ldm_x4(a[mi], Asc + R * 32 + ((cr ^ ((R >> 1) & 3)) << 3));
            }
#pragma unroll
            for (int nj = 0; nj < 4; nj++) {
                int Kr = kk + lrow;
                int cn = (nw + nj * 16 + lcol) >> 3;
                ldm_x4t(b[nj], Bsc + Kr * 128 + ((cn ^ (Kr & 7)) << 3));
            }
#pragma unroll
            for (int mi = 0; mi < 2; mi++) {
#pragma unroll
                for (int nt = 0; nt < 8; nt++)
                    MMA16816(acc[mi][nt], a[mi],
                             b[nt >> 1][(nt & 1) * 2], b[nt >> 1][(nt & 1) * 2 + 1]);
            }
        }
    }

#pragma unroll
    for (int mi = 0; mi < 2; mi++) {
        int rbase = m0 + m0w + mi * 16 + (lane >> 2);
#pragma unroll
        for (int h2 = 0; h2 < 2; h2++) {
            int row = rbase + 8 * h2;
            int orow = (EPI == 2) ? win_row_to_token(row) : row;
#pragma unroll
            for (int nt = 0; nt < 8; nt++) {
                int col = n0 + nw + nt * 8 + (lane & 3) * 2;
                float v0 = acc[mi][nt][2 * h2 + 0] + bias[col];
                float v1 = acc[mi][nt][2 * h2 + 1] + bias[col + 1];
                if (EPI == 1) {
                    v0 = 0.5f * v0 * (1.0f + erff(v0 * 0.7071067811865475f));
                    v1 = 0.5f * v1 * (1.0f + erff(v1 * 0.7071067811865475f));
                } else if (EPI == 2 || EPI == 3) {
                    const float* ap = add + (size_t)orow * N + col;
                    v0 += ap[0];
                    v1 += ap[1];
                }
                OutT* cp = C + (size_t)orow * N + col;
                if (sizeof(OutT) == 2) {
                    __nv_bfloat162 pk;
                    pk.x = __float2bfloat16(v0);
                    pk.y = __float2bfloat16(v1);
                    *(__nv_bfloat162*)cp = pk;
                } else {
                    float2 pk = make_float2(v0, v1);
                    *(float2*)cp = pk;
                }
            }
        }
    }
}

// ---------------- tensor-core window attention ----------------
__global__ void __launch_bounds__(256) attn_mma_kernel(
    const bf16* __restrict__ QKV, const bf16* __restrict__ bias_all,
    bf16* __restrict__ O)
{
    __shared__ __align__(16) bf16 sQ[2][64][40];
    __shared__ __align__(16) bf16 sK[2][64][40];
    __shared__ __align__(16) bf16 sV[2][64][40];
    __shared__ __align__(16) bf16 sB[2][64][72];

    int win = blockIdx.x, t = threadIdx.x;
    int widx = win & 63;
    int type = (((widx >> 3) == 7) ? 2 : 0) + (((widx & 7) == 7) ? 1 : 0);

    for (int i = t; i < 2 * 15 * 40; i += 256) {
        int hs = i / 600, rem = i % 600;
        int row = 49 + rem / 40, col = rem % 40;
        sK[hs][row][col] = __float2bfloat16(0.f);
        sV[hs][row][col] = __float2bfloat16(0.f);
    }

    int lane = t & 31, w = t >> 5;
    int hs = w >> 2, ww = w & 3;
    int r0 = ww * 16;
    int lrow = (lane & 7) + (lane & 8);
    int lcol = (lane & 16) >> 1;
    int qr = lane >> 2, qc = lane & 3;
    const float scale = 0.17677669529663687f;

    int lr = t >> 2, lc = t & 3;

    for (int p = 0; p < 6; p++) {
        __syncthreads();
        if (lr < 49) {
            const bf16* src = QKV + (size_t)(win * NTOK + lr) * QKVN + lc * 8;
#pragma unroll
            for (int hh = 0; hh < 2; hh++) {
                int h = p * 2 + hh;
                CP16CG(&sQ[hh][lr][lc * 8], src + h * HDIM);
                CP16CG(&sK[hh][lr][lc * 8], src + h * HDIM + CDIM);
                CP16CG(&sV[hh][lr][lc * 8], src + h * HDIM + 2 * CDIM);
            }
        }
#pragma unroll
        for (int hh = 0; hh < 2; hh++) {
            int h = p * 2 + hh;
            const bf16* bsrc = bias_all + (((size_t)type * NHEADS + h) * 64 + lr) * 64;
            CP16(&sB[hh][lr][lc * 8], bsrc + lc * 8);
            CP16(&sB[hh][lr][(lc + 4) * 8], bsrc + (lc + 4) * 8);
        }
        CP_COMMIT(); CP_WAIT(0);
        __syncthreads();

        float acc[8][4] = {};
#pragma unroll
        for (int kc = 0; kc < 32; kc += 16) {
            uint32_t a[4];
            ldm_x4(a, &sQ[hs][r0 + lrow][kc + lcol]);
            uint32_t bb[4][4];
#pragma unroll
            for (int nj = 0; nj < 4; nj++)
                ldm_x4(bb[nj], &sK[hs][nj * 16 + lrow][kc + lcol]);
#pragma unroll
            for (int nj = 0; nj < 4; nj++) {
                MMA16816(acc[nj * 2 + 0], a, bb[nj][0], bb[nj][2]);
                MMA16816(acc[nj * 2 + 1], a, bb[nj][1], bb[nj][3]);
            }
        }
#pragma unroll
        for (int cj = 0; cj < 4; cj++) {
            uint32_t bf[4];
            ldm_x4(bf, &sB[hs][r0 + lrow][cj * 16 + lcol]);
            float2 f0 = __bfloat1622float2(*(__nv_bfloat162*)&bf[0]);
            float2 f1 = __bfloat1622float2(*(__nv_bfloat162*)&bf[1]);
            float2 f2 = __bfloat1622float2(*(__nv_bfloat162*)&bf[2]);
            float2 f3 = __bfloat1622float2(*(__nv_bfloat162*)&bf[3]);
            acc[2 * cj][0] = acc[2 * cj][0] * scale + f0.x;
            acc[2 * cj][1] = acc[2 * cj][1] * scale + f0.y;
            acc[2 * cj][2] = acc[2 * cj][2] * scale + f1.x;
            acc[2 * cj][3] = acc[2 * cj][3] * scale + f1.y;
            acc[2 * cj + 1][0] = acc[2 * cj + 1][0] * scale + f2.x;
            acc[2 * cj + 1][1] = acc[2 * cj + 1][1] * scale + f2.y;
            acc[2 * cj + 1][2] = acc[2 * cj + 1][2] * scale + f3.x;
            acc[2 * cj + 1][3] = acc[2 * cj + 1][3] * scale + f3.y;
        }
        float mx1 = -1e30f, mx2 = -1e30f;
#pragma unroll
        for (int nt = 0; nt < 8; nt++) {
            mx1 = fmaxf(mx1, fmaxf(acc[nt][0], acc[nt][1]));
            mx2 = fmaxf(mx2, fmaxf(acc[nt][2], acc[nt][3]));
        }
        mx1 = fmaxf(mx1, __shfl_xor_sync(0xffffffffu, mx1, 1));
        mx1 = fmaxf(mx1, __shfl_xor_sync(0xffffffffu, mx1, 2));
        mx2 = fmaxf(mx2, __shfl_xor_sync(0xffffffffu, mx2, 1));
        mx2 = fmaxf(mx2, __shfl_xor_sync(0xffffffffu, mx2, 2));
        float sum1 = 0.f, sum2 = 0.f;
#pragma unroll
        for (int nt = 0; nt < 8; nt++) {
            acc[nt][0] = __expf(acc[nt][0] - mx1);
            acc[nt][1] = __expf(acc[nt][1] - mx1);
            acc[nt][2] = __expf(acc[nt][2] - mx2);
            acc[nt][3] = __expf(acc[nt][3] - mx2);
            sum1 += acc[nt][0] + acc[nt][1];
            sum2 += acc[nt][2] + acc[nt][3];
        }
        sum1 += __shfl_xor_sync(0xffffffffu, sum1, 1);
        sum1 += __shfl_xor_sync(0xffffffffu, sum1, 2);
        sum2 += __shfl_xor_sync(0xffffffffu, sum2, 1);
        sum2 += __shfl_xor_sync(0xffffffffu, sum2, 2);
        float inv1 = 1.0f / sum1, inv2 = 1.0f / sum2;

        float o[4][4] = {};
#pragma unroll
        for (int kc2 = 0; kc2 < 4; kc2++) {
            uint32_t pa[4];
            pa[0] = packbf(acc[2 * kc2][0],     acc[2 * kc2][1]);
            pa[1] = packbf(acc[2 * kc2][2],     acc[2 * kc2][3]);
            pa[2] = packbf(acc[2 * kc2 + 1][0], acc[2 * kc2 + 1][1]);
            pa[3] = packbf(acc[2 * kc2 + 1][2], acc[2 * kc2 + 1][3]);
#pragma unroll
            for (int nj = 0; nj < 2; nj++) {
                uint32_t vb[4];
                ldm_x4t(vb, &sV[hs][kc2 * 16 + lrow][nj * 16 + lcol]);
                MMA16816(o[nj * 2 + 0], pa, vb[0], vb[1]);
                MMA16816(o[nj * 2 + 1], pa, vb[2], vb[3]);
            }
        }
        int H = p * 2 + hs;
        int row1 = r0 + qr, row2 = r0 + qr + 8;
        if (row1 < NTOK) {
            bf16* dst = O + (size_t)(win * NTOK + row1) * CDIM + H * HDIM + qc * 2;
#pragma unroll
            for (int nt = 0; nt < 4; nt++) {
                __nv_bfloat162 pk;
                pk.x = __float2bfloat16(o[nt][0] * inv1);
                pk.y = __float2bfloat16(o[nt][1] * inv1);
                *(__nv_bfloat162*)(dst + nt * 8) = pk;
            }
        }
        if (row2 < NTOK) {
            bf16* dst = O + (size_t)(win * NTOK + row2) * CDIM + H * HDIM + qc * 2;
#pragma unroll
            for (int nt = 0; nt < 4; nt++) {
                __nv_bfloat162 pk;
                pk.x = __float2bfloat16(o[nt][2] * inv2);
                pk.y = __float2bfloat16(o[nt][3] * inv2);
                *(__nv_bfloat162*)(dst + nt * 8) = pk;
            }
        }
    }
}

// ---------------- launch ----------------
extern "C" void kernel_launch(void* const* d_in, const int* in_sizes, int n_in,
                              void* d_out, int out_size)
{
    const float* hidden  = (const float*)d_in[0];
    const float* ln1_g   = (const float*)d_in[1];
    const float* ln1_b   = (const float*)d_in[2];
    const float* q_w     = (const float*)d_in[3];
    const float* q_b     = (const float*)d_in[4];
    const float* k_w     = (const float*)d_in[5];
    const float* k_b     = (const float*)d_in[6];
    const float* v_w     = (const float*)d_in[7];
    const float* v_b     = (const float*)d_in[8];
    const float* rpb     = (const float*)d_in[9];
    const int*   rpi     = (const int*)  d_in[10];
    const float* proj_w  = (const float*)d_in[11];
    const float* proj_b  = (const float*)d_in[12];
    const float* ln2_g   = (const float*)d_in[13];
    const float* ln2_b   = (const float*)d_in[14];
    const float* fc1_w   = (const float*)d_in[15];
    const float* fc1_b   = (const float*)d_in[16];
    const float* fc2_w   = (const float*)d_in[17];
    const float* fc2_b   = (const float*)d_in[18];
    float* out = (float*)d_out;

    bf16 *p_xw, *p_qkv, *p_ctx, *p_ln2, *p_y1;
    bf16 *p_wqkv, *p_wp, *p_w1, *p_w2, *p_bias;
    float *p_h, *p_bqkv;
    cudaGetSymbolAddress((void**)&p_xw,   g_xw);
    cudaGetSymbolAddress((void**)&p_qkv,  g_qkv);
    cudaGetSymbolAddress((void**)&p_ctx,  g_ctx);
    cudaGetSymbolAddress((void**)&p_h,    g_h);
    cudaGetSymbolAddress((void**)&p_ln2,  g_ln2);
    cudaGetSymbolAddress((void**)&p_y1,   g_y1);
    cudaGetSymbolAddress((void**)&p_wqkv, g_wqkv);
    cudaGetSymbolAddress((void**)&p_bqkv, g_bqkv);
    cudaGetSymbolAddress((void**)&p_wp,   g_wp);
    cudaGetSymbolAddress((void**)&p_w1,   g_w1);
    cudaGetSymbolAddress((void**)&p_w2,   g_w2);
    cudaGetSymbolAddress((void**)&p_bias, g_bias);

    cudaFuncSetAttribute(mma_gemm<0, bf16>,  cudaFuncAttributeMaxDynamicSharedMemorySize, TCSMEM);
    cudaFuncSetAttribute(mma_gemm<1, bf16>,  cudaFuncAttributeMaxDynamicSharedMemorySize, TCSMEM);
    cudaFuncSetAttribute(mma_gemm<2, float>, cudaFuncAttributeMaxDynamicSharedMemorySize, TCSMEM);
    cudaFuncSetAttribute(mma_gemm<3, float>, cudaFuncAttributeMaxDynamicSharedMemorySize, TCSMEM);

    // 0) fused prep: pack qkv + convert weights + bias tiles (one launch)
    prep_kernel<<<PREP_BLOCKS, 256>>>(
        q_w, k_w, v_w, q_b, k_b, v_b, p_wqkv, p_bqkv,
        proj_w, p_wp, fc1_w, p_w1, fc2_w, p_w2,
        rpb, rpi, p_bias);

    // 1) LN1 + shift-roll + window partition (gather)
    ln_kernel<<<MTOK / 8, 256>>>(hidden, ln1_g, ln1_b, p_xw, 1);

    // 2) fused QKV projection
    mma_gemm<0, bf16><<<dim3(QKVN / GBN, MTOK / GBM), 256, TCSMEM>>>(
        p_xw, p_wqkv, p_bqkv, nullptr, p_qkv, MTOK, QKVN, CDIM);

    // 3) windowed attention (tensor cores)
    attn_mma_kernel<<<TOTWIN, 256>>>(p_qkv, p_bias, p_ctx);

    // 4) output projection + window-reverse + roll-back + residual (scatter)
    mma_gemm<2, float><<<dim3(CDIM / GBN, MTOK / GBM), 256, TCSMEM>>>(
        p_ctx, p_wp, proj_b, hidden, p_h, MTOK, CDIM, CDIM);

    // 5) LN2
    ln_kernel<<<MTOK / 8, 256>>>(p_h, ln2_g, ln2_b, p_ln2, 0);

    // 6) fc1 + exact GELU
    mma_gemm<1, bf16><<<dim3(FFNDIM / GBN, MTOK / GBM), 256, TCSMEM>>>(
        p_ln2, p_w1, fc1_b, nullptr, p_y1, MTOK, FFNDIM, CDIM);

    // 7) fc2 + residual -> final output
    mma_gemm<3, float><<<dim3(CDIM / GBN, MTOK / GBM), 256, TCSMEM>>>(
        p_y1, p_w2, fc2_b, p_h, out, MTOK, CDIM, FFNDIM);
}

// round 12
// speedup vs baseline: 1.5676x; 1.0103x over previous
#include <cuda_runtime.h>
#include <cuda_bf16.h>
#include <math.h>
#include <stdint.h>

// ---------------- problem constants ----------------
#define BATCH   8
#define HIMG    56
#define WIMG    56
#define CDIM    384
#define NHEADS  12
#define HDIM    32
#define WIN     7
#define NTOK    49
#define SHIFT_S 3
#define TOTWIN  512
#define MTOK    25088
#define FFNDIM  1536
#define QKVN    1152          // 3*CDIM

typedef __nv_bfloat16 bf16;

// ---------------- scratch (device globals; allocation-free) ----------------
__device__ bf16  g_xw  [MTOK * CDIM];
__device__ bf16  g_qkv [MTOK * QKVN];
__device__ bf16  g_ctx [MTOK * CDIM];
__device__ float g_h   [MTOK * CDIM];
__device__ bf16  g_ln2 [MTOK * CDIM];
__device__ bf16  g_y1  [MTOK * FFNDIM];
__device__ bf16  g_wqkv[CDIM * QKVN];   // [K][N] packed q|k|v
__device__ float g_bqkv[QKVN];
__device__ bf16  g_wp  [CDIM * CDIM];
__device__ bf16  g_w1  [CDIM * FFNDIM];
__device__ bf16  g_w2  [FFNDIM * CDIM];
__device__ bf16  g_bias[4 * NHEADS * 64 * 64];

// windowed row r <-> original token t (same map both directions)
__device__ __forceinline__ int win_row_to_token(int r) {
    int b    = r / (HIMG * WIMG);
    int rem  = r - b * (HIMG * WIMG);
    int widx = rem / NTOK;
    int tok  = rem - widx * NTOK;
    int wi = widx >> 3, wj = widx & 7;
    int i = tok / WIN, j = tok - i * WIN;
    int sh = wi * WIN + i + SHIFT_S; if (sh >= HIMG) sh -= HIMG;
    int sw = wj * WIN + j + SHIFT_S; if (sw >= WIMG) sw -= WIMG;
    return b * (HIMG * WIMG) + sh * WIMG + sw;
}

// ---------------- fused prep: pack qkv | convert weights | bias tiles ------
#define W_PROJ4 (CDIM * CDIM / 4)          // 36864
#define W_FFN4  (CDIM * FFNDIM / 4)        // 147456
#define QKV_W4  (CDIM * QKVN / 4)          // 110592
#define PREP_QKV_ITEMS  (QKV_W4 + QKVN / 4)
#define PREP_W_ITEMS    (W_PROJ4 + 2 * W_FFN4)
#define PREP_QKV_BLOCKS ((PREP_QKV_ITEMS + 255) / 256)
#define PREP_W_BLOCKS   ((PREP_W_ITEMS + 255) / 256)
#define PREP_BIAS_BLOCKS 48
#define PREP_BLOCKS (PREP_QKV_BLOCKS + PREP_W_BLOCKS + PREP_BIAS_BLOCKS)

__global__ void __launch_bounds__(256) prep_kernel(
    const float* __restrict__ qw, const float* __restrict__ kw,
    const float* __restrict__ vw, const float* __restrict__ qb,
    const float* __restrict__ kb, const float* __restrict__ vb,
    bf16* __restrict__ wqkv, float* __restrict__ bqkv,
    const float* __restrict__ pw, bf16* __restrict__ wp,
    const float* __restrict__ w1s, bf16* __restrict__ w1,
    const float* __restrict__ w2s, bf16* __restrict__ w2,
    const float* __restrict__ rpb, const int* __restrict__ rpi,
    bf16* __restrict__ bias_out)
{
    int blk = blockIdx.x;
    if (blk < PREP_QKV_BLOCKS) {
        int i = blk * 256 + threadIdx.x;
        if (i < QKV_W4) {
            int row = i / (QKVN / 4);
            int col = (i % (QKVN / 4)) * 4;
            const float* src = (col < CDIM) ? qw : (col < 2 * CDIM ? kw : vw);
            int c = col - (col < CDIM ? 0 : (col < 2 * CDIM ? CDIM : 2 * CDIM));
            float4 v = *(const float4*)(src + (size_t)row * CDIM + c);
            bf16 o[4] = {__float2bfloat16(v.x), __float2bfloat16(v.y),
                         __float2bfloat16(v.z), __float2bfloat16(v.w)};
            *(uint64_t*)(wqkv + (size_t)i * 4) = *(uint64_t*)o;
        } else if (i < PREP_QKV_ITEMS) {
            int col = (i - QKV_W4) * 4;
            const float* src = (col < CDIM) ? qb : (col < 2 * CDIM ? kb : vb);
            int c = col - (col < CDIM ? 0 : (col < 2 * CDIM ? CDIM : 2 * CDIM));
            *(float4*)(bqkv + col) = *(const float4*)(src + c);
        }
    } else if (blk < PREP_QKV_BLOCKS + PREP_W_BLOCKS) {
        int i = (blk - PREP_QKV_BLOCKS) * 256 + threadIdx.x;
        const float* src; bf16* dst; int idx;
        if (i < W_PROJ4)                 { src = pw;  dst = wp; idx = i; }
        else if (i < W_PROJ4 + W_FFN4)   { src = w1s; dst = w1; idx = i - W_PROJ4; }
        else if (i < PREP_W_ITEMS)       { src = w2s; dst = w2; idx = i - W_PROJ4 - W_FFN4; }
        else return;
        float4 v = ((const float4*)src)[idx];
        bf16 o[4] = {__float2bfloat16(v.x), __float2bfloat16(v.y),
                     __float2bfloat16(v.z), __float2bfloat16(v.w)};
        *(uint64_t*)(dst + (size_t)idx * 4) = *(uint64_t*)o;
    } else {
        int bb = blk - PREP_QKV_BLOCKS - PREP_W_BLOCKS;   // 0..47
        int type = bb / NHEADS, h = bb % NHEADS;
        for (int idx = threadIdx.x; idx < 64 * 64; idx += 256) {
            int n = idx >> 6, m = idx & 63;
            float v;
            if (m >= 49)      v = -1e30f;
            else if (n >= 49) v = 0.f;
            else {
                v = rpb[rpi[n * 49 + m] * NHEADS + h];
                int ni = n / 7, nj = n % 7, mi = m / 7, mj = m % 7;
                int cn = ((type & 2) ? (ni < 4 ? 1 : 2) : 0) * 3 + ((type & 1) ? (nj < 4 ? 1 : 2) : 0);
                int cm = ((type & 2) ? (mi < 4 ? 1 : 2) : 0) * 3 + ((type & 1) ? (mj < 4 ? 1 : 2) : 0);
                if (cn != cm) v -= 100.0f;
            }
            bias_out[(((size_t)type * NHEADS + h) * 64 + n) * 64 + m] = __float2bfloat16(v);
        }
    }
}

// ---------------- LayerNorm: warp-per-row, no barriers ----------------
__global__ void __launch_bounds__(256) ln_kernel(
    const float* __restrict__ x, const float* __restrict__ g,
    const float* __restrict__ b, bf16* __restrict__ out, int permute)
{
    int r = blockIdx.x * 8 + (threadIdx.x >> 5);
    int lane = threadIdx.x & 31;
    int t = permute ? win_row_to_token(r) : r;
    const float4* xi = (const float4*)(x + (size_t)t * CDIM);

    float4 v[3];
    float s = 0.f, ss = 0.f;
#pragma unroll
    for (int j = 0; j < 3; j++) {
        v[j] = xi[lane + 32 * j];
        s  += v[j].x + v[j].y + v[j].z + v[j].w;
        ss += v[j].x * v[j].x + v[j].y * v[j].y
            + v[j].z * v[j].z + v[j].w * v[j].w;
    }
#pragma unroll
    for (int o = 16; o; o >>= 1) {
        s  += __shfl_xor_sync(0xffffffffu, s,  o);
        ss += __shfl_xor_sync(0xffffffffu, ss, o);
    }
    float mu = s * (1.0f / CDIM);
    float var = ss * (1.0f / CDIM) - mu * mu;
    float rstd = rsqrtf(var + 1e-5f);

    bf16* yo = out + (size_t)r * CDIM;
#pragma unroll
    for (int j = 0; j < 3; j++) {
        int c = (lane + 32 * j) * 4;
        float4 gg = *(const float4*)(g + c);
        float4 bb = *(const float4*)(b + c);
        bf16 o[4];
        o[0] = __float2bfloat16((v[j].x - mu) * rstd * gg.x + bb.x);
        o[1] = __float2bfloat16((v[j].y - mu) * rstd * gg.y + bb.y);
        o[2] = __float2bfloat16((v[j].z - mu) * rstd * gg.z + bb.z);
        o[3] = __float2bfloat16((v[j].w - mu) * rstd * gg.w + bb.w);
        *(uint64_t*)(yo + c) = *(uint64_t*)o;
    }
}

// ---------------- mma helpers ----------------
#define CP16(dst, src) \
    asm volatile("cp.async.ca.shared.global [%0], [%1], 16;\n" :: \
        "r"((uint32_t)__cvta_generic_to_shared(dst)), "l"(src))
#define CP16CG(dst, src) \
    asm volatile("cp.async.cg.shared.global [%0], [%1], 16;\n" :: \
        "r"((uint32_t)__cvta_generic_to_shared(dst)), "l"(src))
#define CP_COMMIT()  asm volatile("cp.async.commit_group;\n" ::)
#define CP_WAIT(n)   asm volatile("cp.async.wait_group %0;\n" :: "n"(n))

__device__ __forceinline__ void ldm_x4(uint32_t* r, const void* p) {
    uint32_t a = (uint32_t)__cvta_generic_to_shared(p);
    asm volatile("ldmatrix.sync.aligned.m8n8.x4.shared.b16 {%0,%1,%2,%3},[%4];"
        : "=r"(r[0]), "=r"(r[1]), "=r"(r[2]), "=r"(r[3]) : "r"(a));
}
__device__ __forceinline__ void ldm_x4t(uint32_t* r, const void* p) {
    uint32_t a = (uint32_t)__cvta_generic_to_shared(p);
    asm volatile("ldmatrix.sync.aligned.m8n8.x4.trans.shared.b16 {%0,%1,%2,%3},[%4];"
        : "=r"(r[0]), "=r"(r[1]), "=r"(r[2]), "=r"(r[3]) : "r"(a));
}
#define MMA16816(d, a, b0, b1) \
    asm volatile("mma.sync.aligned.m16n8k16.row.col.f32.bf16.bf16.f32 " \
        "{%0,%1,%2,%3},{%4,%5,%6,%7},{%8,%9},{%0,%1,%2,%3};" \
        : "+f"(d[0]), "+f"(d[1]), "+f"(d[2]), "+f"(d[3]) \
        : "r"(a[0]), "r"(a[1]), "r"(a[2]), "r"(a[3]), "r"(b0), "r"(b1))

__device__ __forceinline__ uint32_t packbf(float lo, float hi) {
    __nv_bfloat162 h = __floats2bfloat162_rn(lo, hi);
    return *(uint32_t*)&h;
}

// ---------------- HMMA bf16 GEMM, 128x128x32, 5-stage, XOR-swizzled --------
// EPI 0: store  1: exact GELU  2: scatter+residual  3: residual
#define GBM 128
#define GBN 128
#define GBK 32
#define NSTG 5
#define STG_A (GBM * GBK)
#define STG_B (GBK * GBN)
#define TCSMEM (NSTG * (STG_A + STG_B) * 2)   // 81920 bytes

template <int EPI, typename OutT>
__global__ void __launch_bounds__(256) mma_gemm(
    const bf16* __restrict__ A, const bf16* __restrict__ B,
    const float* __restrict__ bias, const float* __restrict__ add,
    OutT* __restrict__ C, int M, int N, int K)
{
    extern __shared__ __align__(16) bf16 sm[];
    bf16* As = sm;
    bf16* Bs = sm + NSTG * STG_A;

    int t = threadIdx.x;
    int m0 = blockIdx.y * GBM, n0 = blockIdx.x * GBN;

    int ar = t >> 2, acw = t & 3;
    int br = t >> 3, bcw = (t & 7) * 2;
    const bf16* Ag = A + (size_t)(m0 + ar) * K + acw * 8;
    const bf16* Bg = B + (size_t)br * N + n0 + bcw * 8;

    int aswz = (ar >> 1) & 3;
    int a_off0 = ar * 32 + ((acw ^ aswz) << 3);
    int a_off1 = (ar + 64) * 32 + ((acw ^ aswz) << 3);
    int b_off0 = br * 128 + (((bcw)     ^ (br & 7)) << 3);
    int b_off1 = br * 128 + (((bcw + 1) ^ (br & 7)) << 3);

    int lane = t & 31, w = t >> 5;
    int m0w = (w >> 1) * 32, nw = (w & 1) * 64;
    int lrow = (lane & 7) + (lane & 8);
    int lcol = (lane & 16) >> 1;

    float acc[2][8][4] = {};

    int nk = K / GBK;
#pragma unroll
    for (int s = 0; s < NSTG - 1; s++) {
        int k0 = s * GBK;
        CP16CG(&As[s * STG_A + a_off0], Ag + k0);
        CP16CG(&As[s * STG_A + a_off1], Ag + (size_t)64 * K + k0);
        CP16CG(&Bs[s * STG_B + b_off0], Bg + (size_t)k0 * N);
        CP16CG(&Bs[s * STG_B + b_off1], Bg + (size_t)k0 * N + 8);
        CP_COMMIT();
    }

    for (int i = 0; i < nk; i++) {
        if (i + 3 < nk)      { CP_WAIT(3); }
        else if (i + 2 < nk) { CP_WAIT(2); }
        else if (i + 1 < nk) { CP_WAIT(1); }
        else                 { CP_WAIT(0); }
        __syncthreads();
        if (i + NSTG - 1 < nk) {
            int st = (i + NSTG - 1) % NSTG;
            int k0 = (i + NSTG - 1) * GBK;
            CP16CG(&As[st * STG_A + a_off0], Ag + k0);
            CP16CG(&As[st * STG_A + a_off1], Ag + (size_t)64 * K + k0);
            CP16CG(&Bs[st * STG_B + b_off0], Bg + (size_t)k0 * N);
            CP16CG(&Bs[st * STG_B + b_off1], Bg + (size_t)k0 * N + 8);
            CP_COMMIT();
        }
        int cs = i % NSTG;
        const bf16* Asc = As + cs * STG_A;
        const bf16* Bsc = Bs + cs * STG_B;
#pragma unroll
        for (int kk = 0; kk < GBK; kk += 16) {
            uint32_t a[2][4], b[4][4];
#pragma unroll
            for (int mi = 0; mi < 2; mi++) {
                int R = m0w + mi * 16 + lrow;
                int cr = (kk + lcol) >> 3;
                ldm_x4(a[mi], Asc + R * 32 + ((cr ^ ((R >> 1) & 3)) << 3));
            }
#pragma unroll
            for (int nj = 0; nj < 4; nj++) {
                int Kr = kk + lrow;
                int cn = (nw + nj * 16 + lcol) >> 3;
                ldm_x4t(b[nj], Bsc + Kr * 128 + ((cn ^ (Kr & 7)) << 3));
            }
#pragma unroll
            for (int mi = 0; mi < 2; mi++) {
#pragma unroll
                for (int nt = 0; nt < 8; nt++)
                    MMA16816(acc[mi][nt], a[mi],
                             b[nt >> 1][(nt & 1) * 2], b[nt >> 1][(nt & 1) * 2 + 1]);
            }
        }
    }

#pragma unroll
    for (int mi = 0; mi < 2; mi++) {
        int rbase = m0 + m0w + mi * 16 + (lane >> 2);
#pragma unroll
        for (int h2 = 0; h2 < 2; h2++) {
            int row = rbase + 8 * h2;
            int orow = (EPI == 2) ? win_row_to_token(row) : row;
#pragma unroll
            for (int nt = 0; nt < 8; nt++) {
                int col = n0 + nw + nt * 8 + (lane & 3) * 2;
                float v0 = acc[mi][nt][2 * h2 + 0] + bias[col];
                float v1 = acc[mi][nt][2 * h2 + 1] + bias[col + 1];
                if (EPI == 1) {
                    v0 = 0.5f * v0 * (1.0f + erff(v0 * 0.7071067811865475f));
                    v1 = 0.5f * v1 * (1.0f + erff(v1 * 0.7071067811865475f));
                } else if (EPI == 2 || EPI == 3) {
                    const float* ap = add + (size_t)orow * N + col;
                    v0 += ap[0];
                    v1 += ap[1];
                }
                OutT* cp = C + (size_t)orow * N + col;
                if (sizeof(OutT) == 2) {
                    __nv_bfloat162 pk;
                    pk.x = __float2bfloat16(v0);
                    pk.y = __float2bfloat16(v1);
                    *(__nv_bfloat162*)cp = pk;
                } else {
                    float2 pk = make_float2(v0, v1);
                    *(float2*)cp = pk;
                }
            }
        }
    }
}

// ---------------- tensor-core window attention ----------------
// grid (TOTWIN, 6): one block per (window, head-pair). No pass loop.
__global__ void __launch_bounds__(256) attn_mma_kernel(
    const bf16* __restrict__ QKV, const bf16* __restrict__ bias_all,
    bf16* __restrict__ O)
{
    __shared__ __align__(16) bf16 sQ[2][64][40];
    __shared__ __align__(16) bf16 sK[2][64][40];
    __shared__ __align__(16) bf16 sV[2][64][40];
    __shared__ __align__(16) bf16 sB[2][64][72];

    int win = blockIdx.x, p = blockIdx.y, t = threadIdx.x;
    int widx = win & 63;
    int type = (((widx >> 3) == 7) ? 2 : 0) + (((widx & 7) == 7) ? 1 : 0);

    // zero K,V pad rows (49..63)
    for (int i = t; i < 2 * 15 * 40; i += 256) {
        int hz = i / 600, rem = i % 600;
        int row = 49 + rem / 40, col = rem % 40;
        sK[hz][row][col] = __float2bfloat16(0.f);
        sV[hz][row][col] = __float2bfloat16(0.f);
    }

    int lane = t & 31, w = t >> 5;
    int hs = w >> 2, ww = w & 3;
    int r0 = ww * 16;
    int lrow = (lane & 7) + (lane & 8);
    int lcol = (lane & 16) >> 1;
    int qr = lane >> 2, qc = lane & 3;
    const float scale = 0.17677669529663687f;

    int lr = t >> 2, lc = t & 3;

    // loads: 2 heads of Q,K,V + bias tiles
    if (lr < 49) {
        const bf16* src = QKV + (size_t)(win * NTOK + lr) * QKVN + lc * 8;
#pragma unroll
        for (int hh = 0; hh < 2; hh++) {
            int h = p * 2 + hh;
            CP16CG(&sQ[hh][lr][lc * 8], src + h * HDIM);
            CP16CG(&sK[hh][lr][lc * 8], src + h * HDIM + CDIM);
            CP16CG(&sV[hh][lr][lc * 8], src + h * HDIM + 2 * CDIM);
        }
    }
#pragma unroll
    for (int hh = 0; hh < 2; hh++) {
        int h = p * 2 + hh;
        const bf16* bsrc = bias_all + (((size_t)type * NHEADS + h) * 64 + lr) * 64;
        CP16(&sB[hh][lr][lc * 8], bsrc + lc * 8);
        CP16(&sB[hh][lr][(lc + 4) * 8], bsrc + (lc + 4) * 8);
    }
    CP_COMMIT(); CP_WAIT(0);
    __syncthreads();

    // S = Q K^T
    float acc[8][4] = {};
#pragma unroll
    for (int kc = 0; kc < 32; kc += 16) {
        uint32_t a[4];
        ldm_x4(a, &sQ[hs][r0 + lrow][kc + lcol]);
        uint32_t bb[4][4];
#pragma unroll
        for (int nj = 0; nj < 4; nj++)
            ldm_x4(bb[nj], &sK[hs][nj * 16 + lrow][kc + lcol]);
#pragma unroll
        for (int nj = 0; nj < 4; nj++) {
            MMA16816(acc[nj * 2 + 0], a, bb[nj][0], bb[nj][2]);
            MMA16816(acc[nj * 2 + 1], a, bb[nj][1], bb[nj][3]);
        }
    }
    // scale + bias
#pragma unroll
    for (int cj = 0; cj < 4; cj++) {
        uint32_t bf[4];
        ldm_x4(bf, &sB[hs][r0 + lrow][cj * 16 + lcol]);
        float2 f0 = __bfloat1622float2(*(__nv_bfloat162*)&bf[0]);
        float2 f1 = __bfloat1622float2(*(__nv_bfloat162*)&bf[1]);
        float2 f2 = __bfloat1622float2(*(__nv_bfloat162*)&bf[2]);
        float2 f3 = __bfloat1622float2(*(__nv_bfloat162*)&bf[3]);
        acc[2 * cj][0] = acc[2 * cj][0] * scale + f0.x;
        acc[2 * cj][1] = acc[2 * cj][1] * scale + f0.y;
        acc[2 * cj][2] = acc[2 * cj][2] * scale + f1.x;
        acc[2 * cj][3] = acc[2 * cj][3] * scale + f1.y;
        acc[2 * cj + 1][0] = acc[2 * cj + 1][0] * scale + f2.x;
        acc[2 * cj + 1][1] = acc[2 * cj + 1][1] * scale + f2.y;
        acc[2 * cj + 1][2] = acc[2 * cj + 1][2] * scale + f3.x;
        acc[2 * cj + 1][3] = acc[2 * cj + 1][3] * scale + f3.y;
    }
    // softmax
    float mx1 = -1e30f, mx2 = -1e30f;
#pragma unroll
    for (int nt = 0; nt < 8; nt++) {
        mx1 = fmaxf(mx1, fmaxf(acc[nt][0], acc[nt][1]));
        mx2 = fmaxf(mx2, fmaxf(acc[nt][2], acc[nt][3]));
    }
    mx1 = fmaxf(mx1, __shfl_xor_sync(0xffffffffu, mx1, 1));
    mx1 = fmaxf(mx1, __shfl_xor_sync(0xffffffffu, mx1, 2));
    mx2 = fmaxf(mx2, __shfl_xor_sync(0xffffffffu, mx2, 1));
    mx2 = fmaxf(mx2, __shfl_xor_sync(0xffffffffu, mx2, 2));
    float sum1 = 0.f, sum2 = 0.f;
#pragma unroll
    for (int nt = 0; nt < 8; nt++) {
        acc[nt][0] = __expf(acc[nt][0] - mx1);
        acc[nt][1] = __expf(acc[nt][1] - mx1);
        acc[nt][2] = __expf(acc[nt][2] - mx2);
        acc[nt][3] = __expf(acc[nt][3] - mx2);
        sum1 += acc[nt][0] + acc[nt][1];
        sum2 += acc[nt][2] + acc[nt][3];
    }
    sum1 += __shfl_xor_sync(0xffffffffu, sum1, 1);
    sum1 += __shfl_xor_sync(0xffffffffu, sum1, 2);
    sum2 += __shfl_xor_sync(0xffffffffu, sum2, 1);
    sum2 += __shfl_xor_sync(0xffffffffu, sum2, 2);
    float inv1 = 1.0f / sum1, inv2 = 1.0f / sum2;

    // ctx = P V
    float o[4][4] = {};
#pragma unroll
    for (int kc2 = 0; kc2 < 4; kc2++) {
        uint32_t pa[4];
        pa[0] = packbf(acc[2 * kc2][0],     acc[2 * kc2][1]);
        pa[1] = packbf(acc[2 * kc2][2],     acc[2 * kc2][3]);
        pa[2] = packbf(acc[2 * kc2 + 1][0], acc[2 * kc2 + 1][1]);
        pa[3] = packbf(acc[2 * kc2 + 1][2], acc[2 * kc2 + 1][3]);
#pragma unroll
        for (int nj = 0; nj < 2; nj++) {
            uint32_t vb[4];
            ldm_x4t(vb, &sV[hs][kc2 * 16 + lrow][nj * 16 + lcol]);
            MMA16816(o[nj * 2 + 0], pa, vb[0], vb[1]);
            MMA16816(o[nj * 2 + 1], pa, vb[2], vb[3]);
        }
    }
    int H = p * 2 + hs;
    int row1 = r0 + qr, row2 = r0 + qr + 8;
    if (row1 < NTOK) {
        bf16* dst = O + (size_t)(win * NTOK + row1) * CDIM + H * HDIM + qc * 2;
#pragma unroll
        for (int nt = 0; nt < 4; nt++) {
            __nv_bfloat162 pk;
            pk.x = __float2bfloat16(o[nt][0] * inv1);
            pk.y = __float2bfloat16(o[nt][1] * inv1);
            *(__nv_bfloat162*)(dst + nt * 8) = pk;
        }
    }
    if (row2 < NTOK) {
        bf16* dst = O + (size_t)(win * NTOK + row2) * CDIM + H * HDIM + qc * 2;
#pragma unroll
        for (int nt = 0; nt < 4; nt++) {
            __nv_bfloat162 pk;
            pk.x = __float2bfloat16(o[nt][2] * inv2);
            pk.y = __float2bfloat16(o[nt][3] * inv2);
            *(__nv_bfloat162*)(dst + nt * 8) = pk;
        }
    }
}

// ---------------- launch ----------------
extern "C" void kernel_launch(void* const* d_in, const int* in_sizes, int n_in,
                              void* d_out, int out_size)
{
    const float* hidden  = (const float*)d_in[0];
    const float* ln1_g   = (const float*)d_in[1];
    const float* ln1_b   = (const float*)d_in[2];
    const float* q_w     = (const float*)d_in[3];
    const float* q_b     = (const float*)d_in[4];
    const float* k_w     = (const float*)d_in[5];
    const float* k_b     = (const float*)d_in[6];
    const float* v_w     = (const float*)d_in[7];
    const float* v_b     = (const float*)d_in[8];
    const float* rpb     = (const float*)d_in[9];
    const int*   rpi     = (const int*)  d_in[10];
    const float* proj_w  = (const float*)d_in[11];
    const float* proj_b  = (const float*)d_in[12];
    const float* ln2_g   = (const float*)d_in[13];
    const float* ln2_b   = (const float*)d_in[14];
    const float* fc1_w   = (const float*)d_in[15];
    const float* fc1_b   = (const float*)d_in[16];
    const float* fc2_w   = (const float*)d_in[17];
    const float* fc2_b   = (const float*)d_in[18];
    float* out = (float*)d_out;

    bf16 *p_xw, *p_qkv, *p_ctx, *p_ln2, *p_y1;
    bf16 *p_wqkv, *p_wp, *p_w1, *p_w2, *p_bias;
    float *p_h, *p_bqkv;
    cudaGetSymbolAddress((void**)&p_xw,   g_xw);
    cudaGetSymbolAddress((void**)&p_qkv,  g_qkv);
    cudaGetSymbolAddress((void**)&p_ctx,  g_ctx);
    cudaGetSymbolAddress((void**)&p_h,    g_h);
    cudaGetSymbolAddress((void**)&p_ln2,  g_ln2);
    cudaGetSymbolAddress((void**)&p_y1,   g_y1);
    cudaGetSymbolAddress((void**)&p_wqkv, g_wqkv);
    cudaGetSymbolAddress((void**)&p_bqkv, g_bqkv);
    cudaGetSymbolAddress((void**)&p_wp,   g_wp);
    cudaGetSymbolAddress((void**)&p_w1,   g_w1);
    cudaGetSymbolAddress((void**)&p_w2,   g_w2);
    cudaGetSymbolAddress((void**)&p_bias, g_bias);

    cudaFuncSetAttribute(mma_gemm<0, bf16>,  cudaFuncAttributeMaxDynamicSharedMemorySize, TCSMEM);
    cudaFuncSetAttribute(mma_gemm<1, bf16>,  cudaFuncAttributeMaxDynamicSharedMemorySize, TCSMEM);
    cudaFuncSetAttribute(mma_gemm<2, float>, cudaFuncAttributeMaxDynamicSharedMemorySize, TCSMEM);
    cudaFuncSetAttribute(mma_gemm<3, float>, cudaFuncAttributeMaxDynamicSharedMemorySize, TCSMEM);

    // 0) fused prep: pack qkv + convert weights + bias tiles
    prep_kernel<<<PREP_BLOCKS, 256>>>(
        q_w, k_w, v_w, q_b, k_b, v_b, p_wqkv, p_bqkv,
        proj_w, p_wp, fc1_w, p_w1, fc2_w, p_w2,
        rpb, rpi, p_bias);

    // 1) LN1 + shift-roll + window partition (gather)
    ln_kernel<<<MTOK / 8, 256>>>(hidden, ln1_g, ln1_b, p_xw, 1);

    // 2) fused QKV projection
    mma_gemm<0, bf16><<<dim3(QKVN / GBN, MTOK / GBM), 256, TCSMEM>>>(
        p_xw, p_wqkv, p_bqkv, nullptr, p_qkv, MTOK, QKVN, CDIM);

    // 3) windowed attention (one block per window x head-pair)
    attn_mma_kernel<<<dim3(TOTWIN, NHEADS / 2), 256>>>(p_qkv, p_bias, p_ctx);

    // 4) output projection + window-reverse + roll-back + residual (scatter)
    mma_gemm<2, float><<<dim3(CDIM / GBN, MTOK / GBM), 256, TCSMEM>>>(
        p_ctx, p_wp, proj_b, hidden, p_h, MTOK, CDIM, CDIM);

    // 5) LN2
    ln_kernel<<<MTOK / 8, 256>>>(p_h, ln2_g, ln2_b, p_ln2, 0);

    // 6) fc1 + exact GELU
    mma_gemm<1, bf16><<<dim3(FFNDIM / GBN, MTOK / GBM), 256, TCSMEM>>>(
        p_ln2, p_w1, fc1_b, nullptr, p_y1, MTOK, FFNDIM, CDIM);

    // 7) fc2 + residual -> final output
    mma_gemm<3, float><<<dim3(CDIM / GBN, MTOK / GBM), 256, TCSMEM>>>(
        p_y1, p_w2, fc2_b, p_h, out, MTOK, CDIM, FFNDIM);
}